// round 1
// baseline (speedup 1.0000x reference)
#include <cuda_runtime.h>
#include <math.h>

// Problem constants
#define B_    256
#define TCAP  51
#define T_    50
#define V_    10000
#define WD_   512
#define H_    512
#define IC_   2048
#define G3    1536    // 3*H

// ---------------- static device scratch (no runtime allocation allowed) ----------------
__device__ float g_img [B_ * IC_];            // sorted image codes           (2 MB)
__device__ float g_gi0c[B_ * G3];             // img-part of layer0 input gates + b_ih0
__device__ float g_gi0 [(size_t)T_ * B_ * G3];// full layer0 input gates, all steps (78.6 MB)
__device__ float g_gh0 [B_ * G3];
__device__ float g_gi1 [B_ * G3];
__device__ float g_gh1 [B_ * G3];
__device__ float g_h0  [B_ * H_];
__device__ float g_h1  [B_ * H_];
__device__ float g_H1  [(size_t)T_ * B_ * H_];// stored h1 per step (26 MB), 0 for masked rows
__device__ int   g_order [B_];
__device__ int   g_len   [B_];                // lengths = sorted_len - 1, descending
__device__ int   g_nvalid[T_];                // #rows with len > t
__device__ int   g_rowidx[T_ * B_];           // token id per (t, b) for embedding gather

// ---------------- sort + metadata (stable descending by cap_len) ----------------
__global__ void sort_kernel(const int* __restrict__ cap_lens,
                            const int* __restrict__ captions,
                            float* __restrict__ out, long long out_size)
{
    __shared__ int lens[B_];
    __shared__ int ord [B_];
    int i = threadIdx.x;
    lens[i] = cap_lens[i];
    __syncthreads();
    int li = lens[i];
    int rank = 0;
    #pragma unroll 8
    for (int j = 0; j < B_; j++) {
        int lj = lens[j];
        rank += (lj > li) || (lj == li && j < i);   // stable descending
    }
    ord[rank] = i;
    __syncthreads();
    int src = ord[i];
    int len = lens[src] - 1;                        // decode steps for this row
    g_order[i] = src;
    g_len[i]   = len;
    if (i < T_) {
        int c = 0;
        #pragma unroll 8
        for (int b = 0; b < B_; b++) c += (lens[ord[b]] - 1) > i;
        g_nvalid[i] = c;
    }
    const long long PRED = (long long)B_ * T_ * V_;
    for (int t = 0; t < TCAP; t++) {
        int tok = captions[src * TCAP + t];
        if (t < T_) g_rowidx[t * B_ + i] = tok;
        if (out_size >= PRED + (long long)B_ * TCAP)
            out[PRED + (long long)i * TCAP + t] = (float)tok;       // caps
    }
    if (out_size >= PRED + (long long)B_ * TCAP + 2LL * B_) {
        out[PRED + (long long)B_ * TCAP + i]       = (float)len;    // lengths
        out[PRED + (long long)B_ * TCAP + B_ + i]  = (float)src;    // order
    }
}

__global__ void gather_img_kernel(const float* __restrict__ image_code)
{
    int idx = blockIdx.x * 256 + threadIdx.x;      // 256*2048 total
    int b = idx >> 11, k = idx & 2047;
    g_img[idx] = image_code[g_order[b] * IC_ + k];
}

// ---------------- generic tiled fp32 GEMM: C[M,N] = A[M,K] @ B[N,K]^T + bias ----------------
// 64x64 tile, BK=16, 256 threads, 4x4 per thread. Optional row gather on A (rowidx),
// optional early-exit on masked row blocks via g_nvalid[tstep].
__global__ void __launch_bounds__(256)
gemm_kernel(const float* __restrict__ A, const float* __restrict__ Bw,
            const float* __restrict__ bias, float* __restrict__ C,
            int N, int K, int lda, int ldb, int ldc,
            const int* __restrict__ rowidx, int tstep)
{
    int m0 = blockIdx.y * 64;
    int n0 = blockIdx.x * 64;
    if (tstep >= 0 && m0 >= g_nvalid[tstep]) return;   // fully-masked row block

    __shared__ float As[16][65];
    __shared__ float Bs[16][65];
    int tid = threadIdx.x;
    int tx = tid & 15, ty = tid >> 4;
    int r  = tid >> 2;            // 0..63: tile row for both A and B staging
    int kq = (tid & 3) * 4;       // k-quad offset

    int gmA  = m0 + r;
    int arow = rowidx ? rowidx[gmA] : gmA;
    const float* Aptr = A + (size_t)arow * lda + kq;
    int gnB   = n0 + r;
    bool bval = gnB < N;
    const float* Bptr = Bw + (size_t)(bval ? gnB : (N - 1)) * ldb + kq;

    float acc[4][4] = {};
    for (int k0 = 0; k0 < K; k0 += 16) {
        float4 av = *(const float4*)(Aptr + k0);
        float4 bv = bval ? *(const float4*)(Bptr + k0) : make_float4(0.f, 0.f, 0.f, 0.f);
        As[kq + 0][r] = av.x; As[kq + 1][r] = av.y; As[kq + 2][r] = av.z; As[kq + 3][r] = av.w;
        Bs[kq + 0][r] = bv.x; Bs[kq + 1][r] = bv.y; Bs[kq + 2][r] = bv.z; Bs[kq + 3][r] = bv.w;
        __syncthreads();
        #pragma unroll
        for (int k = 0; k < 16; k++) {
            float a0 = As[k][ty * 4 + 0], a1 = As[k][ty * 4 + 1];
            float a2 = As[k][ty * 4 + 2], a3 = As[k][ty * 4 + 3];
            float b0 = Bs[k][tx * 4 + 0], b1 = Bs[k][tx * 4 + 1];
            float b2 = Bs[k][tx * 4 + 2], b3 = Bs[k][tx * 4 + 3];
            acc[0][0] += a0 * b0; acc[0][1] += a0 * b1; acc[0][2] += a0 * b2; acc[0][3] += a0 * b3;
            acc[1][0] += a1 * b0; acc[1][1] += a1 * b1; acc[1][2] += a1 * b2; acc[1][3] += a1 * b3;
            acc[2][0] += a2 * b0; acc[2][1] += a2 * b1; acc[2][2] += a2 * b2; acc[2][3] += a2 * b3;
            acc[3][0] += a3 * b0; acc[3][1] += a3 * b1; acc[3][2] += a3 * b2; acc[3][3] += a3 * b3;
        }
        __syncthreads();
    }
    #pragma unroll
    for (int i = 0; i < 4; i++) {
        int gm = m0 + ty * 4 + i;
        #pragma unroll
        for (int j = 0; j < 4; j++) {
            int gn = n0 + tx * 4 + j;
            if (gn < N)
                C[(size_t)gm * ldc + gn] = acc[i][j] + (bias ? bias[gn] : 0.f);
        }
    }
}

// ---------------- FC head GEMM: preds = H1_all @ fc_w^T + fc_b, masked + scattered ----------------
__global__ void __launch_bounds__(256)
fc_kernel(const float* __restrict__ A, const float* __restrict__ Bw,
          const float* __restrict__ bias, float* __restrict__ out)
{
    const int N = V_, K = H_;
    int m0 = blockIdx.y * 64;         // m = t*256 + b
    int n0 = blockIdx.x * 64;
    int t  = m0 >> 8;
    int b0 = m0 & 255;
    int tid = threadIdx.x;
    int tx = tid & 15, ty = tid >> 4;

    if (t >= g_len[b0]) {             // lengths descending: whole tile masked -> zeros
        #pragma unroll
        for (int i = 0; i < 4; i++) {
            int b = b0 + ty * 4 + i;
            #pragma unroll
            for (int j = 0; j < 4; j++) {
                int gn = n0 + tx * 4 + j;
                if (gn < N)
                    out[(size_t)b * T_ * V_ + (size_t)t * V_ + gn] = 0.f;
            }
        }
        return;
    }

    __shared__ float As[16][65];
    __shared__ float Bs[16][65];
    int r  = tid >> 2;
    int kq = (tid & 3) * 4;
    const float* Aptr = A + (size_t)(m0 + r) * K + kq;
    int gnB   = n0 + r;
    bool bval = gnB < N;
    const float* Bptr = Bw + (size_t)(bval ? gnB : (N - 1)) * K + kq;

    float acc[4][4] = {};
    for (int k0 = 0; k0 < K; k0 += 16) {
        float4 av = *(const float4*)(Aptr + k0);
        float4 bv = bval ? *(const float4*)(Bptr + k0) : make_float4(0.f, 0.f, 0.f, 0.f);
        As[kq + 0][r] = av.x; As[kq + 1][r] = av.y; As[kq + 2][r] = av.z; As[kq + 3][r] = av.w;
        Bs[kq + 0][r] = bv.x; Bs[kq + 1][r] = bv.y; Bs[kq + 2][r] = bv.z; Bs[kq + 3][r] = bv.w;
        __syncthreads();
        #pragma unroll
        for (int k = 0; k < 16; k++) {
            float a0 = As[k][ty * 4 + 0], a1 = As[k][ty * 4 + 1];
            float a2 = As[k][ty * 4 + 2], a3 = As[k][ty * 4 + 3];
            float b0v = Bs[k][tx * 4 + 0], b1v = Bs[k][tx * 4 + 1];
            float b2v = Bs[k][tx * 4 + 2], b3v = Bs[k][tx * 4 + 3];
            acc[0][0] += a0 * b0v; acc[0][1] += a0 * b1v; acc[0][2] += a0 * b2v; acc[0][3] += a0 * b3v;
            acc[1][0] += a1 * b0v; acc[1][1] += a1 * b1v; acc[1][2] += a1 * b2v; acc[1][3] += a1 * b3v;
            acc[2][0] += a2 * b0v; acc[2][1] += a2 * b1v; acc[2][2] += a2 * b2v; acc[2][3] += a2 * b3v;
            acc[3][0] += a3 * b0v; acc[3][1] += a3 * b1v; acc[3][2] += a3 * b2v; acc[3][3] += a3 * b3v;
        }
        __syncthreads();
    }
    #pragma unroll
    for (int i = 0; i < 4; i++) {
        int b = b0 + ty * 4 + i;
        bool valid = t < g_len[b];
        #pragma unroll
        for (int j = 0; j < 4; j++) {
            int gn = n0 + tx * 4 + j;
            if (gn < N)
                out[(size_t)b * T_ * V_ + (size_t)t * V_ + gn] =
                    valid ? (acc[i][j] + bias[gn]) : 0.f;
        }
    }
}

// ---------------- broadcast-add of the time-invariant layer0 input gates ----------------
__global__ void addc_kernel()
{
    size_t idx = (size_t)blockIdx.x * 256 + threadIdx.x;   // T_*B_*G3 total
    int n = (int)(idx % G3);
    size_t m = idx / G3;
    int b = (int)(m & 255);
    g_gi0[idx] += g_gi0c[b * G3 + n];
}

// ---------------- GRU gates (torch ordering r, z, n) ----------------
__device__ __forceinline__ float sigf(float x) { return 1.f / (1.f + expf(-x)); }

__global__ void gate0_kernel(int t)
{
    int idx = blockIdx.x * 256 + threadIdx.x;  // B_*H_
    int b = idx >> 9, h = idx & 511;
    if (t >= g_len[b]) return;                  // masked rows keep old hidden
    const float* gi = g_gi0 + ((size_t)t * B_ + b) * G3;
    const float* gh = g_gh0 + (size_t)b * G3;
    float r = sigf(gi[h]          + gh[h]);
    float z = sigf(gi[h + H_]     + gh[h + H_]);
    float n = tanhf(gi[h + 2*H_]  + r * gh[h + 2*H_]);
    g_h0[idx] = (1.f - z) * n + z * g_h0[idx];
}

__global__ void gate1_kernel(int t)
{
    int idx = blockIdx.x * 256 + threadIdx.x;
    int b = idx >> 9, h = idx & 511;
    float* H1row = g_H1 + (size_t)t * B_ * H_;
    if (t >= g_len[b]) { H1row[idx] = 0.f; return; }   // masked preds are zero (fc_b added only when valid)
    const float* gi = g_gi1 + (size_t)b * G3;
    const float* gh = g_gh1 + (size_t)b * G3;
    float r = sigf(gi[h]          + gh[h]);
    float z = sigf(gi[h + H_]     + gh[h + H_]);
    float n = tanhf(gi[h + 2*H_]  + r * gh[h + 2*H_]);
    float hn = (1.f - z) * n + z * g_h1[idx];
    g_h1[idx]  = hn;
    H1row[idx] = hn;
}

// ---------------- host orchestration (graph-capturable: launches only) ----------------
extern "C" void kernel_launch(void* const* d_in, const int* in_sizes, int n_in,
                              void* d_out, int out_size)
{
    const float* image_code = (const float*)d_in[0];
    const int*   captions   = (const int*)  d_in[1];
    const int*   cap_lens   = (const int*)  d_in[2];
    const float* embed_w    = (const float*)d_in[3];
    const float* init_w     = (const float*)d_in[4];
    const float* init_b     = (const float*)d_in[5];
    const float* w_ih0      = (const float*)d_in[6];
    const float* w_hh0      = (const float*)d_in[7];
    const float* b_ih0      = (const float*)d_in[8];
    const float* b_hh0      = (const float*)d_in[9];
    const float* w_ih1      = (const float*)d_in[10];
    const float* w_hh1      = (const float*)d_in[11];
    const float* b_ih1      = (const float*)d_in[12];
    const float* b_hh1      = (const float*)d_in[13];
    const float* fc_w       = (const float*)d_in[14];
    const float* fc_b       = (const float*)d_in[15];
    float* out = (float*)d_out;

    void* p;
    cudaGetSymbolAddress(&p, g_img);    float* dimg  = (float*)p;
    cudaGetSymbolAddress(&p, g_gi0c);   float* dgi0c = (float*)p;
    cudaGetSymbolAddress(&p, g_gi0);    float* dgi0  = (float*)p;
    cudaGetSymbolAddress(&p, g_gh0);    float* dgh0  = (float*)p;
    cudaGetSymbolAddress(&p, g_gi1);    float* dgi1  = (float*)p;
    cudaGetSymbolAddress(&p, g_gh1);    float* dgh1  = (float*)p;
    cudaGetSymbolAddress(&p, g_h0);     float* dh0   = (float*)p;
    cudaGetSymbolAddress(&p, g_h1);     float* dh1   = (float*)p;
    cudaGetSymbolAddress(&p, g_H1);     float* dH1   = (float*)p;
    cudaGetSymbolAddress(&p, g_rowidx); int*   drow  = (int*)p;

    // 1. sort + metadata + aux outputs
    sort_kernel<<<1, 256>>>(cap_lens, captions, out, (long long)out_size);
    // 2. gather sorted image codes
    gather_img_kernel<<<(B_ * IC_) / 256, 256>>>(image_code);
    // 3. h0/h1 init: (256,512,K=2048) each
    gemm_kernel<<<dim3(8, 4), 256>>>(dimg, init_w,              init_b,        dh0, 512, IC_, IC_, IC_, 512, nullptr, -1);
    gemm_kernel<<<dim3(8, 4), 256>>>(dimg, init_w + 512 * IC_,  init_b + 512,  dh1, 512, IC_, IC_, IC_, 512, nullptr, -1);
    // 4. time-invariant image part of layer0 input gates (+ b_ih0)
    gemm_kernel<<<dim3(24, 4), 256>>>(dimg, w_ih0, b_ih0, dgi0c, G3, IC_, IC_, IC_ + WD_, G3, nullptr, -1);
    // 5. embedding part for ALL 12800 tokens (gathered rows of embed_w)
    gemm_kernel<<<dim3(24, 200), 256>>>(embed_w, w_ih0 + IC_, nullptr, dgi0, G3, WD_, WD_, IC_ + WD_, G3, drow, -1);
    // 6. broadcast-add the invariant part
    addc_kernel<<<(unsigned)(((size_t)T_ * B_ * G3) / 256), 256>>>();
    // 7. sequential recurrence: 3 small GEMMs + 2 gate kernels per step
    for (int t = 0; t < T_; t++) {
        gemm_kernel<<<dim3(24, 4), 256>>>(dh0, w_hh0, b_hh0, dgh0, G3, H_, H_, H_, G3, nullptr, t);
        gate0_kernel<<<(B_ * H_) / 256, 256>>>(t);
        gemm_kernel<<<dim3(24, 4), 256>>>(dh0, w_ih1, b_ih1, dgi1, G3, H_, H_, H_, G3, nullptr, t);
        gemm_kernel<<<dim3(24, 4), 256>>>(dh1, w_hh1, b_hh1, dgh1, G3, H_, H_, H_, G3, nullptr, t);
        gate1_kernel<<<(B_ * H_) / 256, 256>>>(t);
    }
    // 8. one big FC GEMM for all (t, b), masked + scattered to (B, T, V)
    fc_kernel<<<dim3((V_ + 63) / 64, (T_ * B_) / 64), 256>>>(dH1, fc_w, fc_b, out);
}

// round 2
// speedup vs baseline: 1.3557x; 1.3557x over previous
#include <cuda_runtime.h>
#include <math.h>

// Problem constants
#define B_    256
#define TCAP  51
#define T_    50
#define V_    10000
#define WD_   512
#define H_    512
#define IC_   2048
#define G3    1536    // 3*H

// ---------------- static device scratch ----------------
__device__ float g_img [B_ * IC_];
__device__ float g_gi0c[B_ * G3];
__device__ float g_gi0 [(size_t)T_ * B_ * G3];   // precomputed layer0 input gates
__device__ float g_h0a [B_ * H_];
__device__ float g_h0b [B_ * H_];
__device__ float g_h1a [B_ * H_];
__device__ float g_h1b [B_ * H_];
__device__ float g_H1  [(size_t)T_ * B_ * H_];   // stored h1 per step (0 for masked rows)
__device__ int   g_order [B_];
__device__ int   g_len   [B_];
__device__ int   g_nvalid[T_];
__device__ int   g_rowidx[T_ * B_];

__device__ __forceinline__ float sigf(float x) { return 1.f / (1.f + expf(-x)); }

// ---------------- sort + metadata (stable descending by cap_len) ----------------
__global__ void sort_kernel(const int* __restrict__ cap_lens,
                            const int* __restrict__ captions,
                            float* __restrict__ out, long long out_size)
{
    __shared__ int lens[B_];
    __shared__ int ord [B_];
    int i = threadIdx.x;
    lens[i] = cap_lens[i];
    __syncthreads();
    int li = lens[i];
    int rank = 0;
    #pragma unroll 8
    for (int j = 0; j < B_; j++) {
        int lj = lens[j];
        rank += (lj > li) || (lj == li && j < i);
    }
    ord[rank] = i;
    __syncthreads();
    int src = ord[i];
    int len = lens[src] - 1;
    g_order[i] = src;
    g_len[i]   = len;
    if (i < T_) {
        int c = 0;
        #pragma unroll 8
        for (int b = 0; b < B_; b++) c += (lens[ord[b]] - 1) > i;
        g_nvalid[i] = c;
    }
    const long long PRED = (long long)B_ * T_ * V_;
    for (int t = 0; t < TCAP; t++) {
        int tok = captions[src * TCAP + t];
        if (t < T_) g_rowidx[t * B_ + i] = tok;
        if (out_size >= PRED + (long long)B_ * TCAP)
            out[PRED + (long long)i * TCAP + t] = (float)tok;
    }
    if (out_size >= PRED + (long long)B_ * TCAP + 2LL * B_) {
        out[PRED + (long long)B_ * TCAP + i]      = (float)len;
        out[PRED + (long long)B_ * TCAP + B_ + i] = (float)src;
    }
}

__global__ void gather_img_kernel(const float* __restrict__ image_code)
{
    int idx = blockIdx.x * 256 + threadIdx.x;
    int b = idx >> 11, k = idx & 2047;
    g_img[idx] = image_code[g_order[b] * IC_ + k];
}

// ---------------- 64x64 tile GEMM for deep-K prologue (inits, gi0c) ----------------
// C[M,N] = A[M,K] @ B[N,K]^T + bias.  If Cb!=null: col<512 -> C (ld 512), else Cb.
__global__ void __launch_bounds__(256)
gemm64_kernel(const float* __restrict__ A, int lda,
              const float* __restrict__ Bw, int ldb,
              const float* __restrict__ bias,
              float* __restrict__ C, int ldc, float* __restrict__ Cb, int K)
{
    __shared__ float As[16][68];
    __shared__ float Bs[16][68];
    int m0 = blockIdx.y * 64, n0 = blockIdx.x * 64;
    int tid = threadIdx.x;
    int lr = tid >> 2, kq = (tid & 3) * 4;
    const float* Ap = A  + (size_t)(m0 + lr) * lda + kq;
    const float* Bp = Bw + (size_t)(n0 + lr) * ldb + kq;
    int tx = tid & 15, ty = tid >> 4;
    float acc[4][4] = {};
    for (int k0 = 0; k0 < K; k0 += 16) {
        float4 av = *(const float4*)(Ap + k0);
        float4 bv = *(const float4*)(Bp + k0);
        As[kq+0][lr]=av.x; As[kq+1][lr]=av.y; As[kq+2][lr]=av.z; As[kq+3][lr]=av.w;
        Bs[kq+0][lr]=bv.x; Bs[kq+1][lr]=bv.y; Bs[kq+2][lr]=bv.z; Bs[kq+3][lr]=bv.w;
        __syncthreads();
        #pragma unroll
        for (int k = 0; k < 16; k++) {
            float4 a = *(const float4*)&As[k][ty*4];
            float4 b = *(const float4*)&Bs[k][tx*4];
            acc[0][0]+=a.x*b.x; acc[0][1]+=a.x*b.y; acc[0][2]+=a.x*b.z; acc[0][3]+=a.x*b.w;
            acc[1][0]+=a.y*b.x; acc[1][1]+=a.y*b.y; acc[1][2]+=a.y*b.z; acc[1][3]+=a.y*b.w;
            acc[2][0]+=a.z*b.x; acc[2][1]+=a.z*b.y; acc[2][2]+=a.z*b.z; acc[2][3]+=a.z*b.w;
            acc[3][0]+=a.w*b.x; acc[3][1]+=a.w*b.y; acc[3][2]+=a.w*b.z; acc[3][3]+=a.w*b.w;
        }
        __syncthreads();
    }
    #pragma unroll
    for (int i = 0; i < 4; i++) {
        int m = m0 + ty * 4 + i;
        #pragma unroll
        for (int j = 0; j < 4; j++) {
            int n = n0 + tx * 4 + j;
            float v = acc[i][j] + (bias ? bias[n] : 0.f);
            if (Cb) {
                if (n < H_) C [(size_t)m * H_ + n]       = v;
                else        Cb[(size_t)m * H_ + (n-H_)]  = v;
            } else {
                C[(size_t)m * ldc + n] = v;
            }
        }
    }
}

// ---------------- 128x128 tile, 8x8/thread, double-buffered SGEMM (gi0) ----------------
// C[M,N] = A[gather(M),K] @ B[N,K]^T  (+ cadd[(m%256)*ldc + n] if cadd)
// N, M multiples of 128.
__global__ void __launch_bounds__(256)
gemm128_kernel(const float* __restrict__ A, int lda, const int* __restrict__ rowidx,
               const float* __restrict__ Bw, int ldb,
               const float* __restrict__ cadd,
               float* __restrict__ C, int ldc, int K)
{
    __shared__ float As[2][8][132];
    __shared__ float Bs[2][8][132];
    int m0 = blockIdx.y * 128, n0 = blockIdx.x * 128;
    int tid = threadIdx.x;
    int lr = tid >> 1, kq = (tid & 1) * 4;
    int am = m0 + lr;
    int arow = rowidx ? rowidx[am] : am;
    const float* Ap = A  + (size_t)arow * lda + kq;
    const float* Bp = Bw + (size_t)(n0 + lr) * ldb + kq;
    int tx = tid & 15, ty = tid >> 4;
    float acc[8][8] = {};
    float4 av = *(const float4*)Ap;
    float4 bv = *(const float4*)Bp;
    As[0][kq+0][lr]=av.x; As[0][kq+1][lr]=av.y; As[0][kq+2][lr]=av.z; As[0][kq+3][lr]=av.w;
    Bs[0][kq+0][lr]=bv.x; Bs[0][kq+1][lr]=bv.y; Bs[0][kq+2][lr]=bv.z; Bs[0][kq+3][lr]=bv.w;
    __syncthreads();
    int iters = K >> 3;
    int buf = 0;
    for (int it = 0; it < iters; it++) {
        if (it + 1 < iters) {
            av = *(const float4*)(Ap + (it + 1) * 8);
            bv = *(const float4*)(Bp + (it + 1) * 8);
        }
        #pragma unroll
        for (int k = 0; k < 8; k++) {
            float4 a0 = *(const float4*)&As[buf][k][ty*4];
            float4 a1 = *(const float4*)&As[buf][k][ty*4+64];
            float4 b0 = *(const float4*)&Bs[buf][k][tx*4];
            float4 b1 = *(const float4*)&Bs[buf][k][tx*4+64];
            float a[8] = {a0.x,a0.y,a0.z,a0.w,a1.x,a1.y,a1.z,a1.w};
            float b[8] = {b0.x,b0.y,b0.z,b0.w,b1.x,b1.y,b1.z,b1.w};
            #pragma unroll
            for (int mi = 0; mi < 8; mi++)
                #pragma unroll
                for (int ni = 0; ni < 8; ni++)
                    acc[mi][ni] += a[mi] * b[ni];
        }
        if (it + 1 < iters) {
            int nb = buf ^ 1;
            As[nb][kq+0][lr]=av.x; As[nb][kq+1][lr]=av.y; As[nb][kq+2][lr]=av.z; As[nb][kq+3][lr]=av.w;
            Bs[nb][kq+0][lr]=bv.x; Bs[nb][kq+1][lr]=bv.y; Bs[nb][kq+2][lr]=bv.z; Bs[nb][kq+3][lr]=bv.w;
        }
        __syncthreads();
        buf ^= 1;
    }
    #pragma unroll
    for (int mi = 0; mi < 8; mi++) {
        int m = m0 + ty * 4 + (mi & 3) + ((mi >> 2) * 64);
        #pragma unroll
        for (int ni = 0; ni < 8; ni++) {
            int n = n0 + tx * 4 + (ni & 3) + ((ni >> 2) * 64);
            float v = acc[mi][ni];
            if (cadd) v += cadd[(size_t)(m & 255) * ldc + n];
            C[(size_t)m * ldc + n] = v;
        }
    }
}

// ---------------- FC head: preds = H1_all @ fc_w^T + fc_b, masked + scattered ----------------
__global__ void __launch_bounds__(256)
fc128_kernel(const float* __restrict__ A, const float* __restrict__ Bw,
             const float* __restrict__ bias, float* __restrict__ out)
{
    int m0 = blockIdx.y * 128, n0 = blockIdx.x * 128;
    int t = m0 >> 8;
    int bbase = m0 & 255;
    int tid = threadIdx.x;
    int tx = tid & 15, ty = tid >> 4;

    if (t >= g_len[bbase]) {   // sorted-descending lengths: whole tile masked -> zeros
        #pragma unroll
        for (int mi = 0; mi < 8; mi++) {
            int b = bbase + ty * 4 + (mi & 3) + ((mi >> 2) * 64);
            #pragma unroll
            for (int ni = 0; ni < 8; ni++) {
                int n = n0 + tx * 4 + (ni & 3) + ((ni >> 2) * 64);
                if (n < V_)
                    out[(size_t)b * T_ * V_ + (size_t)t * V_ + n] = 0.f;
            }
        }
        return;
    }

    __shared__ float As[2][8][132];
    __shared__ float Bs[2][8][132];
    int lr = tid >> 1, kq = (tid & 1) * 4;
    const float* Ap = A + (size_t)(m0 + lr) * H_ + kq;
    int brow = n0 + lr; if (brow > V_ - 1) brow = V_ - 1;   // clamp (garbage cols never written)
    const float* Bp = Bw + (size_t)brow * H_ + kq;
    float acc[8][8] = {};
    float4 av = *(const float4*)Ap;
    float4 bv = *(const float4*)Bp;
    As[0][kq+0][lr]=av.x; As[0][kq+1][lr]=av.y; As[0][kq+2][lr]=av.z; As[0][kq+3][lr]=av.w;
    Bs[0][kq+0][lr]=bv.x; Bs[0][kq+1][lr]=bv.y; Bs[0][kq+2][lr]=bv.z; Bs[0][kq+3][lr]=bv.w;
    __syncthreads();
    const int iters = H_ >> 3;
    int buf = 0;
    for (int it = 0; it < iters; it++) {
        if (it + 1 < iters) {
            av = *(const float4*)(Ap + (it + 1) * 8);
            bv = *(const float4*)(Bp + (it + 1) * 8);
        }
        #pragma unroll
        for (int k = 0; k < 8; k++) {
            float4 a0 = *(const float4*)&As[buf][k][ty*4];
            float4 a1 = *(const float4*)&As[buf][k][ty*4+64];
            float4 b0 = *(const float4*)&Bs[buf][k][tx*4];
            float4 b1 = *(const float4*)&Bs[buf][k][tx*4+64];
            float a[8] = {a0.x,a0.y,a0.z,a0.w,a1.x,a1.y,a1.z,a1.w};
            float b[8] = {b0.x,b0.y,b0.z,b0.w,b1.x,b1.y,b1.z,b1.w};
            #pragma unroll
            for (int mi = 0; mi < 8; mi++)
                #pragma unroll
                for (int ni = 0; ni < 8; ni++)
                    acc[mi][ni] += a[mi] * b[ni];
        }
        if (it + 1 < iters) {
            int nb = buf ^ 1;
            As[nb][kq+0][lr]=av.x; As[nb][kq+1][lr]=av.y; As[nb][kq+2][lr]=av.z; As[nb][kq+3][lr]=av.w;
            Bs[nb][kq+0][lr]=bv.x; Bs[nb][kq+1][lr]=bv.y; Bs[nb][kq+2][lr]=bv.z; Bs[nb][kq+3][lr]=bv.w;
        }
        __syncthreads();
        buf ^= 1;
    }
    #pragma unroll
    for (int mi = 0; mi < 8; mi++) {
        int b = bbase + ty * 4 + (mi & 3) + ((mi >> 2) * 64);
        bool valid = t < g_len[b];
        #pragma unroll
        for (int ni = 0; ni < 8; ni++) {
            int n = n0 + tx * 4 + (ni & 3) + ((ni >> 2) * 64);
            if (n < V_)
                out[(size_t)b * T_ * V_ + (size_t)t * V_ + n] =
                    valid ? (acc[mi][ni] + bias[n]) : 0.f;
        }
    }
}

// ---------------- recurrence: fused GEMM+gate kernels ----------------
// Shared inner-segment macro: accumulates r/z/ACCN over K=512 from ASRC @ WSRC^T
// for a 32(m) x 32(h) tile with 3 gate column groups.
#define GRU_SEGMENT(ASRC, WSRC, ACCN)                                           \
    for (int k0 = 0; k0 < H_; k0 += 16) {                                       \
        { int r = tid >> 3, k = (tid * 2) & 15;                                 \
          float2 v = *(const float2*)&ASRC[(size_t)(m0 + r) * H_ + k0 + k];     \
          As[k][r] = v.x; As[k+1][r] = v.y; }                                   \
        { int hh = tid >> 3, k = (tid * 2) & 15;                                \
          _Pragma("unroll")                                                     \
          for (int j = 0; j < 3; j++) {                                         \
            float2 v = *(const float2*)&WSRC[(size_t)(j * H_ + hb + hh) * H_ + k0 + k]; \
            Ws[k][j*32 + hh] = v.x; Ws[k+1][j*32 + hh] = v.y; } }               \
        __syncthreads();                                                        \
        _Pragma("unroll")                                                       \
        for (int k = 0; k < 16; k++) {                                          \
            float A0 = As[k][ty2],     A1 = As[k][ty2+1];                       \
            float wr0 = Ws[k][tx2],    wr1 = Ws[k][tx2+1];                      \
            float wz0 = Ws[k][32+tx2], wz1 = Ws[k][32+tx2+1];                   \
            float wn0 = Ws[k][64+tx2], wn1 = Ws[k][64+tx2+1];                   \
            accr[0][0]+=A0*wr0; accr[0][1]+=A0*wr1; accr[1][0]+=A1*wr0; accr[1][1]+=A1*wr1; \
            accz[0][0]+=A0*wz0; accz[0][1]+=A0*wz1; accz[1][0]+=A1*wz0; accz[1][1]+=A1*wz1; \
            ACCN[0][0]+=A0*wn0; ACCN[0][1]+=A0*wn1; ACCN[1][0]+=A1*wn0; ACCN[1][1]+=A1*wn1; \
        }                                                                       \
        __syncthreads();                                                        \
    }

// Phase A: h0_new = GRU0(gi0[t], h0_old)   grid (16, 8), 256 threads
__global__ void __launch_bounds__(256)
gru0_kernel(const float* __restrict__ h0old, float* __restrict__ h0new,
            const float* __restrict__ w_hh0, const float* __restrict__ b_hh0, int t)
{
    int hb = blockIdx.x * 32;
    int m0 = blockIdx.y * 32;
    int tid = threadIdx.x;
    if (m0 >= g_nvalid[t]) {                 // fully-masked tile: carry hidden
        int r = tid >> 3, c0 = (tid & 7) * 4;
        *(float4*)&h0new[(size_t)(m0 + r) * H_ + hb + c0] =
            *(const float4*)&h0old[(size_t)(m0 + r) * H_ + hb + c0];
        return;
    }
    __shared__ float As[17][34];
    __shared__ float Ws[17][98];
    int tx = tid & 15, ty = tid >> 4;
    int tx2 = tx * 2, ty2 = ty * 2;
    float accr[2][2] = {}, accz[2][2] = {}, accn[2][2] = {};
    GRU_SEGMENT(h0old, w_hh0, accn)
    #pragma unroll
    for (int i = 0; i < 2; i++) {
        int b = m0 + ty2 + i;
        bool valid = t < g_len[b];
        const float* gi = g_gi0 + ((size_t)t * B_ + b) * G3;
        #pragma unroll
        for (int j = 0; j < 2; j++) {
            int h = hb + tx2 + j;
            float old = h0old[(size_t)b * H_ + h];
            float v;
            if (valid) {
                float r = sigf(gi[h]        + accr[i][j] + b_hh0[h]);
                float z = sigf(gi[h + H_]   + accz[i][j] + b_hh0[h + H_]);
                float n = tanhf(gi[h + 2*H_] + r * (accn[i][j] + b_hh0[h + 2*H_]));
                v = (1.f - z) * n + z * old;
            } else v = old;
            h0new[(size_t)b * H_ + h] = v;
        }
    }
}

// Phase B: h1_new = GRU1(h0_new, h1_old); store into g_H1[t]   grid (16, 8)
__global__ void __launch_bounds__(256)
gru1_kernel(const float* __restrict__ h0cur, const float* __restrict__ h1old,
            float* __restrict__ h1new,
            const float* __restrict__ w_ih1, const float* __restrict__ w_hh1,
            const float* __restrict__ b_ih1, const float* __restrict__ b_hh1, int t)
{
    int hb = blockIdx.x * 32;
    int m0 = blockIdx.y * 32;
    int tid = threadIdx.x;
    float* H1r = g_H1 + (size_t)t * B_ * H_;
    if (m0 >= g_nvalid[t]) {
        int r = tid >> 3, c0 = (tid & 7) * 4;
        *(float4*)&h1new[(size_t)(m0 + r) * H_ + hb + c0] =
            *(const float4*)&h1old[(size_t)(m0 + r) * H_ + hb + c0];
        *(float4*)&H1r[(size_t)(m0 + r) * H_ + hb + c0] = make_float4(0.f,0.f,0.f,0.f);
        return;
    }
    __shared__ float As[17][34];
    __shared__ float Ws[17][98];
    int tx = tid & 15, ty = tid >> 4;
    int tx2 = tx * 2, ty2 = ty * 2;
    float accr[2][2] = {}, accz[2][2] = {}, accin[2][2] = {}, acchn[2][2] = {};
    GRU_SEGMENT(h0cur, w_ih1, accin)   // input-side: r,z joint; n -> accin
    GRU_SEGMENT(h1old, w_hh1, acchn)   // hidden-side: r,z joint; n -> acchn
    #pragma unroll
    for (int i = 0; i < 2; i++) {
        int b = m0 + ty2 + i;
        bool valid = t < g_len[b];
        #pragma unroll
        for (int j = 0; j < 2; j++) {
            int h = hb + tx2 + j;
            float old = h1old[(size_t)b * H_ + h];
            size_t idx = (size_t)b * H_ + h;
            if (valid) {
                float r = sigf(accr[i][j] + b_ih1[h]        + b_hh1[h]);
                float z = sigf(accz[i][j] + b_ih1[h + H_]   + b_hh1[h + H_]);
                float n = tanhf(accin[i][j] + b_ih1[h + 2*H_]
                                + r * (acchn[i][j] + b_hh1[h + 2*H_]));
                float v = (1.f - z) * n + z * old;
                h1new[idx] = v;
                H1r[idx]   = v;
            } else {
                h1new[idx] = old;
                H1r[idx]   = 0.f;
            }
        }
    }
}

// ---------------- host orchestration (graph-capturable: launches only) ----------------
extern "C" void kernel_launch(void* const* d_in, const int* in_sizes, int n_in,
                              void* d_out, int out_size)
{
    const float* image_code = (const float*)d_in[0];
    const int*   captions   = (const int*)  d_in[1];
    const int*   cap_lens   = (const int*)  d_in[2];
    const float* embed_w    = (const float*)d_in[3];
    const float* init_w     = (const float*)d_in[4];
    const float* init_b     = (const float*)d_in[5];
    const float* w_ih0      = (const float*)d_in[6];
    const float* w_hh0      = (const float*)d_in[7];
    const float* b_ih0      = (const float*)d_in[8];
    const float* b_hh0      = (const float*)d_in[9];
    const float* w_ih1      = (const float*)d_in[10];
    const float* w_hh1      = (const float*)d_in[11];
    const float* b_ih1      = (const float*)d_in[12];
    const float* b_hh1      = (const float*)d_in[13];
    const float* fc_w       = (const float*)d_in[14];
    const float* fc_b       = (const float*)d_in[15];
    float* out = (float*)d_out;

    void* p;
    cudaGetSymbolAddress(&p, g_img);    float* dimg  = (float*)p;
    cudaGetSymbolAddress(&p, g_gi0c);   float* dgi0c = (float*)p;
    cudaGetSymbolAddress(&p, g_gi0);    float* dgi0  = (float*)p;
    cudaGetSymbolAddress(&p, g_h0a);    float* dh0a  = (float*)p;
    cudaGetSymbolAddress(&p, g_h0b);    float* dh0b  = (float*)p;
    cudaGetSymbolAddress(&p, g_h1a);    float* dh1a  = (float*)p;
    cudaGetSymbolAddress(&p, g_h1b);    float* dh1b  = (float*)p;
    cudaGetSymbolAddress(&p, g_H1);     float* dH1   = (float*)p;
    cudaGetSymbolAddress(&p, g_rowidx); int*   drow  = (int*)p;

    // 1. sort + metadata + aux outputs
    sort_kernel<<<1, 256>>>(cap_lens, captions, out, (long long)out_size);
    // 2. gather sorted image codes
    gather_img_kernel<<<(B_ * IC_) / 256, 256>>>(image_code);
    // 3. h0/h1 init in ONE GEMM: (256, 1024, K=2048); cols 0..511 -> h0a, 512.. -> h1a
    gemm64_kernel<<<dim3(16, 4), 256>>>(dimg, IC_, init_w, IC_, init_b,
                                        dh0a, H_, dh1a, IC_);
    // 4. time-invariant img part of layer0 input gates (+ b_ih0): (256, 1536, K=2048)
    gemm64_kernel<<<dim3(24, 4), 256>>>(dimg, IC_, w_ih0, IC_ + WD_, b_ih0,
                                        dgi0c, G3, nullptr, IC_);
    // 5. embedding-side layer0 input gates for ALL 12800 tokens, + gi0c fused add
    gemm128_kernel<<<dim3(12, 100), 256>>>(embed_w, WD_, drow,
                                           w_ih0 + IC_, IC_ + WD_,
                                           dgi0c, dgi0, G3, WD_);
    // 6. sequential recurrence: 2 fused kernels per step, ping-pong hidden buffers
    for (int t = 0; t < T_; t++) {
        float* h0o = (t & 1) ? dh0b : dh0a;
        float* h0n = (t & 1) ? dh0a : dh0b;
        float* h1o = (t & 1) ? dh1b : dh1a;
        float* h1n = (t & 1) ? dh1a : dh1b;
        gru0_kernel<<<dim3(16, 8), 256>>>(h0o, h0n, w_hh0, b_hh0, t);
        gru1_kernel<<<dim3(16, 8), 256>>>(h0n, h1o, h1n, w_ih1, w_hh1, b_ih1, b_hh1, t);
    }
    // 7. one big FC GEMM for all (t, b), masked + scattered to (B, T, V)
    fc128_kernel<<<dim3(79, 100), 256>>>(dH1, fc_w, fc_b, out);
}

// round 5
// speedup vs baseline: 1.5001x; 1.1065x over previous
#include <cuda_runtime.h>
#include <cuda_bf16.h>
#include <stdint.h>
#include <cstdint>
#include <math.h>

// Problem constants
#define B_    256
#define TCAP  51
#define T_    50
#define V_    10000
#define WD_   512
#define H_    512
#define IC_   2048
#define G3    1536    // 3*H

// ---------------- static device scratch ----------------
__device__ float g_img [B_ * IC_];
__device__ float g_gi0c[B_ * G3];
__device__ float g_gi0 [(size_t)T_ * B_ * G3];   // precomputed layer0 input gates
__device__ float g_h0a [B_ * H_];
__device__ float g_h0b [B_ * H_];
__device__ float g_h1a [B_ * H_];
__device__ float g_h1b [B_ * H_];
__device__ float g_H1  [(size_t)T_ * B_ * H_];   // stored h1 per step (0 for masked rows)
__device__ int   g_order [B_];
__device__ int   g_len   [B_];
__device__ int   g_nvalid[T_];
__device__ int   g_rowidx[T_ * B_];

__device__ __forceinline__ float sigf(float x) { return 1.f / (1.f + expf(-x)); }

// ---------------- sort + metadata (stable descending by cap_len) ----------------
__global__ void sort_kernel(const int* __restrict__ cap_lens,
                            const int* __restrict__ captions,
                            float* __restrict__ out, long long out_size)
{
    __shared__ int lens[B_];
    __shared__ int ord [B_];
    int i = threadIdx.x;
    lens[i] = cap_lens[i];
    __syncthreads();
    int li = lens[i];
    int rank = 0;
    #pragma unroll 8
    for (int j = 0; j < B_; j++) {
        int lj = lens[j];
        rank += (lj > li) || (lj == li && j < i);
    }
    ord[rank] = i;
    __syncthreads();
    int src = ord[i];
    int len = lens[src] - 1;
    g_order[i] = src;
    g_len[i]   = len;
    if (i < T_) {
        int c = 0;
        #pragma unroll 8
        for (int b = 0; b < B_; b++) c += (lens[ord[b]] - 1) > i;
        g_nvalid[i] = c;
    }
    const long long PRED = (long long)B_ * T_ * V_;
    for (int t = 0; t < TCAP; t++) {
        int tok = captions[src * TCAP + t];
        if (t < T_) g_rowidx[t * B_ + i] = tok;
        if (out_size >= PRED + (long long)B_ * TCAP)
            out[PRED + (long long)i * TCAP + t] = (float)tok;
    }
    if (out_size >= PRED + (long long)B_ * TCAP + 2LL * B_) {
        out[PRED + (long long)B_ * TCAP + i]      = (float)len;
        out[PRED + (long long)B_ * TCAP + B_ + i] = (float)src;
    }
}

__global__ void gather_img_kernel(const float* __restrict__ image_code)
{
    int idx = blockIdx.x * 256 + threadIdx.x;
    int b = idx >> 11, k = idx & 2047;
    g_img[idx] = image_code[g_order[b] * IC_ + k];
}

// ---------------- 64x64 tile SIMT GEMM for deep-K prologue (inits, gi0c) ----------------
__global__ void __launch_bounds__(256)
gemm64_kernel(const float* __restrict__ A, int lda,
              const float* __restrict__ Bw, int ldb,
              const float* __restrict__ bias,
              float* __restrict__ C, int ldc, float* __restrict__ Cb, int K)
{
    __shared__ float As[16][68];
    __shared__ float Bs[16][68];
    int m0 = blockIdx.y * 64, n0 = blockIdx.x * 64;
    int tid = threadIdx.x;
    int lr = tid >> 2, kq = (tid & 3) * 4;
    const float* Ap = A  + (size_t)(m0 + lr) * lda + kq;
    const float* Bp = Bw + (size_t)(n0 + lr) * ldb + kq;
    int tx = tid & 15, ty = tid >> 4;
    float acc[4][4] = {};
    for (int k0 = 0; k0 < K; k0 += 16) {
        float4 av = *(const float4*)(Ap + k0);
        float4 bv = *(const float4*)(Bp + k0);
        As[kq+0][lr]=av.x; As[kq+1][lr]=av.y; As[kq+2][lr]=av.z; As[kq+3][lr]=av.w;
        Bs[kq+0][lr]=bv.x; Bs[kq+1][lr]=bv.y; Bs[kq+2][lr]=bv.z; Bs[kq+3][lr]=bv.w;
        __syncthreads();
        #pragma unroll
        for (int k = 0; k < 16; k++) {
            float4 a = *(const float4*)&As[k][ty*4];
            float4 b = *(const float4*)&Bs[k][tx*4];
            acc[0][0]+=a.x*b.x; acc[0][1]+=a.x*b.y; acc[0][2]+=a.x*b.z; acc[0][3]+=a.x*b.w;
            acc[1][0]+=a.y*b.x; acc[1][1]+=a.y*b.y; acc[1][2]+=a.y*b.z; acc[1][3]+=a.y*b.w;
            acc[2][0]+=a.z*b.x; acc[2][1]+=a.z*b.y; acc[2][2]+=a.z*b.z; acc[2][3]+=a.z*b.w;
            acc[3][0]+=a.w*b.x; acc[3][1]+=a.w*b.y; acc[3][2]+=a.w*b.z; acc[3][3]+=a.w*b.w;
        }
        __syncthreads();
    }
    #pragma unroll
    for (int i = 0; i < 4; i++) {
        int m = m0 + ty * 4 + i;
        #pragma unroll
        for (int j = 0; j < 4; j++) {
            int n = n0 + tx * 4 + j;
            float v = acc[i][j] + (bias ? bias[n] : 0.f);
            if (Cb) {
                if (n < H_) C [(size_t)m * H_ + n]       = v;
                else        Cb[(size_t)m * H_ + (n-H_)]  = v;
            } else {
                C[(size_t)m * ldc + n] = v;
            }
        }
    }
}

// ---------------- tensor-core bf16-3term GEMM machinery ----------------
__device__ __forceinline__ unsigned int s2u(const void* p) {
    return (unsigned int)__cvta_generic_to_shared(p);
}
// pack (x,y) as bf16 hi pair (return) and residual lo pair (out param)
__device__ __forceinline__ unsigned int bf2pack(float x, float y, unsigned int& lo) {
    __nv_bfloat16 hx = __float2bfloat16_rn(x);
    __nv_bfloat16 hy = __float2bfloat16_rn(y);
    float rx = x - __bfloat162float(hx);
    float ry = y - __bfloat162float(hy);
    unsigned short lx = __bfloat16_as_ushort(__float2bfloat16_rn(rx));
    unsigned short ly = __bfloat16_as_ushort(__float2bfloat16_rn(ry));
    lo = (unsigned int)lx | ((unsigned int)ly << 16);
    return (unsigned int)__bfloat16_as_ushort(hx) | ((unsigned int)__bfloat16_as_ushort(hy) << 16);
}
__device__ __forceinline__ void ldsm_x4(unsigned int* r, unsigned int addr) {
    asm volatile("ldmatrix.sync.aligned.m8n8.x4.shared.b16 {%0,%1,%2,%3},[%4];"
        : "=r"(r[0]), "=r"(r[1]), "=r"(r[2]), "=r"(r[3]) : "r"(addr));
}
__device__ __forceinline__ void ldsm_x2(unsigned int& r0, unsigned int& r1, unsigned int addr) {
    asm volatile("ldmatrix.sync.aligned.m8n8.x2.shared.b16 {%0,%1},[%2];"
        : "=r"(r0), "=r"(r1) : "r"(addr));
}
__device__ __forceinline__ void mma16816(float* d, const unsigned int* a,
                                         unsigned int b0, unsigned int b1) {
    asm volatile("mma.sync.aligned.m16n8k16.row.col.f32.bf16.bf16.f32 "
        "{%0,%1,%2,%3},{%4,%5,%6,%7},{%8,%9},{%0,%1,%2,%3};"
        : "+f"(d[0]), "+f"(d[1]), "+f"(d[2]), "+f"(d[3])
        : "r"(a[0]), "r"(a[1]), "r"(a[2]), "r"(a[3]), "r"(b0), "r"(b1));
}

// SMEM layout (bytes), dynamic, total 73728:
//  AH: [0,12288)  AL: [12288,24576)  BH: [24576,49152)  BL: [49152,73728)
//  A plane/buf = 128 rows * 48B ; B plane/buf = 256 rows * 48B (row = 16 bf16 + 8 pad)
#define MMA_SMEM_BYTES 73728

// stage one BK=16 slab (already prefetched into pa/pb regs) into buffer nb
__device__ __forceinline__ void stage_tile(unsigned char* smem, int nb, int row2, int seg, int tid,
    float4 pa0, float4 pa1, float4 pb0, float4 pb1, float4 pb2, float4 pb3)
{
    unsigned int al0, al1, al2, al3;
    unsigned int ah0 = bf2pack(pa0.x, pa0.y, al0);
    unsigned int ah1 = bf2pack(pa0.z, pa0.w, al1);
    unsigned int ah2 = bf2pack(pa1.x, pa1.y, al2);
    unsigned int ah3 = bf2pack(pa1.z, pa1.w, al3);
    unsigned int aoff = (unsigned int)nb * 6144u + (unsigned int)row2 * 48u + (unsigned int)seg * 16u;
    *(uint4*)(smem + aoff)           = make_uint4(ah0, ah1, ah2, ah3);
    *(uint4*)(smem + aoff + 12288u)  = make_uint4(al0, al1, al2, al3);

    unsigned int bl0, bl1, bl2, bl3, bl4, bl5, bl6, bl7;
    unsigned int bh0 = bf2pack(pb0.x, pb0.y, bl0);
    unsigned int bh1 = bf2pack(pb0.z, pb0.w, bl1);
    unsigned int bh2 = bf2pack(pb1.x, pb1.y, bl2);
    unsigned int bh3 = bf2pack(pb1.z, pb1.w, bl3);
    unsigned int bh4 = bf2pack(pb2.x, pb2.y, bl4);
    unsigned int bh5 = bf2pack(pb2.z, pb2.w, bl5);
    unsigned int bh6 = bf2pack(pb3.x, pb3.y, bl6);
    unsigned int bh7 = bf2pack(pb3.z, pb3.w, bl7);
    unsigned int boff = 24576u + (unsigned int)nb * 12288u + (unsigned int)tid * 48u;
    *(uint4*)(smem + boff)                 = make_uint4(bh0, bh1, bh2, bh3);
    *(uint4*)(smem + boff + 16u)           = make_uint4(bh4, bh5, bh6, bh7);
    *(uint4*)(smem + boff + 24576u)        = make_uint4(bl0, bl1, bl2, bl3);
    *(uint4*)(smem + boff + 24576u + 16u)  = make_uint4(bl4, bl5, bl6, bl7);
}

// C[M,N] = A[(gather)m, 0:512] @ Bw[n, 0:512]^T, K=512, BM=128, BN=256.
// modeFC==0: gi0 (A row gather via rowidx, epilogue += aux broadcast over batch, out ld G3)
// modeFC==1: FC  (mask vs g_len, +aux bias, scatter to (B,T,V), zero-fill masked tiles)
__global__ void __launch_bounds__(256)
mmagemm_kernel(const float* __restrict__ A, int lda, const int* __restrict__ rowidx,
               const float* __restrict__ Bw, int ldb,
               const float* __restrict__ aux,
               float* __restrict__ out, int Nmax, int modeFC)
{
    extern __shared__ unsigned char smem[];
    const int tid = threadIdx.x;
    const int m0 = blockIdx.y * 128;
    const int n0 = blockIdx.x * 256;
    const int t  = m0 >> 8;
    const int bbase = m0 & 255;

    if (modeFC != 0) {
        if (t >= g_len[bbase]) {            // whole tile past length -> zeros
            float4 z = make_float4(0.f, 0.f, 0.f, 0.f);
            for (int idx = tid * 4; idx < 128 * 256; idx += 1024) {
                int rr = idx >> 8;
                int cc = idx & 255;
                int gn = n0 + cc;
                if (gn < Nmax) {
                    int b = bbase + rr;
                    *(float4*)&out[((size_t)b * T_ + t) * V_ + gn] = z;
                }
            }
            return;
        }
    }

    const int lane = tid & 31;
    const int w = tid >> 5;
    const int warp_m = w & 1;
    const int warp_n = w >> 1;

    // staging assignments
    const int row2 = tid >> 1;
    const int seg = tid & 1;          // A: 128 rows, two 8-float halves
    int am = m0 + row2;
    int arow = rowidx ? rowidx[am] : am;
    const float* Ag = A + (size_t)arow * lda + seg * 8;
    int nrow = n0 + tid;
    if (nrow > Nmax - 1) nrow = Nmax - 1;
    const float* Bg = Bw + (size_t)nrow * ldb;

    // ldmatrix per-lane offsets
    const int lr8 = lane & 7;
    const int lsel = lane >> 3;
    const unsigned int a_off = (unsigned int)((lr8 + ((lsel & 1) << 3)) * 48 + (lsel >> 1) * 16);
    const unsigned int b_off = (unsigned int)(lr8 * 48 + (((lane >> 3) & 1) ? 16 : 0));
    const unsigned int sbase = s2u(smem);

    float acc[4][8][4];
    #pragma unroll
    for (int i = 0; i < 4; i++)
        #pragma unroll
        for (int j = 0; j < 8; j++)
            #pragma unroll
            for (int q = 0; q < 4; q++) acc[i][j][q] = 0.f;

    float4 pa0, pa1, pb0, pb1, pb2, pb3;
    // prefetch slab 0
    pa0 = *(const float4*)(Ag);
    pa1 = *(const float4*)(Ag + 4);
    pb0 = *(const float4*)(Bg);
    pb1 = *(const float4*)(Bg + 4);
    pb2 = *(const float4*)(Bg + 8);
    pb3 = *(const float4*)(Bg + 12);
    stage_tile(smem, 0, row2, seg, tid, pa0, pa1, pb0, pb1, pb2, pb3);
    __syncthreads();

    int buf = 0;
    for (int it = 0; it < 32; it++) {
        if (it < 31) {
            const float* ap = Ag + (it + 1) * 16;
            const float* bp = Bg + (it + 1) * 16;
            pa0 = *(const float4*)(ap);
            pa1 = *(const float4*)(ap + 4);
            pb0 = *(const float4*)(bp);
            pb1 = *(const float4*)(bp + 4);
            pb2 = *(const float4*)(bp + 8);
            pb3 = *(const float4*)(bp + 12);
        }

        // compute on current buffer
        unsigned int Ah[4][4], Al[4][4];
        #pragma unroll
        for (int i = 0; i < 4; i++) {
            unsigned int abase = sbase + (unsigned int)buf * 6144u
                               + (unsigned int)((warp_m * 4 + i) * 768) + a_off;
            ldsm_x4(Ah[i], abase);
            ldsm_x4(Al[i], abase + 12288u);
        }
        #pragma unroll
        for (int nt = 0; nt < 8; nt++) {
            unsigned int baddr = sbase + 24576u + (unsigned int)buf * 12288u
                               + (unsigned int)((warp_n * 8 + nt) * 384) + b_off;
            unsigned int bh0, bh1, bl0, bl1;
            ldsm_x2(bh0, bh1, baddr);
            ldsm_x2(bl0, bl1, baddr + 24576u);
            #pragma unroll
            for (int i = 0; i < 4; i++) {
                mma16816(acc[i][nt], Ah[i], bh0, bh1);   // hi*hi
                mma16816(acc[i][nt], Ah[i], bl0, bl1);   // hi*lo
                mma16816(acc[i][nt], Al[i], bh0, bh1);   // lo*hi
            }
        }

        if (it < 31)
            stage_tile(smem, buf ^ 1, row2, seg, tid, pa0, pa1, pb0, pb1, pb2, pb3);
        __syncthreads();
        buf ^= 1;
    }

    // epilogue: d0=(r,2c) d1=(r,2c+1) d2=(r+8,2c) d3=(r+8,2c+1)
    const int r  = lane >> 2;
    const int c2 = (lane & 3) * 2;
    #pragma unroll
    for (int i = 0; i < 4; i++) {
        int gm = m0 + (warp_m * 4 + i) * 16 + r;
        if (modeFC != 0) {
            int b1r = gm & 255;
            int b2r = b1r + 8;
            bool v1 = t < g_len[b1r];
            bool v2 = t < g_len[b2r];
            #pragma unroll
            for (int nt = 0; nt < 8; nt++) {
                int gn = n0 + (warp_n * 8 + nt) * 8 + c2;
                if (gn < Nmax) {
                    float bi0 = aux[gn];
                    float bi1 = aux[gn + 1];
                    float* d = acc[i][nt];
                    *(float2*)&out[((size_t)b1r * T_ + t) * V_ + gn] =
                        make_float2(v1 ? d[0] + bi0 : 0.f, v1 ? d[1] + bi1 : 0.f);
                    *(float2*)&out[((size_t)b2r * T_ + t) * V_ + gn] =
                        make_float2(v2 ? d[2] + bi0 : 0.f, v2 ? d[3] + bi1 : 0.f);
                }
            }
        } else {
            int br1 = gm & 255;
            int br2 = (gm + 8) & 255;
            #pragma unroll
            for (int nt = 0; nt < 8; nt++) {
                int gn = n0 + (warp_n * 8 + nt) * 8 + c2;
                if (gn < Nmax) {
                    float2 c1 = *(const float2*)&aux[(size_t)br1 * G3 + gn];
                    float2 cc2 = *(const float2*)&aux[(size_t)br2 * G3 + gn];
                    float* d = acc[i][nt];
                    *(float2*)&out[(size_t)gm * G3 + gn] =
                        make_float2(d[0] + c1.x, d[1] + c1.y);
                    *(float2*)&out[(size_t)(gm + 8) * G3 + gn] =
                        make_float2(d[2] + cc2.x, d[3] + cc2.y);
                }
            }
        }
    }
}

// ---------------- recurrence: fused GEMM+gate kernels (SIMT) ----------------
#define GRU_SEGMENT(ASRC, WSRC, ACCN)                                           \
    for (int k0 = 0; k0 < H_; k0 += 16) {                                       \
        { int r = tid >> 3, k = (tid * 2) & 15;                                 \
          float2 v = *(const float2*)&ASRC[(size_t)(m0 + r) * H_ + k0 + k];     \
          As[k][r] = v.x; As[k+1][r] = v.y; }                                   \
        { int hh = tid >> 3, k = (tid * 2) & 15;                                \
          _Pragma("unroll")                                                     \
          for (int j = 0; j < 3; j++) {                                         \
            float2 v = *(const float2*)&WSRC[(size_t)(j * H_ + hb + hh) * H_ + k0 + k]; \
            Ws[k][j*32 + hh] = v.x; Ws[k+1][j*32 + hh] = v.y; } }               \
        __syncthreads();                                                        \
        _Pragma("unroll")                                                       \
        for (int k = 0; k < 16; k++) {                                          \
            float A0 = As[k][ty2],     A1 = As[k][ty2+1];                       \
            float wr0 = Ws[k][tx2],    wr1 = Ws[k][tx2+1];                      \
            float wz0 = Ws[k][32+tx2], wz1 = Ws[k][32+tx2+1];                   \
            float wn0 = Ws[k][64+tx2], wn1 = Ws[k][64+tx2+1];                   \
            accr[0][0]+=A0*wr0; accr[0][1]+=A0*wr1; accr[1][0]+=A1*wr0; accr[1][1]+=A1*wr1; \
            accz[0][0]+=A0*wz0; accz[0][1]+=A0*wz1; accz[1][0]+=A1*wz0; accz[1][1]+=A1*wz1; \
            ACCN[0][0]+=A0*wn0; ACCN[0][1]+=A0*wn1; ACCN[1][0]+=A1*wn0; ACCN[1][1]+=A1*wn1; \
        }                                                                       \
        __syncthreads();                                                        \
    }

__global__ void __launch_bounds__(256)
gru0_kernel(const float* __restrict__ h0old, float* __restrict__ h0new,
            const float* __restrict__ w_hh0, const float* __restrict__ b_hh0, int t)
{
    int hb = blockIdx.x * 32;
    int m0 = blockIdx.y * 32;
    int tid = threadIdx.x;
    if (m0 >= g_nvalid[t]) {
        int r = tid >> 3, c0 = (tid & 7) * 4;
        *(float4*)&h0new[(size_t)(m0 + r) * H_ + hb + c0] =
            *(const float4*)&h0old[(size_t)(m0 + r) * H_ + hb + c0];
        return;
    }
    __shared__ float As[17][34];
    __shared__ float Ws[17][98];
    int tx = tid & 15, ty = tid >> 4;
    int tx2 = tx * 2, ty2 = ty * 2;
    float accr[2][2] = {}, accz[2][2] = {}, accn[2][2] = {};
    GRU_SEGMENT(h0old, w_hh0, accn)
    #pragma unroll
    for (int i = 0; i < 2; i++) {
        int b = m0 + ty2 + i;
        bool valid = t < g_len[b];
        const float* gi = g_gi0 + ((size_t)t * B_ + b) * G3;
        #pragma unroll
        for (int j = 0; j < 2; j++) {
            int h = hb + tx2 + j;
            float old = h0old[(size_t)b * H_ + h];
            float v;
            if (valid) {
                float r = sigf(gi[h]        + accr[i][j] + b_hh0[h]);
                float z = sigf(gi[h + H_]   + accz[i][j] + b_hh0[h + H_]);
                float n = tanhf(gi[h + 2*H_] + r * (accn[i][j] + b_hh0[h + 2*H_]));
                v = (1.f - z) * n + z * old;
            } else v = old;
            h0new[(size_t)b * H_ + h] = v;
        }
    }
}

__global__ void __launch_bounds__(256)
gru1_kernel(const float* __restrict__ h0cur, const float* __restrict__ h1old,
            float* __restrict__ h1new,
            const float* __restrict__ w_ih1, const float* __restrict__ w_hh1,
            const float* __restrict__ b_ih1, const float* __restrict__ b_hh1, int t)
{
    int hb = blockIdx.x * 32;
    int m0 = blockIdx.y * 32;
    int tid = threadIdx.x;
    float* H1r = g_H1 + (size_t)t * B_ * H_;
    if (m0 >= g_nvalid[t]) {
        int r = tid >> 3, c0 = (tid & 7) * 4;
        *(float4*)&h1new[(size_t)(m0 + r) * H_ + hb + c0] =
            *(const float4*)&h1old[(size_t)(m0 + r) * H_ + hb + c0];
        *(float4*)&H1r[(size_t)(m0 + r) * H_ + hb + c0] = make_float4(0.f,0.f,0.f,0.f);
        return;
    }
    __shared__ float As[17][34];
    __shared__ float Ws[17][98];
    int tx = tid & 15, ty = tid >> 4;
    int tx2 = tx * 2, ty2 = ty * 2;
    float accr[2][2] = {}, accz[2][2] = {}, accin[2][2] = {}, acchn[2][2] = {};
    GRU_SEGMENT(h0cur, w_ih1, accin)
    GRU_SEGMENT(h1old, w_hh1, acchn)
    #pragma unroll
    for (int i = 0; i < 2; i++) {
        int b = m0 + ty2 + i;
        bool valid = t < g_len[b];
        #pragma unroll
        for (int j = 0; j < 2; j++) {
            int h = hb + tx2 + j;
            float old = h1old[(size_t)b * H_ + h];
            size_t idx = (size_t)b * H_ + h;
            if (valid) {
                float r = sigf(accr[i][j] + b_ih1[h]        + b_hh1[h]);
                float z = sigf(accz[i][j] + b_ih1[h + H_]   + b_hh1[h + H_]);
                float n = tanhf(accin[i][j] + b_ih1[h + 2*H_]
                                + r * (acchn[i][j] + b_hh1[h + 2*H_]));
                float v = (1.f - z) * n + z * old;
                h1new[idx] = v;
                H1r[idx]   = v;
            } else {
                h1new[idx] = old;
                H1r[idx]   = 0.f;
            }
        }
    }
}

// ---------------- host orchestration (graph-capturable: launches only) ----------------
extern "C" void kernel_launch(void* const* d_in, const int* in_sizes, int n_in,
                              void* d_out, int out_size)
{
    const float* image_code = (const float*)d_in[0];
    const int*   captions   = (const int*)  d_in[1];
    const int*   cap_lens   = (const int*)  d_in[2];
    const float* embed_w    = (const float*)d_in[3];
    const float* init_w     = (const float*)d_in[4];
    const float* init_b     = (const float*)d_in[5];
    const float* w_ih0      = (const float*)d_in[6];
    const float* w_hh0      = (const float*)d_in[7];
    const float* b_ih0      = (const float*)d_in[8];
    const float* b_hh0      = (const float*)d_in[9];
    const float* w_ih1      = (const float*)d_in[10];
    const float* w_hh1      = (const float*)d_in[11];
    const float* b_ih1      = (const float*)d_in[12];
    const float* b_hh1      = (const float*)d_in[13];
    const float* fc_w       = (const float*)d_in[14];
    const float* fc_b       = (const float*)d_in[15];
    float* out = (float*)d_out;

    void* p;
    cudaGetSymbolAddress(&p, g_img);    float* dimg  = (float*)p;
    cudaGetSymbolAddress(&p, g_gi0c);   float* dgi0c = (float*)p;
    cudaGetSymbolAddress(&p, g_gi0);    float* dgi0  = (float*)p;
    cudaGetSymbolAddress(&p, g_h0a);    float* dh0a  = (float*)p;
    cudaGetSymbolAddress(&p, g_h0b);    float* dh0b  = (float*)p;
    cudaGetSymbolAddress(&p, g_h1a);    float* dh1a  = (float*)p;
    cudaGetSymbolAddress(&p, g_h1b);    float* dh1b  = (float*)p;
    cudaGetSymbolAddress(&p, g_H1);     float* dH1   = (float*)p;
    cudaGetSymbolAddress(&p, g_rowidx); int*   drow  = (int*)p;

    cudaFuncSetAttribute(mmagemm_kernel,
                         cudaFuncAttributeMaxDynamicSharedMemorySize, MMA_SMEM_BYTES);

    // 1. sort + metadata + aux outputs
    sort_kernel<<<1, 256>>>(cap_lens, captions, out, (long long)out_size);
    // 2. gather sorted image codes
    gather_img_kernel<<<(B_ * IC_) / 256, 256>>>(image_code);
    // 3. h0/h1 init in ONE GEMM: (256, 1024, K=2048)
    gemm64_kernel<<<dim3(16, 4), 256>>>(dimg, IC_, init_w, IC_, init_b,
                                        dh0a, H_, dh1a, IC_);
    // 4. time-invariant img part of layer0 input gates (+ b_ih0): (256, 1536, K=2048)
    gemm64_kernel<<<dim3(24, 4), 256>>>(dimg, IC_, w_ih0, IC_ + WD_, b_ih0,
                                        dgi0c, G3, nullptr, IC_);
    // 5. embedding-side layer0 input gates for ALL 12800 tokens (+ gi0c broadcast), tensor-core
    mmagemm_kernel<<<dim3(6, 100), 256, MMA_SMEM_BYTES>>>(
        embed_w, WD_, drow, w_ih0 + IC_, IC_ + WD_, dgi0c, dgi0, G3, 0);
    // 6. sequential recurrence: 2 fused kernels per step, ping-pong hidden buffers
    for (int t = 0; t < T_; t++) {
        float* h0o = (t & 1) ? dh0b : dh0a;
        float* h0n = (t & 1) ? dh0a : dh0b;
        float* h1o = (t & 1) ? dh1b : dh1a;
        float* h1n = (t & 1) ? dh1a : dh1b;
        gru0_kernel<<<dim3(16, 8), 256>>>(h0o, h0n, w_hh0, b_hh0, t);
        gru1_kernel<<<dim3(16, 8), 256>>>(h0n, h1o, h1n, w_ih1, w_hh1, b_ih1, b_hh1, t);
    }
    // 7. FC head on tensor cores: all (t,b) rows, masked + scattered to (B, T, V)
    mmagemm_kernel<<<dim3(40, 100), 256, MMA_SMEM_BYTES>>>(
        dH1, H_, nullptr, fc_w, H_, fc_b, out, V_, 1);
}

// round 6
// speedup vs baseline: 1.8908x; 1.2604x over previous
#include <cuda_runtime.h>
#include <cuda_bf16.h>
#include <stdint.h>
#include <cstdint>
#include <math.h>

// Problem constants
#define B_    256
#define TCAP  51
#define T_    50
#define V_    10000
#define WD_   512
#define H_    512
#define IC_   2048
#define G3    1536    // 3*H

// ---------------- static device scratch ----------------
__device__ float g_img [B_ * IC_];
__device__ float g_gi0c[B_ * G3];
__device__ float g_gi0 [(size_t)T_ * B_ * G3];   // precomputed layer0 input gates
__device__ float g_h0a [B_ * H_];
__device__ float g_h0b [B_ * H_];
__device__ float g_h1a [B_ * H_];
__device__ float g_h1b [B_ * H_];
__device__ int   g_order [B_];
__device__ int   g_len   [B_];
__device__ int   g_nvalid[T_];
__device__ int   g_rowidx[T_ * B_];

// bf16 hi/lo planes (preconverted weights + per-step H1)
__device__ __nv_bfloat16 g_fcw_h [(size_t)V_ * H_];
__device__ __nv_bfloat16 g_fcw_l [(size_t)V_ * H_];
__device__ __nv_bfloat16 g_emb_h [(size_t)V_ * H_];
__device__ __nv_bfloat16 g_emb_l [(size_t)V_ * H_];
__device__ __nv_bfloat16 g_wih0e_h[G3 * H_];
__device__ __nv_bfloat16 g_wih0e_l[G3 * H_];
__device__ __nv_bfloat16 g_whh0_h [G3 * H_];
__device__ __nv_bfloat16 g_whh0_l [G3 * H_];
__device__ __nv_bfloat16 g_wih1_h [G3 * H_];
__device__ __nv_bfloat16 g_wih1_l [G3 * H_];
__device__ __nv_bfloat16 g_whh1_h [G3 * H_];
__device__ __nv_bfloat16 g_whh1_l [G3 * H_];
__device__ __nv_bfloat16 g_H1h [(size_t)T_ * B_ * H_];
__device__ __nv_bfloat16 g_H1l [(size_t)T_ * B_ * H_];

__device__ __forceinline__ float sigf(float x) { return 1.f / (1.f + expf(-x)); }

// ---------------- weight preconversion: fp32 -> bf16 hi + bf16 lo ----------------
__global__ void convw_kernel(const float* __restrict__ src, int ld, int col0,
                             __nv_bfloat16* __restrict__ dh,
                             __nv_bfloat16* __restrict__ dl, int n)
{
    int i = blockIdx.x * 256 + threadIdx.x;
    if (i >= n) return;
    int row = i >> 9;        // 512 cols always
    int col = i & 511;
    float x = src[(size_t)row * ld + col0 + col];
    __nv_bfloat16 h = __float2bfloat16_rn(x);
    dh[i] = h;
    dl[i] = __float2bfloat16_rn(x - __bfloat162float(h));
}

// ---------------- sort + metadata (stable descending by cap_len) ----------------
__global__ void sort_kernel(const int* __restrict__ cap_lens,
                            const int* __restrict__ captions,
                            float* __restrict__ out, long long out_size)
{
    __shared__ int lens[B_];
    __shared__ int ord [B_];
    int i = threadIdx.x;
    lens[i] = cap_lens[i];
    __syncthreads();
    int li = lens[i];
    int rank = 0;
    #pragma unroll 8
    for (int j = 0; j < B_; j++) {
        int lj = lens[j];
        rank += (lj > li) || (lj == li && j < i);
    }
    ord[rank] = i;
    __syncthreads();
    int src = ord[i];
    int len = lens[src] - 1;
    g_order[i] = src;
    g_len[i]   = len;
    if (i < T_) {
        int c = 0;
        #pragma unroll 8
        for (int b = 0; b < B_; b++) c += (lens[ord[b]] - 1) > i;
        g_nvalid[i] = c;
    }
    const long long PRED = (long long)B_ * T_ * V_;
    for (int t = 0; t < TCAP; t++) {
        int tok = captions[src * TCAP + t];
        if (t < T_) g_rowidx[t * B_ + i] = tok;
        if (out_size >= PRED + (long long)B_ * TCAP)
            out[PRED + (long long)i * TCAP + t] = (float)tok;
    }
    if (out_size >= PRED + (long long)B_ * TCAP + 2LL * B_) {
        out[PRED + (long long)B_ * TCAP + i]      = (float)len;
        out[PRED + (long long)B_ * TCAP + B_ + i] = (float)src;
    }
}

__global__ void gather_img_kernel(const float* __restrict__ image_code)
{
    int idx = blockIdx.x * 256 + threadIdx.x;
    int b = idx >> 11, k = idx & 2047;
    g_img[idx] = image_code[g_order[b] * IC_ + k];
}

// ---------------- 64x64 tile SIMT GEMM for deep-K prologue (inits, gi0c) ----------------
__global__ void __launch_bounds__(256)
gemm64_kernel(const float* __restrict__ A, int lda,
              const float* __restrict__ Bw, int ldb,
              const float* __restrict__ bias,
              float* __restrict__ C, int ldc, float* __restrict__ Cb, int K)
{
    __shared__ float As[16][68];
    __shared__ float Bs[16][68];
    int m0 = blockIdx.y * 64, n0 = blockIdx.x * 64;
    int tid = threadIdx.x;
    int lr = tid >> 2, kq = (tid & 3) * 4;
    const float* Ap = A  + (size_t)(m0 + lr) * lda + kq;
    const float* Bp = Bw + (size_t)(n0 + lr) * ldb + kq;
    int tx = tid & 15, ty = tid >> 4;
    float acc[4][4] = {};
    for (int k0 = 0; k0 < K; k0 += 16) {
        float4 av = *(const float4*)(Ap + k0);
        float4 bv = *(const float4*)(Bp + k0);
        As[kq+0][lr]=av.x; As[kq+1][lr]=av.y; As[kq+2][lr]=av.z; As[kq+3][lr]=av.w;
        Bs[kq+0][lr]=bv.x; Bs[kq+1][lr]=bv.y; Bs[kq+2][lr]=bv.z; Bs[kq+3][lr]=bv.w;
        __syncthreads();
        #pragma unroll
        for (int k = 0; k < 16; k++) {
            float4 a = *(const float4*)&As[k][ty*4];
            float4 b = *(const float4*)&Bs[k][tx*4];
            acc[0][0]+=a.x*b.x; acc[0][1]+=a.x*b.y; acc[0][2]+=a.x*b.z; acc[0][3]+=a.x*b.w;
            acc[1][0]+=a.y*b.x; acc[1][1]+=a.y*b.y; acc[1][2]+=a.y*b.z; acc[1][3]+=a.y*b.w;
            acc[2][0]+=a.z*b.x; acc[2][1]+=a.z*b.y; acc[2][2]+=a.z*b.z; acc[2][3]+=a.z*b.w;
            acc[3][0]+=a.w*b.x; acc[3][1]+=a.w*b.y; acc[3][2]+=a.w*b.z; acc[3][3]+=a.w*b.w;
        }
        __syncthreads();
    }
    #pragma unroll
    for (int i = 0; i < 4; i++) {
        int m = m0 + ty * 4 + i;
        #pragma unroll
        for (int j = 0; j < 4; j++) {
            int n = n0 + tx * 4 + j;
            float v = acc[i][j] + (bias ? bias[n] : 0.f);
            if (Cb) {
                if (n < H_) C [(size_t)m * H_ + n]       = v;
                else        Cb[(size_t)m * H_ + (n-H_)]  = v;
            } else {
                C[(size_t)m * ldc + n] = v;
            }
        }
    }
}

// ---------------- tensor-core bf16-3term GEMM machinery ----------------
__device__ __forceinline__ unsigned int s2u(const void* p) {
    return (unsigned int)__cvta_generic_to_shared(p);
}
// pack (x,y) as bf16 hi pair (return) and residual lo pair (out param)
__device__ __forceinline__ unsigned int bf2pack(float x, float y, unsigned int& lo) {
    __nv_bfloat16 hx = __float2bfloat16_rn(x);
    __nv_bfloat16 hy = __float2bfloat16_rn(y);
    float rx = x - __bfloat162float(hx);
    float ry = y - __bfloat162float(hy);
    unsigned short lx = __bfloat16_as_ushort(__float2bfloat16_rn(rx));
    unsigned short ly = __bfloat16_as_ushort(__float2bfloat16_rn(ry));
    lo = (unsigned int)lx | ((unsigned int)ly << 16);
    return (unsigned int)__bfloat16_as_ushort(hx) | ((unsigned int)__bfloat16_as_ushort(hy) << 16);
}
__device__ __forceinline__ void ldsm_x4(unsigned int* r, unsigned int addr) {
    asm volatile("ldmatrix.sync.aligned.m8n8.x4.shared.b16 {%0,%1,%2,%3},[%4];"
        : "=r"(r[0]), "=r"(r[1]), "=r"(r[2]), "=r"(r[3]) : "r"(addr));
}
__device__ __forceinline__ void ldsm_x2(unsigned int& r0, unsigned int& r1, unsigned int addr) {
    asm volatile("ldmatrix.sync.aligned.m8n8.x2.shared.b16 {%0,%1},[%2];"
        : "=r"(r0), "=r"(r1) : "r"(addr));
}
__device__ __forceinline__ void mma16816(float* d, const unsigned int* a,
                                         unsigned int b0, unsigned int b1) {
    asm volatile("mma.sync.aligned.m16n8k16.row.col.f32.bf16.bf16.f32 "
        "{%0,%1,%2,%3},{%4,%5,%6,%7},{%8,%9},{%0,%1,%2,%3};"
        : "+f"(d[0]), "+f"(d[1]), "+f"(d[2]), "+f"(d[3])
        : "r"(a[0]), "r"(a[1]), "r"(a[2]), "r"(a[3]), "r"(b0), "r"(b1));
}

// SMEM layout (bytes), dynamic, total 73728:
//  AH: [0,12288)  AL: [12288,24576)  BH: [24576,49152)  BL: [49152,73728)
//  A plane/buf = 128 rows * 48B ; B plane/buf = 256 rows * 48B (row = 16 bf16 + 8 pad)
#define MMA_SMEM_BYTES 73728

// C[M,N] = A[(gather)m, 0:512] @ Bw[n, 0:512]^T, K=512, BM=128, BN=256.
// A and B given as preconverted bf16 hi/lo planes (row-major, 512 cols).
// modeFC==0: gi0 (A row gather via rowidx, epilogue += aux broadcast over batch, out ld G3)
// modeFC==1: FC  (mask vs g_len, +aux bias, scatter to (B,T,V), zero-fill masked tiles)
__global__ void __launch_bounds__(256)
mmagemm_kernel(const __nv_bfloat16* __restrict__ Ah, const __nv_bfloat16* __restrict__ Al,
               const int* __restrict__ rowidx,
               const __nv_bfloat16* __restrict__ Bh, const __nv_bfloat16* __restrict__ Bl,
               const float* __restrict__ aux,
               float* __restrict__ out, int Nmax, int modeFC)
{
    extern __shared__ unsigned char smem[];
    const int tid = threadIdx.x;
    const int m0 = blockIdx.y * 128;
    const int n0 = blockIdx.x * 256;
    const int t  = m0 >> 8;
    const int bbase = m0 & 255;

    if (modeFC != 0) {
        if (t >= g_len[bbase]) {            // whole tile past length -> zeros
            float4 z = make_float4(0.f, 0.f, 0.f, 0.f);
            for (int idx = tid * 4; idx < 128 * 256; idx += 1024) {
                int rr = idx >> 8;
                int cc = idx & 255;
                int gn = n0 + cc;
                if (gn < Nmax) {
                    int b = bbase + rr;
                    *(float4*)&out[((size_t)b * T_ + t) * V_ + gn] = z;
                }
            }
            return;
        }
    }

    const int lane = tid & 31;
    const int w = tid >> 5;
    const int warp_m = w & 1;
    const int warp_n = w >> 1;

    // staging assignments
    const int row2 = tid >> 1;
    const int seg = tid & 1;          // A: 128 rows, two 16B halves per plane
    int am = m0 + row2;
    int arow = rowidx ? rowidx[am] : am;
    const char* Agh = (const char*)Ah + ((size_t)arow * H_) * 2 + seg * 16;
    const char* Agl = (const char*)Al + ((size_t)arow * H_) * 2 + seg * 16;
    int nrow = n0 + tid;
    if (nrow > Nmax - 1) nrow = Nmax - 1;
    const char* Bgh = (const char*)Bh + ((size_t)nrow * H_) * 2;
    const char* Bgl = (const char*)Bl + ((size_t)nrow * H_) * 2;

    // ldmatrix per-lane offsets
    const int lr8 = lane & 7;
    const int lsel = lane >> 3;
    const unsigned int a_off = (unsigned int)((lr8 + ((lsel & 1) << 3)) * 48 + (lsel >> 1) * 16);
    const unsigned int b_off = (unsigned int)(lr8 * 48 + (((lane >> 3) & 1) ? 16 : 0));
    const unsigned int sbase = s2u(smem);

    float acc[4][8][4];
    #pragma unroll
    for (int i = 0; i < 4; i++)
        #pragma unroll
        for (int j = 0; j < 8; j++)
            #pragma unroll
            for (int q = 0; q < 4; q++) acc[i][j][q] = 0.f;

    uint4 pah, pal, pbh0, pbh1, pbl0, pbl1;
    // prefetch slab 0 (bf16: 16 elems = 32B per row per plane)
    pah  = *(const uint4*)(Agh);
    pal  = *(const uint4*)(Agl);
    pbh0 = *(const uint4*)(Bgh);
    pbh1 = *(const uint4*)(Bgh + 16);
    pbl0 = *(const uint4*)(Bgl);
    pbl1 = *(const uint4*)(Bgl + 16);
    {
        unsigned int aoff = (unsigned int)row2 * 48u + (unsigned int)seg * 16u;
        *(uint4*)(smem + aoff)           = pah;
        *(uint4*)(smem + aoff + 12288u)  = pal;
        unsigned int boff = 24576u + (unsigned int)tid * 48u;
        *(uint4*)(smem + boff)                 = pbh0;
        *(uint4*)(smem + boff + 16u)           = pbh1;
        *(uint4*)(smem + boff + 24576u)        = pbl0;
        *(uint4*)(smem + boff + 24576u + 16u)  = pbl1;
    }
    __syncthreads();

    int buf = 0;
    for (int it = 0; it < 32; it++) {
        if (it < 31) {
            int koff = (it + 1) * 32;     // bytes: 16 bf16 per slab
            pah  = *(const uint4*)(Agh + koff);
            pal  = *(const uint4*)(Agl + koff);
            pbh0 = *(const uint4*)(Bgh + koff);
            pbh1 = *(const uint4*)(Bgh + koff + 16);
            pbl0 = *(const uint4*)(Bgl + koff);
            pbl1 = *(const uint4*)(Bgl + koff + 16);
        }

        // compute on current buffer
        unsigned int Ahf[4][4], Alf[4][4];
        #pragma unroll
        for (int i = 0; i < 4; i++) {
            unsigned int abase = sbase + (unsigned int)buf * 6144u
                               + (unsigned int)((warp_m * 4 + i) * 768) + a_off;
            ldsm_x4(Ahf[i], abase);
            ldsm_x4(Alf[i], abase + 12288u);
        }
        #pragma unroll
        for (int nt = 0; nt < 8; nt++) {
            unsigned int baddr = sbase + 24576u + (unsigned int)buf * 12288u
                               + (unsigned int)((warp_n * 8 + nt) * 384) + b_off;
            unsigned int bh0, bh1, bl0, bl1;
            ldsm_x2(bh0, bh1, baddr);
            ldsm_x2(bl0, bl1, baddr + 24576u);
            #pragma unroll
            for (int i = 0; i < 4; i++) {
                mma16816(acc[i][nt], Ahf[i], bh0, bh1);   // hi*hi
                mma16816(acc[i][nt], Ahf[i], bl0, bl1);   // hi*lo
                mma16816(acc[i][nt], Alf[i], bh0, bh1);   // lo*hi
            }
        }

        if (it < 31) {
            int nb = buf ^ 1;
            unsigned int aoff = (unsigned int)nb * 6144u
                              + (unsigned int)row2 * 48u + (unsigned int)seg * 16u;
            *(uint4*)(smem + aoff)           = pah;
            *(uint4*)(smem + aoff + 12288u)  = pal;
            unsigned int boff = 24576u + (unsigned int)nb * 12288u + (unsigned int)tid * 48u;
            *(uint4*)(smem + boff)                 = pbh0;
            *(uint4*)(smem + boff + 16u)           = pbh1;
            *(uint4*)(smem + boff + 24576u)        = pbl0;
            *(uint4*)(smem + boff + 24576u + 16u)  = pbl1;
        }
        __syncthreads();
        buf ^= 1;
    }

    // epilogue: d0=(r,2c) d1=(r,2c+1) d2=(r+8,2c) d3=(r+8,2c+1)
    const int r  = lane >> 2;
    const int c2 = (lane & 3) * 2;
    #pragma unroll
    for (int i = 0; i < 4; i++) {
        int gm = m0 + (warp_m * 4 + i) * 16 + r;
        if (modeFC != 0) {
            int b1r = gm & 255;
            int b2r = b1r + 8;
            bool v1 = t < g_len[b1r];
            bool v2 = t < g_len[b2r];
            #pragma unroll
            for (int nt = 0; nt < 8; nt++) {
                int gn = n0 + (warp_n * 8 + nt) * 8 + c2;
                if (gn < Nmax) {
                    float bi0 = aux[gn];
                    float bi1 = aux[gn + 1];
                    float* d = acc[i][nt];
                    *(float2*)&out[((size_t)b1r * T_ + t) * V_ + gn] =
                        make_float2(v1 ? d[0] + bi0 : 0.f, v1 ? d[1] + bi1 : 0.f);
                    *(float2*)&out[((size_t)b2r * T_ + t) * V_ + gn] =
                        make_float2(v2 ? d[2] + bi0 : 0.f, v2 ? d[3] + bi1 : 0.f);
                }
            }
        } else {
            int br1 = gm & 255;
            int br2 = (gm + 8) & 255;
            #pragma unroll
            for (int nt = 0; nt < 8; nt++) {
                int gn = n0 + (warp_n * 8 + nt) * 8 + c2;
                if (gn < Nmax) {
                    float2 c1 = *(const float2*)&aux[(size_t)br1 * G3 + gn];
                    float2 cc2 = *(const float2*)&aux[(size_t)br2 * G3 + gn];
                    float* d = acc[i][nt];
                    *(float2*)&out[(size_t)gm * G3 + gn] =
                        make_float2(d[0] + c1.x, d[1] + c1.y);
                    *(float2*)&out[(size_t)(gm + 8) * G3 + gn] =
                        make_float2(d[2] + cc2.x, d[3] + cc2.y);
                }
            }
        }
    }
}

// ================= tensor-core GRU recurrence =================
// Block tile: 32 batch rows x 32 h-cols (96 gate rows: r,z,n). grid (16, 8).
// SMEM layout (bytes):
//   A stage: buf*3072 + plane*1536 + row*48 + half*16        [0, 6144)
//   B stage: 6144 + buf*9216 + plane*4608 + row*48 + half*16 [6144, 24576)
//   Cs1 (floats, stride 100): [24576, 37376)
//   Cs2: [37376, 50176)
#define GRU_SMEM_BYTES 50176

__device__ __forceinline__ void gru_storeA(unsigned char* smem, int buf, int row, int half,
                                           float4 v0, float4 v1)
{
    unsigned int l0, l1, l2, l3;
    unsigned int h0 = bf2pack(v0.x, v0.y, l0);
    unsigned int h1 = bf2pack(v0.z, v0.w, l1);
    unsigned int h2 = bf2pack(v1.x, v1.y, l2);
    unsigned int h3 = bf2pack(v1.z, v1.w, l3);
    unsigned int off = (unsigned int)buf * 3072u + (unsigned int)row * 48u
                     + (unsigned int)half * 16u;
    *(uint4*)(smem + off)          = make_uint4(h0, h1, h2, h3);
    *(uint4*)(smem + off + 1536u)  = make_uint4(l0, l1, l2, l3);
}

__device__ __forceinline__ const uint4* gruB_src(const __nv_bfloat16* Wh,
                                                 const __nv_bfloat16* Wl,
                                                 int idx, int hb, int k0)
{
    int plane = idx / 192;
    int r2 = idx - plane * 192;
    int row = r2 >> 1, half = r2 & 1;
    int gate = row >> 5;
    int wrow = gate * H_ + hb + (row & 31);
    const __nv_bfloat16* W = plane ? Wl : Wh;
    return (const uint4*)((const char*)W + ((size_t)wrow * H_ + k0) * 2 + half * 16);
}
__device__ __forceinline__ unsigned int gruB_dst(int idx, int buf)
{
    int plane = idx / 192;
    int r2 = idx - plane * 192;
    int row = r2 >> 1, half = r2 & 1;
    return 6144u + (unsigned int)buf * 9216u + (unsigned int)plane * 4608u
         + (unsigned int)row * 48u + (unsigned int)half * 16u;
}

__device__ __forceinline__ void gru_compute(unsigned int sbase, int buf,
    int warp_m, int warp_n, unsigned int a_off, unsigned int b_off, float acc[3][4])
{
    unsigned int Ahf[4], Alf[4];
    unsigned int abase = sbase + (unsigned int)buf * 3072u
                       + (unsigned int)(warp_m * 16) * 48u + a_off;
    ldsm_x4(Ahf, abase);
    ldsm_x4(Alf, abase + 1536u);
    #pragma unroll
    for (int nt = 0; nt < 3; nt++) {
        unsigned int bb = sbase + 6144u + (unsigned int)buf * 9216u
                        + (unsigned int)((warp_n * 24 + nt * 8) * 48) + b_off;
        unsigned int bh0, bh1, bl0, bl1;
        ldsm_x2(bh0, bh1, bb);
        ldsm_x2(bl0, bl1, bb + 4608u);
        mma16816(acc[nt], Ahf, bh0, bh1);
        mma16816(acc[nt], Ahf, bl0, bl1);
        mma16816(acc[nt], Alf, bh0, bh1);
    }
}

// full K=512 segment: acc += A[m0..m0+32, :] @ W[gates rows, :]^T
__device__ __forceinline__ void gru_segment(unsigned char* smem, unsigned int sbase,
    int tid, int warp_m, int warp_n, unsigned int a_off, unsigned int b_off,
    const float* __restrict__ Asrc, int m0,
    const __nv_bfloat16* __restrict__ Wh, const __nv_bfloat16* __restrict__ Wl, int hb,
    float acc[3][4])
{
    // iter 0 staging (direct)
    if (tid < 64) {
        int row = tid >> 1, half = tid & 1;
        const float* p = Asrc + (size_t)(m0 + row) * H_ + half * 8;
        gru_storeA(smem, 0, row, half, *(const float4*)p, *(const float4*)(p + 4));
    }
    *(uint4*)(smem + gruB_dst(tid, 0)) = *gruB_src(Wh, Wl, tid, hb, 0);
    if (tid < 128)
        *(uint4*)(smem + gruB_dst(tid + 256, 0)) = *gruB_src(Wh, Wl, tid + 256, hb, 0);
    __syncthreads();

    int buf = 0;
    for (int it = 0; it < 32; it++) {
        float4 pa0, pa1;
        uint4 pb0, pb1;
        if (it < 31) {
            int k0 = (it + 1) * 16;
            if (tid < 64) {
                int row = tid >> 1, half = tid & 1;
                const float* p = Asrc + (size_t)(m0 + row) * H_ + k0 + half * 8;
                pa0 = *(const float4*)p;
                pa1 = *(const float4*)(p + 4);
            }
            pb0 = *gruB_src(Wh, Wl, tid, hb, k0);
            if (tid < 128) pb1 = *gruB_src(Wh, Wl, tid + 256, hb, k0);
        }
        gru_compute(sbase, buf, warp_m, warp_n, a_off, b_off, acc);
        if (it < 31) {
            int nb = buf ^ 1;
            if (tid < 64) {
                int row = tid >> 1, half = tid & 1;
                gru_storeA(smem, nb, row, half, pa0, pa1);
            }
            *(uint4*)(smem + gruB_dst(tid, nb)) = pb0;
            if (tid < 128) *(uint4*)(smem + gruB_dst(tid + 256, nb)) = pb1;
        }
        __syncthreads();
        buf ^= 1;
    }
}

__device__ __forceinline__ void gru_dump(unsigned char* smem, int csoff,
    int warp_m, int warp_n, int lane, float acc[3][4])
{
    float* Cs = (float*)(smem + csoff);
    int lr = lane >> 2, lc = (lane & 3) * 2;
    #pragma unroll
    for (int nt = 0; nt < 3; nt++) {
        int rowt = warp_m * 16 + lr;
        int col = warp_n * 24 + nt * 8 + lc;
        Cs[rowt * 100 + col]           = acc[nt][0];
        Cs[rowt * 100 + col + 1]       = acc[nt][1];
        Cs[(rowt + 8) * 100 + col]     = acc[nt][2];
        Cs[(rowt + 8) * 100 + col + 1] = acc[nt][3];
    }
}

// Phase A: h0_new = GRU0(gi0[t], h0_old)   grid (16, 8), 256 threads
__global__ void __launch_bounds__(256)
gru0mma_kernel(const float* __restrict__ h0old, float* __restrict__ h0new,
               const float* __restrict__ b_hh0, int t)
{
    extern __shared__ unsigned char smem[];
    int hb = blockIdx.x * 32;
    int m0 = blockIdx.y * 32;
    int tid = threadIdx.x;
    if (m0 >= g_nvalid[t]) {                 // fully masked tile: carry hidden
        int row = tid >> 3, c4 = (tid & 7) * 4;
        *(float4*)&h0new[(size_t)(m0 + row) * H_ + hb + c4] =
            *(const float4*)&h0old[(size_t)(m0 + row) * H_ + hb + c4];
        return;
    }
    const int lane = tid & 31;
    const int wrp = tid >> 5;
    const int warp_m = wrp >> 2;
    const int warp_n = wrp & 3;
    const int lr8 = lane & 7;
    const int lsel = lane >> 3;
    const unsigned int a_off = (unsigned int)((lr8 + ((lsel & 1) << 3)) * 48 + (lsel >> 1) * 16);
    const unsigned int b_off = (unsigned int)(lr8 * 48 + (((lane >> 3) & 1) ? 16 : 0));
    const unsigned int sbase = s2u(smem);

    float acc[3][4];
    #pragma unroll
    for (int i = 0; i < 3; i++)
        #pragma unroll
        for (int q = 0; q < 4; q++) acc[i][q] = 0.f;

    gru_segment(smem, sbase, tid, warp_m, warp_n, a_off, b_off,
                h0old, m0, g_whh0_h, g_whh0_l, hb, acc);
    gru_dump(smem, 24576, warp_m, warp_n, lane, acc);
    __syncthreads();

    const float* Cs = (const float*)(smem + 24576);
    #pragma unroll
    for (int q = 0; q < 4; q++) {
        int i = tid + q * 256;
        int m = i >> 5, hl = i & 31;
        int b = m0 + m;
        int h = hb + hl;
        float old = h0old[(size_t)b * H_ + h];
        float v;
        if (t < g_len[b]) {
            const float* gi = g_gi0 + ((size_t)t * B_ + b) * G3;
            float r = sigf(gi[h]        + Cs[m * 100 + hl]      + b_hh0[h]);
            float z = sigf(gi[512 + h]  + Cs[m * 100 + 32 + hl] + b_hh0[512 + h]);
            float n = tanhf(gi[1024 + h] + r * (Cs[m * 100 + 64 + hl] + b_hh0[1024 + h]));
            v = (1.f - z) * n + z * old;
        } else v = old;
        h0new[(size_t)b * H_ + h] = v;
    }
}

// Phase B: h1_new = GRU1(h0_cur, h1_old); store H1 bf16 planes   grid (16, 8)
__global__ void __launch_bounds__(256)
gru1mma_kernel(const float* __restrict__ h0cur, const float* __restrict__ h1old,
               float* __restrict__ h1new,
               const float* __restrict__ b_ih1, const float* __restrict__ b_hh1, int t)
{
    extern __shared__ unsigned char smem[];
    int hb = blockIdx.x * 32;
    int m0 = blockIdx.y * 32;
    int tid = threadIdx.x;
    if (m0 >= g_nvalid[t]) {
        int row = tid >> 3, c4 = (tid & 7) * 4;
        *(float4*)&h1new[(size_t)(m0 + row) * H_ + hb + c4] =
            *(const float4*)&h1old[(size_t)(m0 + row) * H_ + hb + c4];
        size_t hidx = ((size_t)t * B_ + m0 + row) * H_ + hb + c4;
        *(uint2*)((char*)g_H1h + hidx * 2) = make_uint2(0u, 0u);
        *(uint2*)((char*)g_H1l + hidx * 2) = make_uint2(0u, 0u);
        return;
    }
    const int lane = tid & 31;
    const int wrp = tid >> 5;
    const int warp_m = wrp >> 2;
    const int warp_n = wrp & 3;
    const int lr8 = lane & 7;
    const int lsel = lane >> 3;
    const unsigned int a_off = (unsigned int)((lr8 + ((lsel & 1) << 3)) * 48 + (lsel >> 1) * 16);
    const unsigned int b_off = (unsigned int)(lr8 * 48 + (((lane >> 3) & 1) ? 16 : 0));
    const unsigned int sbase = s2u(smem);

    float acc[3][4];
    #pragma unroll
    for (int i = 0; i < 3; i++)
        #pragma unroll
        for (int q = 0; q < 4; q++) acc[i][q] = 0.f;

    // segment 1: input side (h0cur @ w_ih1^T) -> Cs1
    gru_segment(smem, sbase, tid, warp_m, warp_n, a_off, b_off,
                h0cur, m0, g_wih1_h, g_wih1_l, hb, acc);
    gru_dump(smem, 24576, warp_m, warp_n, lane, acc);

    #pragma unroll
    for (int i = 0; i < 3; i++)
        #pragma unroll
        for (int q = 0; q < 4; q++) acc[i][q] = 0.f;

    // segment 2: hidden side (h1old @ w_hh1^T) -> Cs2
    gru_segment(smem, sbase, tid, warp_m, warp_n, a_off, b_off,
                h1old, m0, g_whh1_h, g_whh1_l, hb, acc);
    gru_dump(smem, 37376, warp_m, warp_n, lane, acc);
    __syncthreads();

    const float* Cs1 = (const float*)(smem + 24576);
    const float* Cs2 = (const float*)(smem + 37376);
    #pragma unroll
    for (int q = 0; q < 4; q++) {
        int i = tid + q * 256;
        int m = i >> 5, hl = i & 31;
        int b = m0 + m;
        int h = hb + hl;
        size_t idx = (size_t)b * H_ + h;
        size_t hidx = ((size_t)t * B_ + b) * H_ + h;
        float old = h1old[idx];
        if (t < g_len[b]) {
            float r = sigf(Cs1[m * 100 + hl]      + b_ih1[h]
                         + Cs2[m * 100 + hl]      + b_hh1[h]);
            float z = sigf(Cs1[m * 100 + 32 + hl] + b_ih1[512 + h]
                         + Cs2[m * 100 + 32 + hl] + b_hh1[512 + h]);
            float n = tanhf(Cs1[m * 100 + 64 + hl] + b_ih1[1024 + h]
                          + r * (Cs2[m * 100 + 64 + hl] + b_hh1[1024 + h]));
            float v = (1.f - z) * n + z * old;
            h1new[idx] = v;
            __nv_bfloat16 vh = __float2bfloat16_rn(v);
            g_H1h[hidx] = vh;
            g_H1l[hidx] = __float2bfloat16_rn(v - __bfloat162float(vh));
        } else {
            h1new[idx] = old;
            g_H1h[hidx] = __float2bfloat16_rn(0.f);
            g_H1l[hidx] = __float2bfloat16_rn(0.f);
        }
    }
}

// ---------------- host orchestration (graph-capturable: launches only) ----------------
extern "C" void kernel_launch(void* const* d_in, const int* in_sizes, int n_in,
                              void* d_out, int out_size)
{
    const float* image_code = (const float*)d_in[0];
    const int*   captions   = (const int*)  d_in[1];
    const int*   cap_lens   = (const int*)  d_in[2];
    const float* embed_w    = (const float*)d_in[3];
    const float* init_w     = (const float*)d_in[4];
    const float* init_b     = (const float*)d_in[5];
    const float* w_ih0      = (const float*)d_in[6];
    const float* w_hh0      = (const float*)d_in[7];
    const float* b_ih0      = (const float*)d_in[8];
    const float* b_hh0      = (const float*)d_in[9];
    const float* w_ih1      = (const float*)d_in[10];
    const float* w_hh1      = (const float*)d_in[11];
    const float* b_ih1      = (const float*)d_in[12];
    const float* b_hh1      = (const float*)d_in[13];
    const float* fc_w       = (const float*)d_in[14];
    const float* fc_b       = (const float*)d_in[15];
    float* out = (float*)d_out;

    void* p;
    cudaGetSymbolAddress(&p, g_img);     float* dimg  = (float*)p;
    cudaGetSymbolAddress(&p, g_gi0c);    float* dgi0c = (float*)p;
    cudaGetSymbolAddress(&p, g_gi0);     float* dgi0  = (float*)p;
    cudaGetSymbolAddress(&p, g_h0a);     float* dh0a  = (float*)p;
    cudaGetSymbolAddress(&p, g_h0b);     float* dh0b  = (float*)p;
    cudaGetSymbolAddress(&p, g_h1a);     float* dh1a  = (float*)p;
    cudaGetSymbolAddress(&p, g_h1b);     float* dh1b  = (float*)p;
    cudaGetSymbolAddress(&p, g_rowidx);  int*   drow  = (int*)p;
    cudaGetSymbolAddress(&p, g_fcw_h);   __nv_bfloat16* dfcwh = (__nv_bfloat16*)p;
    cudaGetSymbolAddress(&p, g_fcw_l);   __nv_bfloat16* dfcwl = (__nv_bfloat16*)p;
    cudaGetSymbolAddress(&p, g_emb_h);   __nv_bfloat16* dembh = (__nv_bfloat16*)p;
    cudaGetSymbolAddress(&p, g_emb_l);   __nv_bfloat16* dembl = (__nv_bfloat16*)p;
    cudaGetSymbolAddress(&p, g_wih0e_h); __nv_bfloat16* dw0h  = (__nv_bfloat16*)p;
    cudaGetSymbolAddress(&p, g_wih0e_l); __nv_bfloat16* dw0l  = (__nv_bfloat16*)p;
    cudaGetSymbolAddress(&p, g_whh0_h);  __nv_bfloat16* dwh0h = (__nv_bfloat16*)p;
    cudaGetSymbolAddress(&p, g_whh0_l);  __nv_bfloat16* dwh0l = (__nv_bfloat16*)p;
    cudaGetSymbolAddress(&p, g_wih1_h);  __nv_bfloat16* dwi1h = (__nv_bfloat16*)p;
    cudaGetSymbolAddress(&p, g_wih1_l);  __nv_bfloat16* dwi1l = (__nv_bfloat16*)p;
    cudaGetSymbolAddress(&p, g_whh1_h);  __nv_bfloat16* dwh1h = (__nv_bfloat16*)p;
    cudaGetSymbolAddress(&p, g_whh1_l);  __nv_bfloat16* dwh1l = (__nv_bfloat16*)p;
    cudaGetSymbolAddress(&p, g_H1h);     __nv_bfloat16* dH1h  = (__nv_bfloat16*)p;
    cudaGetSymbolAddress(&p, g_H1l);     __nv_bfloat16* dH1l  = (__nv_bfloat16*)p;

    cudaFuncSetAttribute(mmagemm_kernel,
                         cudaFuncAttributeMaxDynamicSharedMemorySize, MMA_SMEM_BYTES);
    cudaFuncSetAttribute(gru0mma_kernel,
                         cudaFuncAttributeMaxDynamicSharedMemorySize, GRU_SMEM_BYTES);
    cudaFuncSetAttribute(gru1mma_kernel,
                         cudaFuncAttributeMaxDynamicSharedMemorySize, GRU_SMEM_BYTES);

    // 0. weight preconversion to bf16 hi/lo planes
    const int NW = V_ * H_;          // 5.12M
    const int NG = G3 * H_;          // 786432
    convw_kernel<<<(NW + 255) / 256, 256>>>(fc_w,    H_, 0,   dfcwh, dfcwl, NW);
    convw_kernel<<<(NW + 255) / 256, 256>>>(embed_w, H_, 0,   dembh, dembl, NW);
    convw_kernel<<<(NG + 255) / 256, 256>>>(w_ih0, IC_ + WD_, IC_, dw0h, dw0l, NG);
    convw_kernel<<<(NG + 255) / 256, 256>>>(w_hh0,   H_, 0,   dwh0h, dwh0l, NG);
    convw_kernel<<<(NG + 255) / 256, 256>>>(w_ih1,   H_, 0,   dwi1h, dwi1l, NG);
    convw_kernel<<<(NG + 255) / 256, 256>>>(w_hh1,   H_, 0,   dwh1h, dwh1l, NG);

    // 1. sort + metadata + aux outputs
    sort_kernel<<<1, 256>>>(cap_lens, captions, out, (long long)out_size);
    // 2. gather sorted image codes
    gather_img_kernel<<<(B_ * IC_) / 256, 256>>>(image_code);
    // 3. h0/h1 init in ONE GEMM: (256, 1024, K=2048)
    gemm64_kernel<<<dim3(16, 4), 256>>>(dimg, IC_, init_w, IC_, init_b,
                                        dh0a, H_, dh1a, IC_);
    // 4. time-invariant img part of layer0 input gates (+ b_ih0): (256, 1536, K=2048)
    gemm64_kernel<<<dim3(24, 4), 256>>>(dimg, IC_, w_ih0, IC_ + WD_, b_ih0,
                                        dgi0c, G3, nullptr, IC_);
    // 5. embedding-side layer0 input gates for ALL 12800 tokens (+ gi0c broadcast)
    mmagemm_kernel<<<dim3(6, 100), 256, MMA_SMEM_BYTES>>>(
        dembh, dembl, drow, dw0h, dw0l, dgi0c, dgi0, G3, 0);
    // 6. sequential recurrence: 2 tensor-core kernels per step, ping-pong hidden buffers
    for (int t = 0; t < T_; t++) {
        float* h0o = (t & 1) ? dh0b : dh0a;
        float* h0n = (t & 1) ? dh0a : dh0b;
        float* h1o = (t & 1) ? dh1b : dh1a;
        float* h1n = (t & 1) ? dh1a : dh1b;
        gru0mma_kernel<<<dim3(16, 8), 256, GRU_SMEM_BYTES>>>(h0o, h0n, b_hh0, t);
        gru1mma_kernel<<<dim3(16, 8), 256, GRU_SMEM_BYTES>>>(h0n, h1o, h1n, b_ih1, b_hh1, t);
    }
    // 7. FC head on tensor cores: all (t,b) rows, masked + scattered to (B, T, V)
    mmagemm_kernel<<<dim3(40, 100), 256, MMA_SMEM_BYTES>>>(
        dH1h, dH1l, nullptr, dfcwh, dfcwl, fc_b, out, V_, 1);
}

// round 7
// speedup vs baseline: 2.5164x; 1.3309x over previous
#include <cuda_runtime.h>
#include <cuda_bf16.h>
#include <stdint.h>
#include <cstdint>
#include <math.h>

// Problem constants
#define B_    256
#define TCAP  51
#define T_    50
#define V_    10000
#define WD_   512
#define H_    512
#define IC_   2048
#define G3    1536    // 3*H
#define NBLK  128     // persistent recurrence blocks (1 wave on 148 SMs)

// ---------------- static device scratch ----------------
__device__ float g_img [B_ * IC_];
__device__ float g_gi0c[B_ * G3];
__device__ float g_gi0 [(size_t)T_ * B_ * G3];   // precomputed layer0 input gates
__device__ float g_h0f [2][B_ * H_];             // fp32 hidden ping-pong
__device__ float g_h1f [2][B_ * H_];
__device__ int   g_order [B_];
__device__ int   g_len   [B_];
__device__ int   g_nvalid[T_];
__device__ int   g_rowidx[T_ * B_];
__device__ unsigned int g_barcnt;                // monotonic grid barrier

// bf16 hi/lo planes (preconverted weights, hidden states, H1)
__device__ __nv_bfloat16 g_fcw_h [(size_t)V_ * H_];
__device__ __nv_bfloat16 g_fcw_l [(size_t)V_ * H_];
__device__ __nv_bfloat16 g_emb_h [(size_t)V_ * H_];
__device__ __nv_bfloat16 g_emb_l [(size_t)V_ * H_];
__device__ __nv_bfloat16 g_wih0e_h[G3 * H_];
__device__ __nv_bfloat16 g_wih0e_l[G3 * H_];
__device__ __nv_bfloat16 g_whh0_h [G3 * H_];
__device__ __nv_bfloat16 g_whh0_l [G3 * H_];
__device__ __nv_bfloat16 g_wih1_h [G3 * H_];
__device__ __nv_bfloat16 g_wih1_l [G3 * H_];
__device__ __nv_bfloat16 g_whh1_h [G3 * H_];
__device__ __nv_bfloat16 g_whh1_l [G3 * H_];
__device__ __nv_bfloat16 g_h0ph[2][B_ * H_];
__device__ __nv_bfloat16 g_h0pl[2][B_ * H_];
__device__ __nv_bfloat16 g_h1ph[2][B_ * H_];
__device__ __nv_bfloat16 g_h1pl[2][B_ * H_];
__device__ __nv_bfloat16 g_H1h [(size_t)T_ * B_ * H_];
__device__ __nv_bfloat16 g_H1l [(size_t)T_ * B_ * H_];

__device__ __forceinline__ float sigf(float x) { return 1.f / (1.f + expf(-x)); }

// ---------------- weight preconversion: fp32 -> bf16 hi + bf16 lo ----------------
__global__ void convw_kernel(const float* __restrict__ src, int ld, int col0,
                             __nv_bfloat16* __restrict__ dh,
                             __nv_bfloat16* __restrict__ dl, int n)
{
    int i = blockIdx.x * 256 + threadIdx.x;
    if (i >= n) return;
    int row = i >> 9;        // 512 cols always
    int col = i & 511;
    float x = src[(size_t)row * ld + col0 + col];
    __nv_bfloat16 h = __float2bfloat16_rn(x);
    dh[i] = h;
    dl[i] = __float2bfloat16_rn(x - __bfloat162float(h));
}

// ---------------- sort + metadata (stable descending by cap_len) ----------------
__global__ void sort_kernel(const int* __restrict__ cap_lens,
                            const int* __restrict__ captions,
                            float* __restrict__ out, long long out_size)
{
    __shared__ int lens[B_];
    __shared__ int ord [B_];
    int i = threadIdx.x;
    lens[i] = cap_lens[i];
    __syncthreads();
    int li = lens[i];
    int rank = 0;
    #pragma unroll 8
    for (int j = 0; j < B_; j++) {
        int lj = lens[j];
        rank += (lj > li) || (lj == li && j < i);
    }
    ord[rank] = i;
    __syncthreads();
    int src = ord[i];
    int len = lens[src] - 1;
    g_order[i] = src;
    g_len[i]   = len;
    if (i < T_) {
        int c = 0;
        #pragma unroll 8
        for (int b = 0; b < B_; b++) c += (lens[ord[b]] - 1) > i;
        g_nvalid[i] = c;
    }
    const long long PRED = (long long)B_ * T_ * V_;
    for (int t = 0; t < TCAP; t++) {
        int tok = captions[src * TCAP + t];
        if (t < T_) g_rowidx[t * B_ + i] = tok;
        if (out_size >= PRED + (long long)B_ * TCAP)
            out[PRED + (long long)i * TCAP + t] = (float)tok;
    }
    if (out_size >= PRED + (long long)B_ * TCAP + 2LL * B_) {
        out[PRED + (long long)B_ * TCAP + i]      = (float)len;
        out[PRED + (long long)B_ * TCAP + B_ + i] = (float)src;
    }
}

__global__ void gather_img_kernel(const float* __restrict__ image_code)
{
    int idx = blockIdx.x * 256 + threadIdx.x;
    int b = idx >> 11, k = idx & 2047;
    g_img[idx] = image_code[g_order[b] * IC_ + k];
}

// ---------------- 64x64 tile SIMT GEMM for deep-K prologue (inits, gi0c) ----------------
__global__ void __launch_bounds__(256)
gemm64_kernel(const float* __restrict__ A, int lda,
              const float* __restrict__ Bw, int ldb,
              const float* __restrict__ bias,
              float* __restrict__ C, int ldc, float* __restrict__ Cb, int K)
{
    __shared__ float As[16][68];
    __shared__ float Bs[16][68];
    int m0 = blockIdx.y * 64, n0 = blockIdx.x * 64;
    int tid = threadIdx.x;
    int lr = tid >> 2, kq = (tid & 3) * 4;
    const float* Ap = A  + (size_t)(m0 + lr) * lda + kq;
    const float* Bp = Bw + (size_t)(n0 + lr) * ldb + kq;
    int tx = tid & 15, ty = tid >> 4;
    float acc[4][4] = {};
    for (int k0 = 0; k0 < K; k0 += 16) {
        float4 av = *(const float4*)(Ap + k0);
        float4 bv = *(const float4*)(Bp + k0);
        As[kq+0][lr]=av.x; As[kq+1][lr]=av.y; As[kq+2][lr]=av.z; As[kq+3][lr]=av.w;
        Bs[kq+0][lr]=bv.x; Bs[kq+1][lr]=bv.y; Bs[kq+2][lr]=bv.z; Bs[kq+3][lr]=bv.w;
        __syncthreads();
        #pragma unroll
        for (int k = 0; k < 16; k++) {
            float4 a = *(const float4*)&As[k][ty*4];
            float4 b = *(const float4*)&Bs[k][tx*4];
            acc[0][0]+=a.x*b.x; acc[0][1]+=a.x*b.y; acc[0][2]+=a.x*b.z; acc[0][3]+=a.x*b.w;
            acc[1][0]+=a.y*b.x; acc[1][1]+=a.y*b.y; acc[1][2]+=a.y*b.z; acc[1][3]+=a.y*b.w;
            acc[2][0]+=a.z*b.x; acc[2][1]+=a.z*b.y; acc[2][2]+=a.z*b.z; acc[2][3]+=a.z*b.w;
            acc[3][0]+=a.w*b.x; acc[3][1]+=a.w*b.y; acc[3][2]+=a.w*b.z; acc[3][3]+=a.w*b.w;
        }
        __syncthreads();
    }
    #pragma unroll
    for (int i = 0; i < 4; i++) {
        int m = m0 + ty * 4 + i;
        #pragma unroll
        for (int j = 0; j < 4; j++) {
            int n = n0 + tx * 4 + j;
            float v = acc[i][j] + (bias ? bias[n] : 0.f);
            if (Cb) {
                if (n < H_) C [(size_t)m * H_ + n]       = v;
                else        Cb[(size_t)m * H_ + (n-H_)]  = v;
            } else {
                C[(size_t)m * ldc + n] = v;
            }
        }
    }
}

// ---------------- tensor-core bf16-3term GEMM machinery ----------------
__device__ __forceinline__ unsigned int s2u(const void* p) {
    return (unsigned int)__cvta_generic_to_shared(p);
}
__device__ __forceinline__ void ldsm_x4(unsigned int* r, unsigned int addr) {
    asm volatile("ldmatrix.sync.aligned.m8n8.x4.shared.b16 {%0,%1,%2,%3},[%4];"
        : "=r"(r[0]), "=r"(r[1]), "=r"(r[2]), "=r"(r[3]) : "r"(addr));
}
__device__ __forceinline__ void ldsm_x2(unsigned int& r0, unsigned int& r1, unsigned int addr) {
    asm volatile("ldmatrix.sync.aligned.m8n8.x2.shared.b16 {%0,%1},[%2];"
        : "=r"(r0), "=r"(r1) : "r"(addr));
}
__device__ __forceinline__ void mma16816(float* d, const unsigned int* a,
                                         unsigned int b0, unsigned int b1) {
    asm volatile("mma.sync.aligned.m16n8k16.row.col.f32.bf16.bf16.f32 "
        "{%0,%1,%2,%3},{%4,%5,%6,%7},{%8,%9},{%0,%1,%2,%3};"
        : "+f"(d[0]), "+f"(d[1]), "+f"(d[2]), "+f"(d[3])
        : "r"(a[0]), "r"(a[1]), "r"(a[2]), "r"(a[3]), "r"(b0), "r"(b1));
}
__device__ __forceinline__ void cpasync16(unsigned int dst, const void* src) {
    asm volatile("cp.async.cg.shared.global [%0], [%1], 16;"
        :: "r"(dst), "l"(src) : "memory");
}
__device__ __forceinline__ void cp_commit() {
    asm volatile("cp.async.commit_group;" ::: "memory");
}
__device__ __forceinline__ void cp_wait2() {
    asm volatile("cp.async.wait_group 2;" ::: "memory");
}

// ---------------- big parallel mma GEMM (gi0 + FC), round-6-proven ----------------
// SMEM layout (bytes), dynamic, total 73728:
//  AH: [0,12288)  AL: [12288,24576)  BH: [24576,49152)  BL: [49152,73728)
#define MMA_SMEM_BYTES 73728

__global__ void __launch_bounds__(256)
mmagemm_kernel(const __nv_bfloat16* __restrict__ Ah, const __nv_bfloat16* __restrict__ Al,
               const int* __restrict__ rowidx,
               const __nv_bfloat16* __restrict__ Bh, const __nv_bfloat16* __restrict__ Bl,
               const float* __restrict__ aux,
               float* __restrict__ out, int Nmax, int modeFC)
{
    extern __shared__ unsigned char smem[];
    const int tid = threadIdx.x;
    const int m0 = blockIdx.y * 128;
    const int n0 = blockIdx.x * 256;
    const int t  = m0 >> 8;
    const int bbase = m0 & 255;

    if (modeFC != 0) {
        if (t >= g_len[bbase]) {            // whole tile past length -> zeros
            float4 z = make_float4(0.f, 0.f, 0.f, 0.f);
            for (int idx = tid * 4; idx < 128 * 256; idx += 1024) {
                int rr = idx >> 8;
                int cc = idx & 255;
                int gn = n0 + cc;
                if (gn < Nmax) {
                    int b = bbase + rr;
                    *(float4*)&out[((size_t)b * T_ + t) * V_ + gn] = z;
                }
            }
            return;
        }
    }

    const int lane = tid & 31;
    const int w = tid >> 5;
    const int warp_m = w & 1;
    const int warp_n = w >> 1;

    const int row2 = tid >> 1;
    const int seg = tid & 1;
    int am = m0 + row2;
    int arow = rowidx ? rowidx[am] : am;
    const char* Agh = (const char*)Ah + ((size_t)arow * H_) * 2 + seg * 16;
    const char* Agl = (const char*)Al + ((size_t)arow * H_) * 2 + seg * 16;
    int nrow = n0 + tid;
    if (nrow > Nmax - 1) nrow = Nmax - 1;
    const char* Bgh = (const char*)Bh + ((size_t)nrow * H_) * 2;
    const char* Bgl = (const char*)Bl + ((size_t)nrow * H_) * 2;

    const int lr8 = lane & 7;
    const int lsel = lane >> 3;
    const unsigned int a_off = (unsigned int)((lr8 + ((lsel & 1) << 3)) * 48 + (lsel >> 1) * 16);
    const unsigned int b_off = (unsigned int)(lr8 * 48 + (((lane >> 3) & 1) ? 16 : 0));
    const unsigned int sbase = s2u(smem);

    float acc[4][8][4];
    #pragma unroll
    for (int i = 0; i < 4; i++)
        #pragma unroll
        for (int j = 0; j < 8; j++)
            #pragma unroll
            for (int q = 0; q < 4; q++) acc[i][j][q] = 0.f;

    uint4 pah, pal, pbh0, pbh1, pbl0, pbl1;
    pah  = *(const uint4*)(Agh);
    pal  = *(const uint4*)(Agl);
    pbh0 = *(const uint4*)(Bgh);
    pbh1 = *(const uint4*)(Bgh + 16);
    pbl0 = *(const uint4*)(Bgl);
    pbl1 = *(const uint4*)(Bgl + 16);
    {
        unsigned int aoff = (unsigned int)row2 * 48u + (unsigned int)seg * 16u;
        *(uint4*)(smem + aoff)           = pah;
        *(uint4*)(smem + aoff + 12288u)  = pal;
        unsigned int boff = 24576u + (unsigned int)tid * 48u;
        *(uint4*)(smem + boff)                 = pbh0;
        *(uint4*)(smem + boff + 16u)           = pbh1;
        *(uint4*)(smem + boff + 24576u)        = pbl0;
        *(uint4*)(smem + boff + 24576u + 16u)  = pbl1;
    }
    __syncthreads();

    int buf = 0;
    for (int it = 0; it < 32; it++) {
        if (it < 31) {
            int koff = (it + 1) * 32;
            pah  = *(const uint4*)(Agh + koff);
            pal  = *(const uint4*)(Agl + koff);
            pbh0 = *(const uint4*)(Bgh + koff);
            pbh1 = *(const uint4*)(Bgh + koff + 16);
            pbl0 = *(const uint4*)(Bgl + koff);
            pbl1 = *(const uint4*)(Bgl + koff + 16);
        }

        unsigned int Ahf[4][4], Alf[4][4];
        #pragma unroll
        for (int i = 0; i < 4; i++) {
            unsigned int abase = sbase + (unsigned int)buf * 6144u
                               + (unsigned int)((warp_m * 4 + i) * 768) + a_off;
            ldsm_x4(Ahf[i], abase);
            ldsm_x4(Alf[i], abase + 12288u);
        }
        #pragma unroll
        for (int nt = 0; nt < 8; nt++) {
            unsigned int baddr = sbase + 24576u + (unsigned int)buf * 12288u
                               + (unsigned int)((warp_n * 8 + nt) * 384) + b_off;
            unsigned int bh0, bh1, bl0, bl1;
            ldsm_x2(bh0, bh1, baddr);
            ldsm_x2(bl0, bl1, baddr + 24576u);
            #pragma unroll
            for (int i = 0; i < 4; i++) {
                mma16816(acc[i][nt], Ahf[i], bh0, bh1);
                mma16816(acc[i][nt], Ahf[i], bl0, bl1);
                mma16816(acc[i][nt], Alf[i], bh0, bh1);
            }
        }

        if (it < 31) {
            int nb = buf ^ 1;
            unsigned int aoff = (unsigned int)nb * 6144u
                              + (unsigned int)row2 * 48u + (unsigned int)seg * 16u;
            *(uint4*)(smem + aoff)           = pah;
            *(uint4*)(smem + aoff + 12288u)  = pal;
            unsigned int boff = 24576u + (unsigned int)nb * 12288u + (unsigned int)tid * 48u;
            *(uint4*)(smem + boff)                 = pbh0;
            *(uint4*)(smem + boff + 16u)           = pbh1;
            *(uint4*)(smem + boff + 24576u)        = pbl0;
            *(uint4*)(smem + boff + 24576u + 16u)  = pbl1;
        }
        __syncthreads();
        buf ^= 1;
    }

    const int r  = lane >> 2;
    const int c2 = (lane & 3) * 2;
    #pragma unroll
    for (int i = 0; i < 4; i++) {
        int gm = m0 + (warp_m * 4 + i) * 16 + r;
        if (modeFC != 0) {
            int b1r = gm & 255;
            int b2r = b1r + 8;
            bool v1 = t < g_len[b1r];
            bool v2 = t < g_len[b2r];
            #pragma unroll
            for (int nt = 0; nt < 8; nt++) {
                int gn = n0 + (warp_n * 8 + nt) * 8 + c2;
                if (gn < Nmax) {
                    float bi0 = aux[gn];
                    float bi1 = aux[gn + 1];
                    float* d = acc[i][nt];
                    *(float2*)&out[((size_t)b1r * T_ + t) * V_ + gn] =
                        make_float2(v1 ? d[0] + bi0 : 0.f, v1 ? d[1] + bi1 : 0.f);
                    *(float2*)&out[((size_t)b2r * T_ + t) * V_ + gn] =
                        make_float2(v2 ? d[2] + bi0 : 0.f, v2 ? d[3] + bi1 : 0.f);
                }
            }
        } else {
            int br1 = gm & 255;
            int br2 = (gm + 8) & 255;
            #pragma unroll
            for (int nt = 0; nt < 8; nt++) {
                int gn = n0 + (warp_n * 8 + nt) * 8 + c2;
                if (gn < Nmax) {
                    float2 c1 = *(const float2*)&aux[(size_t)br1 * G3 + gn];
                    float2 cc2 = *(const float2*)&aux[(size_t)br2 * G3 + gn];
                    float* d = acc[i][nt];
                    *(float2*)&out[(size_t)gm * G3 + gn] =
                        make_float2(d[0] + c1.x, d[1] + c1.y);
                    *(float2*)&out[(size_t)(gm + 8) * G3 + gn] =
                        make_float2(d[2] + cc2.x, d[3] + cc2.y);
                }
            }
        }
    }
}

// ================= persistent tensor-core GRU recurrence =================
// 128 blocks x 256 threads, all 50 steps inside. Per block: 32 batch x 32 h-cols.
// SMEM: 4 cp.async stages x 12288 B (A planes 3072 + B planes 9216), then
//       Cs1 [49152,61952), Cs2 [61952,74752).  Total 74752 B.
#define PS_SMEM   74752
#define STAGE_SZ  12288

__device__ __forceinline__ void grid_bar()
{
    __syncthreads();
    if (threadIdx.x == 0) {
        __threadfence();
        unsigned int my = atomicAdd(&g_barcnt, 1u) + 1u;
        unsigned int target = ((my + NBLK - 1u) / NBLK) * NBLK;
        while (atomicAdd(&g_barcnt, 0u) < target) { }
    }
    __syncthreads();
}

// chunk idx in [0,512): A chunks [0,128), B chunks [128,512)
__device__ __forceinline__ void ps_issue_chunk(int idx, int slab, int st,
    const __nv_bfloat16* __restrict__ Aph, const __nv_bfloat16* __restrict__ Apl, int m0,
    const __nv_bfloat16* __restrict__ Wh, const __nv_bfloat16* __restrict__ Wl, int hb,
    unsigned int sbase)
{
    if (idx < 128) {
        int plane = idx >> 6, r2 = idx & 63, row = r2 >> 1, half = r2 & 1;
        const __nv_bfloat16* P = plane ? Apl : Aph;
        const char* src = (const char*)P + ((size_t)(m0 + row) * H_ + slab * 16 + half * 8) * 2;
        unsigned int dst = sbase + (unsigned int)st * STAGE_SZ + (unsigned int)plane * 1536u
                         + (unsigned int)row * 48u + (unsigned int)half * 16u;
        cpasync16(dst, src);
    } else {
        int j = idx - 128;
        int plane = j / 192, r2 = j % 192, row = r2 >> 1, half = r2 & 1;
        int wrow = (row >> 5) * H_ + hb + (row & 31);
        const __nv_bfloat16* P = plane ? Wl : Wh;
        const char* src = (const char*)P + ((size_t)wrow * H_ + slab * 16 + half * 8) * 2;
        unsigned int dst = sbase + (unsigned int)st * STAGE_SZ + 3072u
                         + (unsigned int)plane * 4608u
                         + (unsigned int)row * 48u + (unsigned int)half * 16u;
        cpasync16(dst, src);
    }
}

__device__ __forceinline__ void ps_segment(unsigned int sbase, int tid,
    int warp_m, int warp_n, unsigned int a_off, unsigned int b_off,
    const __nv_bfloat16* __restrict__ Aph, const __nv_bfloat16* __restrict__ Apl, int m0,
    const __nv_bfloat16* __restrict__ Wh, const __nv_bfloat16* __restrict__ Wl, int hb,
    float acc[3][4])
{
    // prologue: fill stages 0..2
    #pragma unroll
    for (int s = 0; s < 3; s++) {
        ps_issue_chunk(tid,       s, s, Aph, Apl, m0, Wh, Wl, hb, sbase);
        ps_issue_chunk(tid + 256, s, s, Aph, Apl, m0, Wh, Wl, hb, sbase);
        cp_commit();
    }
    for (int it = 0; it < 32; it++) {
        cp_wait2();
        __syncthreads();
        int st = it & 3;
        // compute on stage st
        {
            unsigned int Ahf[4], Alf[4];
            unsigned int abase = sbase + (unsigned int)st * STAGE_SZ
                               + (unsigned int)(warp_m * 16) * 48u + a_off;
            ldsm_x4(Ahf, abase);
            ldsm_x4(Alf, abase + 1536u);
            #pragma unroll
            for (int nt = 0; nt < 3; nt++) {
                unsigned int bb = sbase + (unsigned int)st * STAGE_SZ + 3072u
                                + (unsigned int)((warp_n * 24 + nt * 8) * 48) + b_off;
                unsigned int bh0, bh1, bl0, bl1;
                ldsm_x2(bh0, bh1, bb);
                ldsm_x2(bl0, bl1, bb + 4608u);
                mma16816(acc[nt], Ahf, bh0, bh1);
                mma16816(acc[nt], Ahf, bl0, bl1);
                mma16816(acc[nt], Alf, bh0, bh1);
            }
        }
        if (it + 3 < 32) {
            int ns = (it + 3) & 3;
            ps_issue_chunk(tid,       it + 3, ns, Aph, Apl, m0, Wh, Wl, hb, sbase);
            ps_issue_chunk(tid + 256, it + 3, ns, Aph, Apl, m0, Wh, Wl, hb, sbase);
        }
        cp_commit();
    }
    __syncthreads();   // stages free for next segment
}

__device__ __forceinline__ void ps_dump(unsigned char* smem, int csoff,
    int warp_m, int warp_n, int lane, float acc[3][4])
{
    float* Cs = (float*)(smem + csoff);
    int lr = lane >> 2, lc = (lane & 3) * 2;
    #pragma unroll
    for (int nt = 0; nt < 3; nt++) {
        int rowt = warp_m * 16 + lr;
        int col = warp_n * 24 + nt * 8 + lc;
        Cs[rowt * 100 + col]           = acc[nt][0];
        Cs[rowt * 100 + col + 1]       = acc[nt][1];
        Cs[(rowt + 8) * 100 + col]     = acc[nt][2];
        Cs[(rowt + 8) * 100 + col + 1] = acc[nt][3];
    }
}

__global__ void __launch_bounds__(256)
gru_persistent(const float* __restrict__ b_hh0,
               const float* __restrict__ b_ih1, const float* __restrict__ b_hh1)
{
    extern __shared__ unsigned char smem[];
    const int bx = blockIdx.x;
    const int hb = (bx & 15) * 32;
    const int m0 = (bx >> 4) * 32;
    const int tid = threadIdx.x;
    const int lane = tid & 31;
    const int wrp = tid >> 5;
    const int warp_m = wrp >> 2;
    const int warp_n = wrp & 3;
    const int lr8 = lane & 7;
    const int lsel = lane >> 3;
    const unsigned int a_off = (unsigned int)((lr8 + ((lsel & 1) << 3)) * 48 + (lsel >> 1) * 16);
    const unsigned int b_off = (unsigned int)(lr8 * 48 + (((lane >> 3) & 1) ? 16 : 0));
    const unsigned int sbase = s2u(smem);

    for (int t = 0; t < T_; t++) {
        const int ot = t & 1, nt2 = ot ^ 1;
        const float* h0of = g_h0f[ot];
        float*       h0nf = g_h0f[nt2];
        const float* h1of = g_h1f[ot];
        float*       h1nf = g_h1f[nt2];
        bool active = m0 < g_nvalid[t];

        // ---------------- phase A: h0_new = GRU0(gi0[t], h0_old) ----------------
        if (active) {
            float acc[3][4];
            #pragma unroll
            for (int i = 0; i < 3; i++)
                #pragma unroll
                for (int q = 0; q < 4; q++) acc[i][q] = 0.f;
            ps_segment(sbase, tid, warp_m, warp_n, a_off, b_off,
                       g_h0ph[ot], g_h0pl[ot], m0, g_whh0_h, g_whh0_l, hb, acc);
            ps_dump(smem, 49152, warp_m, warp_n, lane, acc);
            __syncthreads();
            const float* Cs = (const float*)(smem + 49152);
            #pragma unroll
            for (int q = 0; q < 4; q++) {
                int i = tid + q * 256;
                int m = i >> 5, hl = i & 31;
                int b = m0 + m;
                int h = hb + hl;
                size_t idx = (size_t)b * H_ + h;
                float old = h0of[idx];
                float v;
                if (t < g_len[b]) {
                    const float* gi = g_gi0 + ((size_t)t * B_ + b) * G3;
                    float r = sigf(gi[h]        + Cs[m * 100 + hl]      + b_hh0[h]);
                    float z = sigf(gi[512 + h]  + Cs[m * 100 + 32 + hl] + b_hh0[512 + h]);
                    float n = tanhf(gi[1024 + h] + r * (Cs[m * 100 + 64 + hl] + b_hh0[1024 + h]));
                    v = (1.f - z) * n + z * old;
                } else v = old;
                h0nf[idx] = v;
                __nv_bfloat16 vh = __float2bfloat16_rn(v);
                g_h0ph[nt2][idx] = vh;
                g_h0pl[nt2][idx] = __float2bfloat16_rn(v - __bfloat162float(vh));
            }
        } else {
            // carry tile: fp32 + planes (own tile, self-written last step)
            int row = tid >> 3, c4 = (tid & 7) * 4;
            size_t idx = (size_t)(m0 + row) * H_ + hb + c4;
            *(float4*)&h0nf[idx] = *(const float4*)&h0of[idx];
            *(uint2*)((char*)&g_h0ph[nt2][idx]) = *(const uint2*)((const char*)&g_h0ph[ot][idx]);
            *(uint2*)((char*)&g_h0pl[nt2][idx]) = *(const uint2*)((const char*)&g_h0pl[ot][idx]);
        }
        grid_bar();

        // ---------------- phase B: h1_new = GRU1(h0_new, h1_old) ----------------
        if (active) {
            float acc[3][4];
            #pragma unroll
            for (int i = 0; i < 3; i++)
                #pragma unroll
                for (int q = 0; q < 4; q++) acc[i][q] = 0.f;
            ps_segment(sbase, tid, warp_m, warp_n, a_off, b_off,
                       g_h0ph[nt2], g_h0pl[nt2], m0, g_wih1_h, g_wih1_l, hb, acc);
            ps_dump(smem, 49152, warp_m, warp_n, lane, acc);
            #pragma unroll
            for (int i = 0; i < 3; i++)
                #pragma unroll
                for (int q = 0; q < 4; q++) acc[i][q] = 0.f;
            ps_segment(sbase, tid, warp_m, warp_n, a_off, b_off,
                       g_h1ph[ot], g_h1pl[ot], m0, g_whh1_h, g_whh1_l, hb, acc);
            ps_dump(smem, 61952, warp_m, warp_n, lane, acc);
            __syncthreads();
            const float* Cs1 = (const float*)(smem + 49152);
            const float* Cs2 = (const float*)(smem + 61952);
            #pragma unroll
            for (int q = 0; q < 4; q++) {
                int i = tid + q * 256;
                int m = i >> 5, hl = i & 31;
                int b = m0 + m;
                int h = hb + hl;
                size_t idx = (size_t)b * H_ + h;
                size_t hidx = ((size_t)t * B_ + b) * H_ + h;
                float old = h1of[idx];
                if (t < g_len[b]) {
                    float r = sigf(Cs1[m * 100 + hl]      + b_ih1[h]
                                 + Cs2[m * 100 + hl]      + b_hh1[h]);
                    float z = sigf(Cs1[m * 100 + 32 + hl] + b_ih1[512 + h]
                                 + Cs2[m * 100 + 32 + hl] + b_hh1[512 + h]);
                    float n = tanhf(Cs1[m * 100 + 64 + hl] + b_ih1[1024 + h]
                                  + r * (Cs2[m * 100 + 64 + hl] + b_hh1[1024 + h]));
                    float v = (1.f - z) * n + z * old;
                    h1nf[idx] = v;
                    __nv_bfloat16 vh = __float2bfloat16_rn(v);
                    g_h1ph[nt2][idx] = vh;
                    g_h1pl[nt2][idx] = __float2bfloat16_rn(v - __bfloat162float(vh));
                    g_H1h[hidx] = vh;
                    g_H1l[hidx] = __float2bfloat16_rn(v - __bfloat162float(vh));
                } else {
                    h1nf[idx] = old;
                    g_h1ph[nt2][idx] = g_h1ph[ot][idx];
                    g_h1pl[nt2][idx] = g_h1pl[ot][idx];
                    g_H1h[hidx] = __float2bfloat16_rn(0.f);
                    g_H1l[hidx] = __float2bfloat16_rn(0.f);
                }
            }
        } else {
            int row = tid >> 3, c4 = (tid & 7) * 4;
            size_t idx = (size_t)(m0 + row) * H_ + hb + c4;
            size_t hidx = ((size_t)t * B_ + m0 + row) * H_ + hb + c4;
            *(float4*)&h1nf[idx] = *(const float4*)&h1of[idx];
            *(uint2*)((char*)&g_h1ph[nt2][idx]) = *(const uint2*)((const char*)&g_h1ph[ot][idx]);
            *(uint2*)((char*)&g_h1pl[nt2][idx]) = *(const uint2*)((const char*)&g_h1pl[ot][idx]);
            *(uint2*)((char*)&g_H1h[hidx]) = make_uint2(0u, 0u);
            *(uint2*)((char*)&g_H1l[hidx]) = make_uint2(0u, 0u);
        }
        grid_bar();
    }
}

// ---------------- host orchestration (graph-capturable: launches only) ----------------
extern "C" void kernel_launch(void* const* d_in, const int* in_sizes, int n_in,
                              void* d_out, int out_size)
{
    const float* image_code = (const float*)d_in[0];
    const int*   captions   = (const int*)  d_in[1];
    const int*   cap_lens   = (const int*)  d_in[2];
    const float* embed_w    = (const float*)d_in[3];
    const float* init_w     = (const float*)d_in[4];
    const float* init_b     = (const float*)d_in[5];
    const float* w_ih0      = (const float*)d_in[6];
    const float* w_hh0      = (const float*)d_in[7];
    const float* b_ih0      = (const float*)d_in[8];
    const float* b_hh0      = (const float*)d_in[9];
    const float* w_ih1      = (const float*)d_in[10];
    const float* w_hh1      = (const float*)d_in[11];
    const float* b_ih1      = (const float*)d_in[12];
    const float* b_hh1      = (const float*)d_in[13];
    const float* fc_w       = (const float*)d_in[14];
    const float* fc_b       = (const float*)d_in[15];
    float* out = (float*)d_out;

    void* p;
    cudaGetSymbolAddress(&p, g_img);     float* dimg  = (float*)p;
    cudaGetSymbolAddress(&p, g_gi0c);    float* dgi0c = (float*)p;
    cudaGetSymbolAddress(&p, g_gi0);     float* dgi0  = (float*)p;
    cudaGetSymbolAddress(&p, g_h0f);     float* dh0a  = (float*)p;            // [0] = buffer 0
    cudaGetSymbolAddress(&p, g_h1f);     float* dh1a  = (float*)p;
    cudaGetSymbolAddress(&p, g_rowidx);  int*   drow  = (int*)p;
    cudaGetSymbolAddress(&p, g_fcw_h);   __nv_bfloat16* dfcwh = (__nv_bfloat16*)p;
    cudaGetSymbolAddress(&p, g_fcw_l);   __nv_bfloat16* dfcwl = (__nv_bfloat16*)p;
    cudaGetSymbolAddress(&p, g_emb_h);   __nv_bfloat16* dembh = (__nv_bfloat16*)p;
    cudaGetSymbolAddress(&p, g_emb_l);   __nv_bfloat16* dembl = (__nv_bfloat16*)p;
    cudaGetSymbolAddress(&p, g_wih0e_h); __nv_bfloat16* dw0h  = (__nv_bfloat16*)p;
    cudaGetSymbolAddress(&p, g_wih0e_l); __nv_bfloat16* dw0l  = (__nv_bfloat16*)p;
    cudaGetSymbolAddress(&p, g_whh0_h);  __nv_bfloat16* dwh0h = (__nv_bfloat16*)p;
    cudaGetSymbolAddress(&p, g_whh0_l);  __nv_bfloat16* dwh0l = (__nv_bfloat16*)p;
    cudaGetSymbolAddress(&p, g_wih1_h);  __nv_bfloat16* dwi1h = (__nv_bfloat16*)p;
    cudaGetSymbolAddress(&p, g_wih1_l);  __nv_bfloat16* dwi1l = (__nv_bfloat16*)p;
    cudaGetSymbolAddress(&p, g_whh1_h);  __nv_bfloat16* dwh1h = (__nv_bfloat16*)p;
    cudaGetSymbolAddress(&p, g_whh1_l);  __nv_bfloat16* dwh1l = (__nv_bfloat16*)p;
    cudaGetSymbolAddress(&p, g_H1h);     __nv_bfloat16* dH1h  = (__nv_bfloat16*)p;
    cudaGetSymbolAddress(&p, g_H1l);     __nv_bfloat16* dH1l  = (__nv_bfloat16*)p;
    cudaGetSymbolAddress(&p, g_h0ph);    __nv_bfloat16* dh0ph0 = (__nv_bfloat16*)p;
    cudaGetSymbolAddress(&p, g_h0pl);    __nv_bfloat16* dh0pl0 = (__nv_bfloat16*)p;
    cudaGetSymbolAddress(&p, g_h1ph);    __nv_bfloat16* dh1ph0 = (__nv_bfloat16*)p;
    cudaGetSymbolAddress(&p, g_h1pl);    __nv_bfloat16* dh1pl0 = (__nv_bfloat16*)p;

    cudaFuncSetAttribute(mmagemm_kernel,
                         cudaFuncAttributeMaxDynamicSharedMemorySize, MMA_SMEM_BYTES);
    cudaFuncSetAttribute(gru_persistent,
                         cudaFuncAttributeMaxDynamicSharedMemorySize, PS_SMEM);

    // 0. weight preconversion to bf16 hi/lo planes
    const int NW = V_ * H_;
    const int NG = G3 * H_;
    convw_kernel<<<(NW + 255) / 256, 256>>>(fc_w,    H_, 0,   dfcwh, dfcwl, NW);
    convw_kernel<<<(NW + 255) / 256, 256>>>(embed_w, H_, 0,   dembh, dembl, NW);
    convw_kernel<<<(NG + 255) / 256, 256>>>(w_ih0, IC_ + WD_, IC_, dw0h, dw0l, NG);
    convw_kernel<<<(NG + 255) / 256, 256>>>(w_hh0,   H_, 0,   dwh0h, dwh0l, NG);
    convw_kernel<<<(NG + 255) / 256, 256>>>(w_ih1,   H_, 0,   dwi1h, dwi1l, NG);
    convw_kernel<<<(NG + 255) / 256, 256>>>(w_hh1,   H_, 0,   dwh1h, dwh1l, NG);

    // 1. sort + metadata + aux outputs
    sort_kernel<<<1, 256>>>(cap_lens, captions, out, (long long)out_size);
    // 2. gather sorted image codes
    gather_img_kernel<<<(B_ * IC_) / 256, 256>>>(image_code);
    // 3. h0/h1 init in ONE GEMM: (256, 1024, K=2048) -> g_h0f[0], g_h1f[0]
    gemm64_kernel<<<dim3(16, 4), 256>>>(dimg, IC_, init_w, IC_, init_b,
                                        dh0a, H_, dh1a, IC_);
    // 3b. convert initial hidden to bf16 planes (buffer 0)
    convw_kernel<<<(B_ * H_ + 255) / 256, 256>>>(dh0a, H_, 0, dh0ph0, dh0pl0, B_ * H_);
    convw_kernel<<<(B_ * H_ + 255) / 256, 256>>>(dh1a, H_, 0, dh1ph0, dh1pl0, B_ * H_);
    // 4. time-invariant img part of layer0 input gates (+ b_ih0): (256, 1536, K=2048)
    gemm64_kernel<<<dim3(24, 4), 256>>>(dimg, IC_, w_ih0, IC_ + WD_, b_ih0,
                                        dgi0c, G3, nullptr, IC_);
    // 5. embedding-side layer0 input gates for ALL 12800 tokens (+ gi0c broadcast)
    mmagemm_kernel<<<dim3(6, 100), 256, MMA_SMEM_BYTES>>>(
        dembh, dembl, drow, dw0h, dw0l, dgi0c, dgi0, G3, 0);
    // 6. persistent recurrence: all 50 steps, both layers, one kernel
    gru_persistent<<<NBLK, 256, PS_SMEM>>>(b_hh0, b_ih1, b_hh1);
    // 7. FC head on tensor cores: all (t,b) rows, masked + scattered to (B, T, V)
    mmagemm_kernel<<<dim3(40, 100), 256, MMA_SMEM_BYTES>>>(
        dH1h, dH1l, nullptr, dfcwh, dfcwl, fc_b, out, V_, 1);
}

// round 8
// speedup vs baseline: 2.6246x; 1.0430x over previous
#include <cuda_runtime.h>
#include <cuda_bf16.h>
#include <stdint.h>
#include <cstdint>
#include <math.h>

// Problem constants
#define B_    256
#define TCAP  51
#define T_    50
#define V_    10000
#define WD_   512
#define H_    512
#define IC_   2048
#define G3    1536    // 3*H
#define NBLK  128     // persistent recurrence blocks
#define GRPSZ 16      // blocks per batch-tile group

// ---------------- static device scratch ----------------
__device__ float g_img [B_ * IC_];
__device__ float g_gi0c[B_ * G3];
__device__ float g_gi0 [(size_t)T_ * B_ * G3];   // precomputed layer0 input gates
__device__ float g_h0f [2][B_ * H_];             // fp32 hidden ping-pong
__device__ float g_h1f [2][B_ * H_];
__device__ int   g_order [B_];
__device__ int   g_len   [B_];
__device__ int   g_nvalid[T_];
__device__ int   g_rowidx[T_ * B_];
__device__ unsigned int g_barG[8];               // per-group barrier counters

// bf16 hi/lo planes (preconverted weights, hidden states, H1)
__device__ __nv_bfloat16 g_fcw_h [(size_t)V_ * H_];
__device__ __nv_bfloat16 g_fcw_l [(size_t)V_ * H_];
__device__ __nv_bfloat16 g_emb_h [(size_t)V_ * H_];
__device__ __nv_bfloat16 g_emb_l [(size_t)V_ * H_];
__device__ __nv_bfloat16 g_wih0e_h[G3 * H_];
__device__ __nv_bfloat16 g_wih0e_l[G3 * H_];
__device__ __nv_bfloat16 g_whh0_h [G3 * H_];
__device__ __nv_bfloat16 g_whh0_l [G3 * H_];
__device__ __nv_bfloat16 g_wih1_h [G3 * H_];
__device__ __nv_bfloat16 g_wih1_l [G3 * H_];
__device__ __nv_bfloat16 g_whh1_h [G3 * H_];
__device__ __nv_bfloat16 g_whh1_l [G3 * H_];
__device__ __nv_bfloat16 g_h0ph[2][B_ * H_];
__device__ __nv_bfloat16 g_h0pl[2][B_ * H_];
__device__ __nv_bfloat16 g_h1ph[2][B_ * H_];
__device__ __nv_bfloat16 g_h1pl[2][B_ * H_];
__device__ __nv_bfloat16 g_H1h [(size_t)T_ * B_ * H_];
__device__ __nv_bfloat16 g_H1l [(size_t)T_ * B_ * H_];

__device__ __forceinline__ float sigf(float x) { return 1.f / (1.f + expf(-x)); }

// ---------------- weight preconversion: fp32 -> bf16 hi + bf16 lo ----------------
__global__ void convw_kernel(const float* __restrict__ src, int ld, int col0,
                             __nv_bfloat16* __restrict__ dh,
                             __nv_bfloat16* __restrict__ dl, int n)
{
    int i = blockIdx.x * 256 + threadIdx.x;
    if (i >= n) return;
    int row = i >> 9;        // 512 cols always
    int col = i & 511;
    float x = src[(size_t)row * ld + col0 + col];
    __nv_bfloat16 h = __float2bfloat16_rn(x);
    dh[i] = h;
    dl[i] = __float2bfloat16_rn(x - __bfloat162float(h));
}

// ---------------- sort + metadata (stable descending by cap_len) ----------------
__global__ void sort_kernel(const int* __restrict__ cap_lens,
                            const int* __restrict__ captions,
                            float* __restrict__ out, long long out_size)
{
    __shared__ int lens[B_];
    __shared__ int ord [B_];
    int i = threadIdx.x;
    if (i < 8) g_barG[i] = 0u;            // reset per-group barriers every replay
    lens[i] = cap_lens[i];
    __syncthreads();
    int li = lens[i];
    int rank = 0;
    #pragma unroll 8
    for (int j = 0; j < B_; j++) {
        int lj = lens[j];
        rank += (lj > li) || (lj == li && j < i);
    }
    ord[rank] = i;
    __syncthreads();
    int src = ord[i];
    int len = lens[src] - 1;
    g_order[i] = src;
    g_len[i]   = len;
    if (i < T_) {
        int c = 0;
        #pragma unroll 8
        for (int b = 0; b < B_; b++) c += (lens[ord[b]] - 1) > i;
        g_nvalid[i] = c;
    }
    const long long PRED = (long long)B_ * T_ * V_;
    for (int t = 0; t < TCAP; t++) {
        int tok = captions[src * TCAP + t];
        if (t < T_) g_rowidx[t * B_ + i] = tok;
        if (out_size >= PRED + (long long)B_ * TCAP)
            out[PRED + (long long)i * TCAP + t] = (float)tok;
    }
    if (out_size >= PRED + (long long)B_ * TCAP + 2LL * B_) {
        out[PRED + (long long)B_ * TCAP + i]      = (float)len;
        out[PRED + (long long)B_ * TCAP + B_ + i] = (float)src;
    }
}

__global__ void gather_img_kernel(const float* __restrict__ image_code)
{
    int idx = blockIdx.x * 256 + threadIdx.x;
    int b = idx >> 11, k = idx & 2047;
    g_img[idx] = image_code[g_order[b] * IC_ + k];
}

// ---------------- 64x64 tile SIMT GEMM for deep-K prologue (inits, gi0c) ----------------
__global__ void __launch_bounds__(256)
gemm64_kernel(const float* __restrict__ A, int lda,
              const float* __restrict__ Bw, int ldb,
              const float* __restrict__ bias,
              float* __restrict__ C, int ldc, float* __restrict__ Cb, int K)
{
    __shared__ float As[16][68];
    __shared__ float Bs[16][68];
    int m0 = blockIdx.y * 64, n0 = blockIdx.x * 64;
    int tid = threadIdx.x;
    int lr = tid >> 2, kq = (tid & 3) * 4;
    const float* Ap = A  + (size_t)(m0 + lr) * lda + kq;
    const float* Bp = Bw + (size_t)(n0 + lr) * ldb + kq;
    int tx = tid & 15, ty = tid >> 4;
    float acc[4][4] = {};
    for (int k0 = 0; k0 < K; k0 += 16) {
        float4 av = *(const float4*)(Ap + k0);
        float4 bv = *(const float4*)(Bp + k0);
        As[kq+0][lr]=av.x; As[kq+1][lr]=av.y; As[kq+2][lr]=av.z; As[kq+3][lr]=av.w;
        Bs[kq+0][lr]=bv.x; Bs[kq+1][lr]=bv.y; Bs[kq+2][lr]=bv.z; Bs[kq+3][lr]=bv.w;
        __syncthreads();
        #pragma unroll
        for (int k = 0; k < 16; k++) {
            float4 a = *(const float4*)&As[k][ty*4];
            float4 b = *(const float4*)&Bs[k][tx*4];
            acc[0][0]+=a.x*b.x; acc[0][1]+=a.x*b.y; acc[0][2]+=a.x*b.z; acc[0][3]+=a.x*b.w;
            acc[1][0]+=a.y*b.x; acc[1][1]+=a.y*b.y; acc[1][2]+=a.y*b.z; acc[1][3]+=a.y*b.w;
            acc[2][0]+=a.z*b.x; acc[2][1]+=a.z*b.y; acc[2][2]+=a.z*b.z; acc[2][3]+=a.z*b.w;
            acc[3][0]+=a.w*b.x; acc[3][1]+=a.w*b.y; acc[3][2]+=a.w*b.z; acc[3][3]+=a.w*b.w;
        }
        __syncthreads();
    }
    #pragma unroll
    for (int i = 0; i < 4; i++) {
        int m = m0 + ty * 4 + i;
        #pragma unroll
        for (int j = 0; j < 4; j++) {
            int n = n0 + tx * 4 + j;
            float v = acc[i][j] + (bias ? bias[n] : 0.f);
            if (Cb) {
                if (n < H_) C [(size_t)m * H_ + n]       = v;
                else        Cb[(size_t)m * H_ + (n-H_)]  = v;
            } else {
                C[(size_t)m * ldc + n] = v;
            }
        }
    }
}

// ---------------- tensor-core bf16-3term GEMM machinery ----------------
__device__ __forceinline__ unsigned int s2u(const void* p) {
    return (unsigned int)__cvta_generic_to_shared(p);
}
__device__ __forceinline__ void ldsm_x4(unsigned int* r, unsigned int addr) {
    asm volatile("ldmatrix.sync.aligned.m8n8.x4.shared.b16 {%0,%1,%2,%3},[%4];"
        : "=r"(r[0]), "=r"(r[1]), "=r"(r[2]), "=r"(r[3]) : "r"(addr));
}
__device__ __forceinline__ void ldsm_x2(unsigned int& r0, unsigned int& r1, unsigned int addr) {
    asm volatile("ldmatrix.sync.aligned.m8n8.x2.shared.b16 {%0,%1},[%2];"
        : "=r"(r0), "=r"(r1) : "r"(addr));
}
__device__ __forceinline__ void mma16816(float* d, const unsigned int* a,
                                         unsigned int b0, unsigned int b1) {
    asm volatile("mma.sync.aligned.m16n8k16.row.col.f32.bf16.bf16.f32 "
        "{%0,%1,%2,%3},{%4,%5,%6,%7},{%8,%9},{%0,%1,%2,%3};"
        : "+f"(d[0]), "+f"(d[1]), "+f"(d[2]), "+f"(d[3])
        : "r"(a[0]), "r"(a[1]), "r"(a[2]), "r"(a[3]), "r"(b0), "r"(b1));
}
__device__ __forceinline__ void cpasync16(unsigned int dst, const void* src) {
    asm volatile("cp.async.cg.shared.global [%0], [%1], 16;"
        :: "r"(dst), "l"(src) : "memory");
}
__device__ __forceinline__ void cp_commit() {
    asm volatile("cp.async.commit_group;" ::: "memory");
}
__device__ __forceinline__ void cp_wait2() {
    asm volatile("cp.async.wait_group 2;" ::: "memory");
}

// ---------------- big parallel mma GEMM (gi0 + FC), proven ----------------
#define MMA_SMEM_BYTES 73728

__global__ void __launch_bounds__(256)
mmagemm_kernel(const __nv_bfloat16* __restrict__ Ah, const __nv_bfloat16* __restrict__ Al,
               const int* __restrict__ rowidx,
               const __nv_bfloat16* __restrict__ Bh, const __nv_bfloat16* __restrict__ Bl,
               const float* __restrict__ aux,
               float* __restrict__ out, int Nmax, int modeFC)
{
    extern __shared__ unsigned char smem[];
    const int tid = threadIdx.x;
    const int m0 = blockIdx.y * 128;
    const int n0 = blockIdx.x * 256;
    const int t  = m0 >> 8;
    const int bbase = m0 & 255;

    if (modeFC != 0) {
        if (t >= g_len[bbase]) {
            float4 z = make_float4(0.f, 0.f, 0.f, 0.f);
            for (int idx = tid * 4; idx < 128 * 256; idx += 1024) {
                int rr = idx >> 8;
                int cc = idx & 255;
                int gn = n0 + cc;
                if (gn < Nmax) {
                    int b = bbase + rr;
                    *(float4*)&out[((size_t)b * T_ + t) * V_ + gn] = z;
                }
            }
            return;
        }
    }

    const int lane = tid & 31;
    const int w = tid >> 5;
    const int warp_m = w & 1;
    const int warp_n = w >> 1;

    const int row2 = tid >> 1;
    const int seg = tid & 1;
    int am = m0 + row2;
    int arow = rowidx ? rowidx[am] : am;
    const char* Agh = (const char*)Ah + ((size_t)arow * H_) * 2 + seg * 16;
    const char* Agl = (const char*)Al + ((size_t)arow * H_) * 2 + seg * 16;
    int nrow = n0 + tid;
    if (nrow > Nmax - 1) nrow = Nmax - 1;
    const char* Bgh = (const char*)Bh + ((size_t)nrow * H_) * 2;
    const char* Bgl = (const char*)Bl + ((size_t)nrow * H_) * 2;

    const int lr8 = lane & 7;
    const int lsel = lane >> 3;
    const unsigned int a_off = (unsigned int)((lr8 + ((lsel & 1) << 3)) * 48 + (lsel >> 1) * 16);
    const unsigned int b_off = (unsigned int)(lr8 * 48 + (((lane >> 3) & 1) ? 16 : 0));
    const unsigned int sbase = s2u(smem);

    float acc[4][8][4];
    #pragma unroll
    for (int i = 0; i < 4; i++)
        #pragma unroll
        for (int j = 0; j < 8; j++)
            #pragma unroll
            for (int q = 0; q < 4; q++) acc[i][j][q] = 0.f;

    uint4 pah, pal, pbh0, pbh1, pbl0, pbl1;
    pah  = *(const uint4*)(Agh);
    pal  = *(const uint4*)(Agl);
    pbh0 = *(const uint4*)(Bgh);
    pbh1 = *(const uint4*)(Bgh + 16);
    pbl0 = *(const uint4*)(Bgl);
    pbl1 = *(const uint4*)(Bgl + 16);
    {
        unsigned int aoff = (unsigned int)row2 * 48u + (unsigned int)seg * 16u;
        *(uint4*)(smem + aoff)           = pah;
        *(uint4*)(smem + aoff + 12288u)  = pal;
        unsigned int boff = 24576u + (unsigned int)tid * 48u;
        *(uint4*)(smem + boff)                 = pbh0;
        *(uint4*)(smem + boff + 16u)           = pbh1;
        *(uint4*)(smem + boff + 24576u)        = pbl0;
        *(uint4*)(smem + boff + 24576u + 16u)  = pbl1;
    }
    __syncthreads();

    int buf = 0;
    for (int it = 0; it < 32; it++) {
        if (it < 31) {
            int koff = (it + 1) * 32;
            pah  = *(const uint4*)(Agh + koff);
            pal  = *(const uint4*)(Agl + koff);
            pbh0 = *(const uint4*)(Bgh + koff);
            pbh1 = *(const uint4*)(Bgh + koff + 16);
            pbl0 = *(const uint4*)(Bgl + koff);
            pbl1 = *(const uint4*)(Bgl + koff + 16);
        }

        unsigned int Ahf[4][4], Alf[4][4];
        #pragma unroll
        for (int i = 0; i < 4; i++) {
            unsigned int abase = sbase + (unsigned int)buf * 6144u
                               + (unsigned int)((warp_m * 4 + i) * 768) + a_off;
            ldsm_x4(Ahf[i], abase);
            ldsm_x4(Alf[i], abase + 12288u);
        }
        #pragma unroll
        for (int nt = 0; nt < 8; nt++) {
            unsigned int baddr = sbase + 24576u + (unsigned int)buf * 12288u
                               + (unsigned int)((warp_n * 8 + nt) * 384) + b_off;
            unsigned int bh0, bh1, bl0, bl1;
            ldsm_x2(bh0, bh1, baddr);
            ldsm_x2(bl0, bl1, baddr + 24576u);
            #pragma unroll
            for (int i = 0; i < 4; i++) {
                mma16816(acc[i][nt], Ahf[i], bh0, bh1);
                mma16816(acc[i][nt], Ahf[i], bl0, bl1);
                mma16816(acc[i][nt], Alf[i], bh0, bh1);
            }
        }

        if (it < 31) {
            int nb = buf ^ 1;
            unsigned int aoff = (unsigned int)nb * 6144u
                              + (unsigned int)row2 * 48u + (unsigned int)seg * 16u;
            *(uint4*)(smem + aoff)           = pah;
            *(uint4*)(smem + aoff + 12288u)  = pal;
            unsigned int boff = 24576u + (unsigned int)nb * 12288u + (unsigned int)tid * 48u;
            *(uint4*)(smem + boff)                 = pbh0;
            *(uint4*)(smem + boff + 16u)           = pbh1;
            *(uint4*)(smem + boff + 24576u)        = pbl0;
            *(uint4*)(smem + boff + 24576u + 16u)  = pbl1;
        }
        __syncthreads();
        buf ^= 1;
    }

    const int r  = lane >> 2;
    const int c2 = (lane & 3) * 2;
    #pragma unroll
    for (int i = 0; i < 4; i++) {
        int gm = m0 + (warp_m * 4 + i) * 16 + r;
        if (modeFC != 0) {
            int b1r = gm & 255;
            int b2r = b1r + 8;
            bool v1 = t < g_len[b1r];
            bool v2 = t < g_len[b2r];
            #pragma unroll
            for (int nt = 0; nt < 8; nt++) {
                int gn = n0 + (warp_n * 8 + nt) * 8 + c2;
                if (gn < Nmax) {
                    float bi0 = aux[gn];
                    float bi1 = aux[gn + 1];
                    float* d = acc[i][nt];
                    *(float2*)&out[((size_t)b1r * T_ + t) * V_ + gn] =
                        make_float2(v1 ? d[0] + bi0 : 0.f, v1 ? d[1] + bi1 : 0.f);
                    *(float2*)&out[((size_t)b2r * T_ + t) * V_ + gn] =
                        make_float2(v2 ? d[2] + bi0 : 0.f, v2 ? d[3] + bi1 : 0.f);
                }
            }
        } else {
            int br1 = gm & 255;
            int br2 = (gm + 8) & 255;
            #pragma unroll
            for (int nt = 0; nt < 8; nt++) {
                int gn = n0 + (warp_n * 8 + nt) * 8 + c2;
                if (gn < Nmax) {
                    float2 c1 = *(const float2*)&aux[(size_t)br1 * G3 + gn];
                    float2 cc2 = *(const float2*)&aux[(size_t)br2 * G3 + gn];
                    float* d = acc[i][nt];
                    *(float2*)&out[(size_t)gm * G3 + gn] =
                        make_float2(d[0] + c1.x, d[1] + c1.y);
                    *(float2*)&out[(size_t)(gm + 8) * G3 + gn] =
                        make_float2(d[2] + cc2.x, d[3] + cc2.y);
                }
            }
        }
    }
}

// ================= persistent tensor-core GRU recurrence =================
// 128 blocks x 256 threads. Per block: 32 batch x 32 h-cols. 8 groups of 16
// blocks share a batch tile; barriers are group-local. Groups exit at t_act.
#define PS_SMEM   74752
#define STAGE_SZ  12288

__device__ __forceinline__ void group_bar(int g, unsigned int target)
{
    __syncthreads();
    if (threadIdx.x == 0) {
        asm volatile("red.release.gpu.global.add.u32 [%0], %1;"
                     :: "l"(&g_barG[g]), "r"(1u) : "memory");
        unsigned int v;
        while (true) {
            asm volatile("ld.acquire.gpu.global.u32 %0, [%1];"
                         : "=r"(v) : "l"(&g_barG[g]));
            if (v >= target) break;
            __nanosleep(64);
        }
    }
    __syncthreads();
}

// chunk idx in [0,512): A chunks [0,128), B chunks [128,512)
__device__ __forceinline__ void ps_issue_chunk(int idx, int slab, int st,
    const __nv_bfloat16* __restrict__ Aph, const __nv_bfloat16* __restrict__ Apl, int m0,
    const __nv_bfloat16* __restrict__ Wh, const __nv_bfloat16* __restrict__ Wl, int hb,
    unsigned int sbase)
{
    if (idx < 128) {
        int plane = idx >> 6, r2 = idx & 63, row = r2 >> 1, half = r2 & 1;
        const __nv_bfloat16* P = plane ? Apl : Aph;
        const char* src = (const char*)P + ((size_t)(m0 + row) * H_ + slab * 16 + half * 8) * 2;
        unsigned int dst = sbase + (unsigned int)st * STAGE_SZ + (unsigned int)plane * 1536u
                         + (unsigned int)row * 48u + (unsigned int)half * 16u;
        cpasync16(dst, src);
    } else {
        int j = idx - 128;
        int plane = j / 192, r2 = j % 192, row = r2 >> 1, half = r2 & 1;
        int wrow = (row >> 5) * H_ + hb + (row & 31);
        const __nv_bfloat16* P = plane ? Wl : Wh;
        const char* src = (const char*)P + ((size_t)wrow * H_ + slab * 16 + half * 8) * 2;
        unsigned int dst = sbase + (unsigned int)st * STAGE_SZ + 3072u
                         + (unsigned int)plane * 4608u
                         + (unsigned int)row * 48u + (unsigned int)half * 16u;
        cpasync16(dst, src);
    }
}

__device__ __forceinline__ void ps_segment(unsigned int sbase, int tid,
    int warp_m, int warp_n, unsigned int a_off, unsigned int b_off,
    const __nv_bfloat16* __restrict__ Aph, const __nv_bfloat16* __restrict__ Apl, int m0,
    const __nv_bfloat16* __restrict__ Wh, const __nv_bfloat16* __restrict__ Wl, int hb,
    float acc[3][4])
{
    #pragma unroll
    for (int s = 0; s < 3; s++) {
        ps_issue_chunk(tid,       s, s, Aph, Apl, m0, Wh, Wl, hb, sbase);
        ps_issue_chunk(tid + 256, s, s, Aph, Apl, m0, Wh, Wl, hb, sbase);
        cp_commit();
    }
    for (int it = 0; it < 32; it++) {
        cp_wait2();
        __syncthreads();
        int st = it & 3;
        {
            unsigned int Ahf[4], Alf[4];
            unsigned int abase = sbase + (unsigned int)st * STAGE_SZ
                               + (unsigned int)(warp_m * 16) * 48u + a_off;
            ldsm_x4(Ahf, abase);
            ldsm_x4(Alf, abase + 1536u);
            #pragma unroll
            for (int nt = 0; nt < 3; nt++) {
                unsigned int bb = sbase + (unsigned int)st * STAGE_SZ + 3072u
                                + (unsigned int)((warp_n * 24 + nt * 8) * 48) + b_off;
                unsigned int bh0, bh1, bl0, bl1;
                ldsm_x2(bh0, bh1, bb);
                ldsm_x2(bl0, bl1, bb + 4608u);
                mma16816(acc[nt], Ahf, bh0, bh1);
                mma16816(acc[nt], Ahf, bl0, bl1);
                mma16816(acc[nt], Alf, bh0, bh1);
            }
        }
        if (it + 3 < 32) {
            int ns = (it + 3) & 3;
            ps_issue_chunk(tid,       it + 3, ns, Aph, Apl, m0, Wh, Wl, hb, sbase);
            ps_issue_chunk(tid + 256, it + 3, ns, Aph, Apl, m0, Wh, Wl, hb, sbase);
        }
        cp_commit();
    }
    __syncthreads();
}

__device__ __forceinline__ void ps_dump(unsigned char* smem, int csoff,
    int warp_m, int warp_n, int lane, float acc[3][4])
{
    float* Cs = (float*)(smem + csoff);
    int lr = lane >> 2, lc = (lane & 3) * 2;
    #pragma unroll
    for (int nt = 0; nt < 3; nt++) {
        int rowt = warp_m * 16 + lr;
        int col = warp_n * 24 + nt * 8 + lc;
        Cs[rowt * 100 + col]           = acc[nt][0];
        Cs[rowt * 100 + col + 1]       = acc[nt][1];
        Cs[(rowt + 8) * 100 + col]     = acc[nt][2];
        Cs[(rowt + 8) * 100 + col + 1] = acc[nt][3];
    }
}

__global__ void __launch_bounds__(256)
gru_persistent(const float* __restrict__ b_hh0,
               const float* __restrict__ b_ih1, const float* __restrict__ b_hh1)
{
    extern __shared__ unsigned char smem[];
    const int bx = blockIdx.x;
    const int hb = (bx & 15) * 32;
    const int m0 = (bx >> 4) * 32;
    const int grp = bx >> 4;
    const int tid = threadIdx.x;
    const int lane = tid & 31;
    const int wrp = tid >> 5;
    const int warp_m = wrp >> 2;
    const int warp_n = wrp & 3;
    const int lr8 = lane & 7;
    const int lsel = lane >> 3;
    const unsigned int a_off = (unsigned int)((lr8 + ((lsel & 1) << 3)) * 48 + (lsel >> 1) * 16);
    const unsigned int b_off = (unsigned int)(lr8 * 48 + (((lane >> 3) & 1) ? 16 : 0));
    const unsigned int sbase = s2u(smem);

    // steps this group is active for (g_nvalid is non-increasing)
    int t_act = 0;
    while (t_act < T_ && m0 < g_nvalid[t_act]) t_act++;

    unsigned int nbar = 0;
    for (int t = 0; t < t_act; t++) {
        const int ot = t & 1, nt2 = ot ^ 1;
        const float* h0of = g_h0f[ot];
        float*       h0nf = g_h0f[nt2];
        const float* h1of = g_h1f[ot];
        float*       h1nf = g_h1f[nt2];

        // ---------------- phase A: h0_new = GRU0(gi0[t], h0_old) ----------------
        {
            float acc[3][4];
            #pragma unroll
            for (int i = 0; i < 3; i++)
                #pragma unroll
                for (int q = 0; q < 4; q++) acc[i][q] = 0.f;
            ps_segment(sbase, tid, warp_m, warp_n, a_off, b_off,
                       g_h0ph[ot], g_h0pl[ot], m0, g_whh0_h, g_whh0_l, hb, acc);
            ps_dump(smem, 49152, warp_m, warp_n, lane, acc);
            __syncthreads();
            const float* Cs = (const float*)(smem + 49152);
            #pragma unroll
            for (int q = 0; q < 4; q++) {
                int i = tid + q * 256;
                int m = i >> 5, hl = i & 31;
                int b = m0 + m;
                int h = hb + hl;
                size_t idx = (size_t)b * H_ + h;
                float old = h0of[idx];
                float v;
                if (t < g_len[b]) {
                    const float* gi = g_gi0 + ((size_t)t * B_ + b) * G3;
                    float r = sigf(gi[h]        + Cs[m * 100 + hl]      + b_hh0[h]);
                    float z = sigf(gi[512 + h]  + Cs[m * 100 + 32 + hl] + b_hh0[512 + h]);
                    float n = tanhf(gi[1024 + h] + r * (Cs[m * 100 + 64 + hl] + b_hh0[1024 + h]));
                    v = (1.f - z) * n + z * old;
                } else v = old;
                h0nf[idx] = v;
                __nv_bfloat16 vh = __float2bfloat16_rn(v);
                g_h0ph[nt2][idx] = vh;
                g_h0pl[nt2][idx] = __float2bfloat16_rn(v - __bfloat162float(vh));
            }
        }
        nbar++;
        group_bar(grp, nbar * GRPSZ);

        // ---------------- phase B: h1_new = GRU1(h0_new, h1_old) ----------------
        {
            float acc[3][4];
            #pragma unroll
            for (int i = 0; i < 3; i++)
                #pragma unroll
                for (int q = 0; q < 4; q++) acc[i][q] = 0.f;
            ps_segment(sbase, tid, warp_m, warp_n, a_off, b_off,
                       g_h0ph[nt2], g_h0pl[nt2], m0, g_wih1_h, g_wih1_l, hb, acc);
            ps_dump(smem, 49152, warp_m, warp_n, lane, acc);
            #pragma unroll
            for (int i = 0; i < 3; i++)
                #pragma unroll
                for (int q = 0; q < 4; q++) acc[i][q] = 0.f;
            ps_segment(sbase, tid, warp_m, warp_n, a_off, b_off,
                       g_h1ph[ot], g_h1pl[ot], m0, g_whh1_h, g_whh1_l, hb, acc);
            ps_dump(smem, 61952, warp_m, warp_n, lane, acc);
            __syncthreads();
            const float* Cs1 = (const float*)(smem + 49152);
            const float* Cs2 = (const float*)(smem + 61952);
            #pragma unroll
            for (int q = 0; q < 4; q++) {
                int i = tid + q * 256;
                int m = i >> 5, hl = i & 31;
                int b = m0 + m;
                int h = hb + hl;
                size_t idx = (size_t)b * H_ + h;
                size_t hidx = ((size_t)t * B_ + b) * H_ + h;
                float old = h1of[idx];
                if (t < g_len[b]) {
                    float r = sigf(Cs1[m * 100 + hl]      + b_ih1[h]
                                 + Cs2[m * 100 + hl]      + b_hh1[h]);
                    float z = sigf(Cs1[m * 100 + 32 + hl] + b_ih1[512 + h]
                                 + Cs2[m * 100 + 32 + hl] + b_hh1[512 + h]);
                    float n = tanhf(Cs1[m * 100 + 64 + hl] + b_ih1[1024 + h]
                                  + r * (Cs2[m * 100 + 64 + hl] + b_hh1[1024 + h]));
                    float v = (1.f - z) * n + z * old;
                    h1nf[idx] = v;
                    __nv_bfloat16 vh = __float2bfloat16_rn(v);
                    __nv_bfloat16 vl = __float2bfloat16_rn(v - __bfloat162float(vh));
                    g_h1ph[nt2][idx] = vh;
                    g_h1pl[nt2][idx] = vl;
                    g_H1h[hidx] = vh;
                    g_H1l[hidx] = vl;
                } else {
                    h1nf[idx] = old;
                    g_h1ph[nt2][idx] = g_h1ph[ot][idx];
                    g_h1pl[nt2][idx] = g_h1pl[ot][idx];
                    g_H1h[hidx] = __float2bfloat16_rn(0.f);
                    g_H1l[hidx] = __float2bfloat16_rn(0.f);
                }
            }
        }
        nbar++;
        group_bar(grp, nbar * GRPSZ);
    }
    // t >= t_act: whole batch tile masked forever; its H1 values are never
    // consumed by the FC kernel (zero-fill / per-row masks) -> just exit.
}

// ---------------- host orchestration (graph-capturable: launches only) ----------------
extern "C" void kernel_launch(void* const* d_in, const int* in_sizes, int n_in,
                              void* d_out, int out_size)
{
    const float* image_code = (const float*)d_in[0];
    const int*   captions   = (const int*)  d_in[1];
    const int*   cap_lens   = (const int*)  d_in[2];
    const float* embed_w    = (const float*)d_in[3];
    const float* init_w     = (const float*)d_in[4];
    const float* init_b     = (const float*)d_in[5];
    const float* w_ih0      = (const float*)d_in[6];
    const float* w_hh0      = (const float*)d_in[7];
    const float* b_ih0      = (const float*)d_in[8];
    const float* b_hh0      = (const float*)d_in[9];
    const float* w_ih1      = (const float*)d_in[10];
    const float* w_hh1      = (const float*)d_in[11];
    const float* b_ih1      = (const float*)d_in[12];
    const float* b_hh1      = (const float*)d_in[13];
    const float* fc_w       = (const float*)d_in[14];
    const float* fc_b       = (const float*)d_in[15];
    float* out = (float*)d_out;

    void* p;
    cudaGetSymbolAddress(&p, g_img);     float* dimg  = (float*)p;
    cudaGetSymbolAddress(&p, g_gi0c);    float* dgi0c = (float*)p;
    cudaGetSymbolAddress(&p, g_gi0);     float* dgi0  = (float*)p;
    cudaGetSymbolAddress(&p, g_h0f);     float* dh0a  = (float*)p;
    cudaGetSymbolAddress(&p, g_h1f);     float* dh1a  = (float*)p;
    cudaGetSymbolAddress(&p, g_rowidx);  int*   drow  = (int*)p;
    cudaGetSymbolAddress(&p, g_fcw_h);   __nv_bfloat16* dfcwh = (__nv_bfloat16*)p;
    cudaGetSymbolAddress(&p, g_fcw_l);   __nv_bfloat16* dfcwl = (__nv_bfloat16*)p;
    cudaGetSymbolAddress(&p, g_emb_h);   __nv_bfloat16* dembh = (__nv_bfloat16*)p;
    cudaGetSymbolAddress(&p, g_emb_l);   __nv_bfloat16* dembl = (__nv_bfloat16*)p;
    cudaGetSymbolAddress(&p, g_wih0e_h); __nv_bfloat16* dw0h  = (__nv_bfloat16*)p;
    cudaGetSymbolAddress(&p, g_wih0e_l); __nv_bfloat16* dw0l  = (__nv_bfloat16*)p;
    cudaGetSymbolAddress(&p, g_whh0_h);  __nv_bfloat16* dwh0h = (__nv_bfloat16*)p;
    cudaGetSymbolAddress(&p, g_whh0_l);  __nv_bfloat16* dwh0l = (__nv_bfloat16*)p;
    cudaGetSymbolAddress(&p, g_wih1_h);  __nv_bfloat16* dwi1h = (__nv_bfloat16*)p;
    cudaGetSymbolAddress(&p, g_wih1_l);  __nv_bfloat16* dwi1l = (__nv_bfloat16*)p;
    cudaGetSymbolAddress(&p, g_whh1_h);  __nv_bfloat16* dwh1h = (__nv_bfloat16*)p;
    cudaGetSymbolAddress(&p, g_whh1_l);  __nv_bfloat16* dwh1l = (__nv_bfloat16*)p;
    cudaGetSymbolAddress(&p, g_H1h);     __nv_bfloat16* dH1h  = (__nv_bfloat16*)p;
    cudaGetSymbolAddress(&p, g_H1l);     __nv_bfloat16* dH1l  = (__nv_bfloat16*)p;
    cudaGetSymbolAddress(&p, g_h0ph);    __nv_bfloat16* dh0ph0 = (__nv_bfloat16*)p;
    cudaGetSymbolAddress(&p, g_h0pl);    __nv_bfloat16* dh0pl0 = (__nv_bfloat16*)p;
    cudaGetSymbolAddress(&p, g_h1ph);    __nv_bfloat16* dh1ph0 = (__nv_bfloat16*)p;
    cudaGetSymbolAddress(&p, g_h1pl);    __nv_bfloat16* dh1pl0 = (__nv_bfloat16*)p;

    cudaFuncSetAttribute(mmagemm_kernel,
                         cudaFuncAttributeMaxDynamicSharedMemorySize, MMA_SMEM_BYTES);
    cudaFuncSetAttribute(gru_persistent,
                         cudaFuncAttributeMaxDynamicSharedMemorySize, PS_SMEM);

    // 0. weight preconversion to bf16 hi/lo planes
    const int NW = V_ * H_;
    const int NG = G3 * H_;
    convw_kernel<<<(NW + 255) / 256, 256>>>(fc_w,    H_, 0,   dfcwh, dfcwl, NW);
    convw_kernel<<<(NW + 255) / 256, 256>>>(embed_w, H_, 0,   dembh, dembl, NW);
    convw_kernel<<<(NG + 255) / 256, 256>>>(w_ih0, IC_ + WD_, IC_, dw0h, dw0l, NG);
    convw_kernel<<<(NG + 255) / 256, 256>>>(w_hh0,   H_, 0,   dwh0h, dwh0l, NG);
    convw_kernel<<<(NG + 255) / 256, 256>>>(w_ih1,   H_, 0,   dwi1h, dwi1l, NG);
    convw_kernel<<<(NG + 255) / 256, 256>>>(w_hh1,   H_, 0,   dwh1h, dwh1l, NG);

    // 1. sort + metadata + aux outputs (also resets group barriers)
    sort_kernel<<<1, 256>>>(cap_lens, captions, out, (long long)out_size);
    // 2. gather sorted image codes
    gather_img_kernel<<<(B_ * IC_) / 256, 256>>>(image_code);
    // 3. h0/h1 init in ONE GEMM: (256, 1024, K=2048) -> g_h0f[0], g_h1f[0]
    gemm64_kernel<<<dim3(16, 4), 256>>>(dimg, IC_, init_w, IC_, init_b,
                                        dh0a, H_, dh1a, IC_);
    // 3b. convert initial hidden to bf16 planes (buffer 0)
    convw_kernel<<<(B_ * H_ + 255) / 256, 256>>>(dh0a, H_, 0, dh0ph0, dh0pl0, B_ * H_);
    convw_kernel<<<(B_ * H_ + 255) / 256, 256>>>(dh1a, H_, 0, dh1ph0, dh1pl0, B_ * H_);
    // 4. time-invariant img part of layer0 input gates (+ b_ih0): (256, 1536, K=2048)
    gemm64_kernel<<<dim3(24, 4), 256>>>(dimg, IC_, w_ih0, IC_ + WD_, b_ih0,
                                        dgi0c, G3, nullptr, IC_);
    // 5. embedding-side layer0 input gates for ALL 12800 tokens (+ gi0c broadcast)
    mmagemm_kernel<<<dim3(6, 100), 256, MMA_SMEM_BYTES>>>(
        dembh, dembl, drow, dw0h, dw0l, dgi0c, dgi0, G3, 0);
    // 6. persistent recurrence: all 50 steps, both layers, one kernel,
    //    group-local barriers, early exit per group
    gru_persistent<<<NBLK, 256, PS_SMEM>>>(b_hh0, b_ih1, b_hh1);
    // 7. FC head on tensor cores: all (t,b) rows, masked + scattered to (B, T, V)
    mmagemm_kernel<<<dim3(40, 100), 256, MMA_SMEM_BYTES>>>(
        dH1h, dH1l, nullptr, dfcwh, dfcwl, fc_b, out, V_, 1);
}

// round 10
// speedup vs baseline: 2.8899x; 1.1011x over previous
#include <cuda_runtime.h>
#include <cuda_bf16.h>
#include <stdint.h>
#include <cstdint>
#include <math.h>

// Problem constants
#define B_    256
#define TCAP  51
#define T_    50
#define V_    10000
#define WD_   512
#define H_    512
#define IC_   2048
#define G3    1536    // 3*H
#define NBLK  128     // persistent recurrence blocks
#define GRPSZ 16      // blocks per batch-tile group

// ---------------- static device scratch ----------------
__device__ float g_img [B_ * IC_];
__device__ float g_gi0c[B_ * G3];
__device__ float g_gi0 [(size_t)T_ * B_ * G3];   // precomputed layer0 input gates
__device__ float g_h0f [2][B_ * H_];             // fp32 hidden ping-pong
__device__ float g_h1f [2][B_ * H_];
__device__ int   g_order [B_];
__device__ int   g_len   [B_];
__device__ int   g_nvalid[T_];
__device__ int   g_rowidx[T_ * B_];
__device__ unsigned int g_barG[8];               // per-group barrier counters

// bf16 hi/lo planes (flat) for the big GEMMs — 128B-aligned (uint4 / bulk reads)
__device__ __align__(128) __nv_bfloat16 g_fcw_h [(size_t)V_ * H_];
__device__ __align__(128) __nv_bfloat16 g_fcw_l [(size_t)V_ * H_];
__device__ __align__(128) __nv_bfloat16 g_emb_h [(size_t)V_ * H_];
__device__ __align__(128) __nv_bfloat16 g_emb_l [(size_t)V_ * H_];
__device__ __align__(128) __nv_bfloat16 g_wih0e_h[G3 * H_];
__device__ __align__(128) __nv_bfloat16 g_wih0e_l[G3 * H_];
__device__ __align__(128) __nv_bfloat16 g_H1h [(size_t)T_ * B_ * H_];
__device__ __align__(128) __nv_bfloat16 g_H1l [(size_t)T_ * B_ * H_];

// slabbed layouts for the persistent recurrence (contiguous per (block, k-slab))
// ALIGNMENT IS LOAD-BEARING: cp.async.bulk requires 16B-aligned global src.
// weight: [hblk 16][slab 32][plane 2][row 96][24 entries (48B: 32B data+16B pad)]
#define WSLAB_ENT 2304            // 96*24 per plane
__device__ __align__(128) __nv_bfloat16 g_whh0_s[16 * 32 * 2 * WSLAB_ENT];
__device__ __align__(128) __nv_bfloat16 g_wih1_s[16 * 32 * 2 * WSLAB_ENT];
__device__ __align__(128) __nv_bfloat16 g_whh1_s[16 * 32 * 2 * WSLAB_ENT];
// hidden: [mtile 8][slab 32][plane 2][row 32][24 entries]
#define HSLAB_ENT 768             // 32*24 per plane
__device__ __align__(128) __nv_bfloat16 g_h0s[2][8 * 32 * 2 * HSLAB_ENT];
__device__ __align__(128) __nv_bfloat16 g_h1s[2][8 * 32 * 2 * HSLAB_ENT];

__device__ __forceinline__ float sigf(float x) { return 1.f / (1.f + expf(-x)); }

// ---------------- flat weight preconversion: fp32 -> bf16 hi + bf16 lo ----------------
__global__ void convw_kernel(const float* __restrict__ src, int ld, int col0,
                             __nv_bfloat16* __restrict__ dh,
                             __nv_bfloat16* __restrict__ dl, int n)
{
    int i = blockIdx.x * 256 + threadIdx.x;
    if (i >= n) return;
    int row = i >> 9;
    int col = i & 511;
    float x = src[(size_t)row * ld + col0 + col];
    __nv_bfloat16 h = __float2bfloat16_rn(x);
    dh[i] = h;
    dl[i] = __float2bfloat16_rn(x - __bfloat162float(h));
}

// ---------------- slabbed weight conversion (recurrence weights) ----------------
__global__ void convw_slab_kernel(const float* __restrict__ src,
                                  __nv_bfloat16* __restrict__ dst)
{
    int i = blockIdx.x * 256 + threadIdx.x;      // 786432 total
    int e = i & 15;
    int row = (i >> 4) % 96;
    int tmp = (i >> 4) / 96;                     // 0..511
    int slab = tmp & 31;
    int hblk = tmp >> 5;
    int g = row >> 5, r = row & 31;
    float x = src[(size_t)(g * 512 + hblk * 32 + r) * 512 + slab * 16 + e];
    __nv_bfloat16 h = __float2bfloat16_rn(x);
    size_t base = (size_t)((hblk * 32 + slab) * 2) * WSLAB_ENT;
    dst[base + row * 24 + e] = h;
    dst[base + WSLAB_ENT + row * 24 + e] = __float2bfloat16_rn(x - __bfloat162float(h));
}

// ---------------- slabbed hidden conversion (initial h0/h1) ----------------
__global__ void convh_slab_kernel(const float* __restrict__ src,
                                  __nv_bfloat16* __restrict__ dst)
{
    int i = blockIdx.x * 256 + threadIdx.x;      // 131072 total
    int e = i & 15;
    int slab = (i >> 4) & 31;
    int row = (i >> 9) & 31;
    int mtile = i >> 14;
    float x = src[(size_t)(mtile * 32 + row) * 512 + slab * 16 + e];
    __nv_bfloat16 h = __float2bfloat16_rn(x);
    size_t base = (size_t)((mtile * 32 + slab) * 2) * HSLAB_ENT;
    dst[base + row * 24 + e] = h;
    dst[base + HSLAB_ENT + row * 24 + e] = __float2bfloat16_rn(x - __bfloat162float(h));
}

// ---------------- sort + metadata (stable descending by cap_len) ----------------
__global__ void sort_kernel(const int* __restrict__ cap_lens,
                            const int* __restrict__ captions,
                            float* __restrict__ out, long long out_size)
{
    __shared__ int lens[B_];
    __shared__ int ord [B_];
    int i = threadIdx.x;
    if (i < 8) g_barG[i] = 0u;
    lens[i] = cap_lens[i];
    __syncthreads();
    int li = lens[i];
    int rank = 0;
    #pragma unroll 8
    for (int j = 0; j < B_; j++) {
        int lj = lens[j];
        rank += (lj > li) || (lj == li && j < i);
    }
    ord[rank] = i;
    __syncthreads();
    int src = ord[i];
    int len = lens[src] - 1;
    g_order[i] = src;
    g_len[i]   = len;
    if (i < T_) {
        int c = 0;
        #pragma unroll 8
        for (int b = 0; b < B_; b++) c += (lens[ord[b]] - 1) > i;
        g_nvalid[i] = c;
    }
    const long long PRED = (long long)B_ * T_ * V_;
    for (int t = 0; t < TCAP; t++) {
        int tok = captions[src * TCAP + t];
        if (t < T_) g_rowidx[t * B_ + i] = tok;
        if (out_size >= PRED + (long long)B_ * TCAP)
            out[PRED + (long long)i * TCAP + t] = (float)tok;
    }
    if (out_size >= PRED + (long long)B_ * TCAP + 2LL * B_) {
        out[PRED + (long long)B_ * TCAP + i]      = (float)len;
        out[PRED + (long long)B_ * TCAP + B_ + i] = (float)src;
    }
}

__global__ void gather_img_kernel(const float* __restrict__ image_code)
{
    int idx = blockIdx.x * 256 + threadIdx.x;
    int b = idx >> 11, k = idx & 2047;
    g_img[idx] = image_code[g_order[b] * IC_ + k];
}

// ---------------- 64x64 tile SIMT GEMM for deep-K prologue (inits, gi0c) ----------------
__global__ void __launch_bounds__(256)
gemm64_kernel(const float* __restrict__ A, int lda,
              const float* __restrict__ Bw, int ldb,
              const float* __restrict__ bias,
              float* __restrict__ C, int ldc, float* __restrict__ Cb, int K)
{
    __shared__ float As[16][68];
    __shared__ float Bs[16][68];
    int m0 = blockIdx.y * 64, n0 = blockIdx.x * 64;
    int tid = threadIdx.x;
    int lr = tid >> 2, kq = (tid & 3) * 4;
    const float* Ap = A  + (size_t)(m0 + lr) * lda + kq;
    const float* Bp = Bw + (size_t)(n0 + lr) * ldb + kq;
    int tx = tid & 15, ty = tid >> 4;
    float acc[4][4] = {};
    for (int k0 = 0; k0 < K; k0 += 16) {
        float4 av = *(const float4*)(Ap + k0);
        float4 bv = *(const float4*)(Bp + k0);
        As[kq+0][lr]=av.x; As[kq+1][lr]=av.y; As[kq+2][lr]=av.z; As[kq+3][lr]=av.w;
        Bs[kq+0][lr]=bv.x; Bs[kq+1][lr]=bv.y; Bs[kq+2][lr]=bv.z; Bs[kq+3][lr]=bv.w;
        __syncthreads();
        #pragma unroll
        for (int k = 0; k < 16; k++) {
            float4 a = *(const float4*)&As[k][ty*4];
            float4 b = *(const float4*)&Bs[k][tx*4];
            acc[0][0]+=a.x*b.x; acc[0][1]+=a.x*b.y; acc[0][2]+=a.x*b.z; acc[0][3]+=a.x*b.w;
            acc[1][0]+=a.y*b.x; acc[1][1]+=a.y*b.y; acc[1][2]+=a.y*b.z; acc[1][3]+=a.y*b.w;
            acc[2][0]+=a.z*b.x; acc[2][1]+=a.z*b.y; acc[2][2]+=a.z*b.z; acc[2][3]+=a.z*b.w;
            acc[3][0]+=a.w*b.x; acc[3][1]+=a.w*b.y; acc[3][2]+=a.w*b.z; acc[3][3]+=a.w*b.w;
        }
        __syncthreads();
    }
    #pragma unroll
    for (int i = 0; i < 4; i++) {
        int m = m0 + ty * 4 + i;
        #pragma unroll
        for (int j = 0; j < 4; j++) {
            int n = n0 + tx * 4 + j;
            float v = acc[i][j] + (bias ? bias[n] : 0.f);
            if (Cb) {
                if (n < H_) C [(size_t)m * H_ + n]       = v;
                else        Cb[(size_t)m * H_ + (n-H_)]  = v;
            } else {
                C[(size_t)m * ldc + n] = v;
            }
        }
    }
}

// ---------------- tensor-core bf16-3term GEMM machinery ----------------
__device__ __forceinline__ unsigned int s2u(const void* p) {
    return (unsigned int)__cvta_generic_to_shared(p);
}
__device__ __forceinline__ void ldsm_x4(unsigned int* r, unsigned int addr) {
    asm volatile("ldmatrix.sync.aligned.m8n8.x4.shared.b16 {%0,%1,%2,%3},[%4];"
        : "=r"(r[0]), "=r"(r[1]), "=r"(r[2]), "=r"(r[3]) : "r"(addr));
}
__device__ __forceinline__ void ldsm_x2(unsigned int& r0, unsigned int& r1, unsigned int addr) {
    asm volatile("ldmatrix.sync.aligned.m8n8.x2.shared.b16 {%0,%1},[%2];"
        : "=r"(r0), "=r"(r1) : "r"(addr));
}
__device__ __forceinline__ void mma16816(float* d, const unsigned int* a,
                                         unsigned int b0, unsigned int b1) {
    asm volatile("mma.sync.aligned.m16n8k16.row.col.f32.bf16.bf16.f32 "
        "{%0,%1,%2,%3},{%4,%5,%6,%7},{%8,%9},{%0,%1,%2,%3};"
        : "+f"(d[0]), "+f"(d[1]), "+f"(d[2]), "+f"(d[3])
        : "r"(a[0]), "r"(a[1]), "r"(a[2]), "r"(a[3]), "r"(b0), "r"(b1));
}

// ---------------- big parallel mma GEMM (gi0 + FC), proven ----------------
#define MMA_SMEM_BYTES 73728

__global__ void __launch_bounds__(256)
mmagemm_kernel(const __nv_bfloat16* __restrict__ Ah, const __nv_bfloat16* __restrict__ Al,
               const int* __restrict__ rowidx,
               const __nv_bfloat16* __restrict__ Bh, const __nv_bfloat16* __restrict__ Bl,
               const float* __restrict__ aux,
               float* __restrict__ out, int Nmax, int modeFC)
{
    extern __shared__ unsigned char smem[];
    const int tid = threadIdx.x;
    const int m0 = blockIdx.y * 128;
    const int n0 = blockIdx.x * 256;
    const int t  = m0 >> 8;
    const int bbase = m0 & 255;

    if (modeFC != 0) {
        if (t >= g_len[bbase]) {
            float4 z = make_float4(0.f, 0.f, 0.f, 0.f);
            for (int idx = tid * 4; idx < 128 * 256; idx += 1024) {
                int rr = idx >> 8;
                int cc = idx & 255;
                int gn = n0 + cc;
                if (gn < Nmax) {
                    int b = bbase + rr;
                    *(float4*)&out[((size_t)b * T_ + t) * V_ + gn] = z;
                }
            }
            return;
        }
    }

    const int lane = tid & 31;
    const int w = tid >> 5;
    const int warp_m = w & 1;
    const int warp_n = w >> 1;

    const int row2 = tid >> 1;
    const int seg = tid & 1;
    int am = m0 + row2;
    int arow = rowidx ? rowidx[am] : am;
    const char* Agh = (const char*)Ah + ((size_t)arow * H_) * 2 + seg * 16;
    const char* Agl = (const char*)Al + ((size_t)arow * H_) * 2 + seg * 16;
    int nrow = n0 + tid;
    if (nrow > Nmax - 1) nrow = Nmax - 1;
    const char* Bgh = (const char*)Bh + ((size_t)nrow * H_) * 2;
    const char* Bgl = (const char*)Bl + ((size_t)nrow * H_) * 2;

    const int lr8 = lane & 7;
    const int lsel = lane >> 3;
    const unsigned int a_off = (unsigned int)((lr8 + ((lsel & 1) << 3)) * 48 + (lsel >> 1) * 16);
    const unsigned int b_off = (unsigned int)(lr8 * 48 + (((lane >> 3) & 1) ? 16 : 0));
    const unsigned int sbase = s2u(smem);

    float acc[4][8][4];
    #pragma unroll
    for (int i = 0; i < 4; i++)
        #pragma unroll
        for (int j = 0; j < 8; j++)
            #pragma unroll
            for (int q = 0; q < 4; q++) acc[i][j][q] = 0.f;

    uint4 pah, pal, pbh0, pbh1, pbl0, pbl1;
    pah  = *(const uint4*)(Agh);
    pal  = *(const uint4*)(Agl);
    pbh0 = *(const uint4*)(Bgh);
    pbh1 = *(const uint4*)(Bgh + 16);
    pbl0 = *(const uint4*)(Bgl);
    pbl1 = *(const uint4*)(Bgl + 16);
    {
        unsigned int aoff = (unsigned int)row2 * 48u + (unsigned int)seg * 16u;
        *(uint4*)(smem + aoff)           = pah;
        *(uint4*)(smem + aoff + 12288u)  = pal;
        unsigned int boff = 24576u + (unsigned int)tid * 48u;
        *(uint4*)(smem + boff)                 = pbh0;
        *(uint4*)(smem + boff + 16u)           = pbh1;
        *(uint4*)(smem + boff + 24576u)        = pbl0;
        *(uint4*)(smem + boff + 24576u + 16u)  = pbl1;
    }
    __syncthreads();

    int buf = 0;
    for (int it = 0; it < 32; it++) {
        if (it < 31) {
            int koff = (it + 1) * 32;
            pah  = *(const uint4*)(Agh + koff);
            pal  = *(const uint4*)(Agl + koff);
            pbh0 = *(const uint4*)(Bgh + koff);
            pbh1 = *(const uint4*)(Bgh + koff + 16);
            pbl0 = *(const uint4*)(Bgl + koff);
            pbl1 = *(const uint4*)(Bgl + koff + 16);
        }

        unsigned int Ahf[4][4], Alf[4][4];
        #pragma unroll
        for (int i = 0; i < 4; i++) {
            unsigned int abase = sbase + (unsigned int)buf * 6144u
                               + (unsigned int)((warp_m * 4 + i) * 768) + a_off;
            ldsm_x4(Ahf[i], abase);
            ldsm_x4(Alf[i], abase + 12288u);
        }
        #pragma unroll
        for (int nt = 0; nt < 8; nt++) {
            unsigned int baddr = sbase + 24576u + (unsigned int)buf * 12288u
                               + (unsigned int)((warp_n * 8 + nt) * 384) + b_off;
            unsigned int bh0, bh1, bl0, bl1;
            ldsm_x2(bh0, bh1, baddr);
            ldsm_x2(bl0, bl1, baddr + 24576u);
            #pragma unroll
            for (int i = 0; i < 4; i++) {
                mma16816(acc[i][nt], Ahf[i], bh0, bh1);
                mma16816(acc[i][nt], Ahf[i], bl0, bl1);
                mma16816(acc[i][nt], Alf[i], bh0, bh1);
            }
        }

        if (it < 31) {
            int nb = buf ^ 1;
            unsigned int aoff = (unsigned int)nb * 6144u
                              + (unsigned int)row2 * 48u + (unsigned int)seg * 16u;
            *(uint4*)(smem + aoff)           = pah;
            *(uint4*)(smem + aoff + 12288u)  = pal;
            unsigned int boff = 24576u + (unsigned int)nb * 12288u + (unsigned int)tid * 48u;
            *(uint4*)(smem + boff)                 = pbh0;
            *(uint4*)(smem + boff + 16u)           = pbh1;
            *(uint4*)(smem + boff + 24576u)        = pbl0;
            *(uint4*)(smem + boff + 24576u + 16u)  = pbl1;
        }
        __syncthreads();
        buf ^= 1;
    }

    const int r  = lane >> 2;
    const int c2 = (lane & 3) * 2;
    #pragma unroll
    for (int i = 0; i < 4; i++) {
        int gm = m0 + (warp_m * 4 + i) * 16 + r;
        if (modeFC != 0) {
            int b1r = gm & 255;
            int b2r = b1r + 8;
            bool v1 = t < g_len[b1r];
            bool v2 = t < g_len[b2r];
            #pragma unroll
            for (int nt = 0; nt < 8; nt++) {
                int gn = n0 + (warp_n * 8 + nt) * 8 + c2;
                if (gn < Nmax) {
                    float bi0 = aux[gn];
                    float bi1 = aux[gn + 1];
                    float* d = acc[i][nt];
                    *(float2*)&out[((size_t)b1r * T_ + t) * V_ + gn] =
                        make_float2(v1 ? d[0] + bi0 : 0.f, v1 ? d[1] + bi1 : 0.f);
                    *(float2*)&out[((size_t)b2r * T_ + t) * V_ + gn] =
                        make_float2(v2 ? d[2] + bi0 : 0.f, v2 ? d[3] + bi1 : 0.f);
                }
            }
        } else {
            int br1 = gm & 255;
            int br2 = (gm + 8) & 255;
            #pragma unroll
            for (int nt = 0; nt < 8; nt++) {
                int gn = n0 + (warp_n * 8 + nt) * 8 + c2;
                if (gn < Nmax) {
                    float2 c1 = *(const float2*)&aux[(size_t)br1 * G3 + gn];
                    float2 cc2 = *(const float2*)&aux[(size_t)br2 * G3 + gn];
                    float* d = acc[i][nt];
                    *(float2*)&out[(size_t)gm * G3 + gn] =
                        make_float2(d[0] + c1.x, d[1] + c1.y);
                    *(float2*)&out[(size_t)(gm + 8) * G3 + gn] =
                        make_float2(d[2] + cc2.x, d[3] + cc2.y);
                }
            }
        }
    }
}

// ================= persistent tensor-core GRU recurrence =================
// 128 blocks x 256 threads. Per block: 32 batch x 32 h-cols. 8 groups of 16
// blocks; group-local barriers; early exit. Staging via cp.async.bulk +
// mbarrier (2 bulk copies/iter instead of 512 cp.async).
// SMEM: 4 stages x 12288 (A 2x1536 + W 2x4608), Cs1 [49152,61952),
//       Cs2 [61952,74752), mbarriers [74752,74784). Total 74784.
#define PS_SMEM   74784
#define STAGE_SZ  12288
#define MBAR_OFF  74752u

__device__ __forceinline__ void group_bar(int g, unsigned int target)
{
    __syncthreads();
    if (threadIdx.x == 0) {
        asm volatile("red.release.gpu.global.add.u32 [%0], %1;"
                     :: "l"(&g_barG[g]), "r"(1u) : "memory");
        unsigned int v;
        while (true) {
            asm volatile("ld.acquire.gpu.global.u32 %0, [%1];"
                         : "=r"(v) : "l"(&g_barG[g]));
            if (v >= target) break;
            __nanosleep(64);
        }
        asm volatile("fence.proxy.async;" ::: "memory");
    }
    __syncthreads();
}

__device__ __forceinline__ void ps_wait(unsigned int mb, unsigned int parity)
{
    unsigned int done;
    asm volatile(
        "{\n\t.reg .pred p;\n\t"
        "mbarrier.try_wait.parity.acquire.cta.shared::cta.b64 p, [%1], %2;\n\t"
        "selp.b32 %0, 1, 0, p;\n\t}"
        : "=r"(done) : "r"(mb), "r"(parity) : "memory");
    if (!done) {
        asm volatile(
            "{\n\t.reg .pred P1;\n\t"
            "WL_%=:\n\t"
            "mbarrier.try_wait.parity.acquire.cta.shared::cta.b64 P1, [%0], %1, 0x989680;\n\t"
            "@P1 bra.uni WD_%=;\n\t"
            "bra.uni WL_%=;\n\t"
            "WD_%=:\n\t}"
            :: "r"(mb), "r"(parity) : "memory");
    }
}

// issue slab s into stage st: expect_tx + 2 bulk copies (A 3072B, W 9216B)
__device__ __forceinline__ void ps_issue(unsigned int sbase, int s, int st,
    const __nv_bfloat16* __restrict__ Abase, const __nv_bfloat16* __restrict__ Wbase)
{
    unsigned int mb = sbase + MBAR_OFF + (unsigned int)st * 8u;
    asm volatile("mbarrier.arrive.expect_tx.shared.b64 _, [%0], %1;"
                 :: "r"(mb), "r"(12288u) : "memory");
    unsigned int dst = sbase + (unsigned int)st * STAGE_SZ;
    const void* asrc = Abase + (size_t)s * (2 * HSLAB_ENT);
    const void* wsrc = Wbase + (size_t)s * (2 * WSLAB_ENT);
    asm volatile("cp.async.bulk.shared::cluster.global.mbarrier::complete_tx::bytes "
                 "[%0], [%1], %2, [%3];"
                 :: "r"(dst), "l"(asrc), "r"(3072u), "r"(mb) : "memory");
    asm volatile("cp.async.bulk.shared::cluster.global.mbarrier::complete_tx::bytes "
                 "[%0], [%1], %2, [%3];"
                 :: "r"(dst + 3072u), "l"(wsrc), "r"(9216u), "r"(mb) : "memory");
}

__device__ __forceinline__ void ps_segment(unsigned int sbase, int tid,
    int warp_m, int warp_n, unsigned int a_off, unsigned int b_off,
    const __nv_bfloat16* __restrict__ Abase, const __nv_bfloat16* __restrict__ Wbase,
    float acc[3][4])
{
    if (tid == 0) {
        ps_issue(sbase, 0, 0, Abase, Wbase);
        ps_issue(sbase, 1, 1, Abase, Wbase);
        ps_issue(sbase, 2, 2, Abase, Wbase);
    }
    for (int it = 0; it < 32; it++) {
        int st = it & 3;
        unsigned int parity = (unsigned int)((it >> 2) & 1);
        ps_wait(sbase + MBAR_OFF + (unsigned int)st * 8u, parity);
        {
            unsigned int Ahf[4], Alf[4];
            unsigned int abase = sbase + (unsigned int)st * STAGE_SZ
                               + (unsigned int)(warp_m * 16) * 48u + a_off;
            ldsm_x4(Ahf, abase);
            ldsm_x4(Alf, abase + 1536u);
            #pragma unroll
            for (int nt = 0; nt < 3; nt++) {
                unsigned int bb = sbase + (unsigned int)st * STAGE_SZ + 3072u
                                + (unsigned int)((warp_n * 24 + nt * 8) * 48) + b_off;
                unsigned int bh0, bh1, bl0, bl1;
                ldsm_x2(bh0, bh1, bb);
                ldsm_x2(bl0, bl1, bb + 4608u);
                mma16816(acc[nt], Ahf, bh0, bh1);
                mma16816(acc[nt], Ahf, bl0, bl1);
                mma16816(acc[nt], Alf, bh0, bh1);
            }
        }
        __syncthreads();
        if (tid == 0 && it + 3 < 32)
            ps_issue(sbase, it + 3, (it + 3) & 3, Abase, Wbase);
    }
}

__device__ __forceinline__ void ps_dump(unsigned char* smem, int csoff,
    int warp_m, int warp_n, int lane, float acc[3][4])
{
    float* Cs = (float*)(smem + csoff);
    int lr = lane >> 2, lc = (lane & 3) * 2;
    #pragma unroll
    for (int nt = 0; nt < 3; nt++) {
        int rowt = warp_m * 16 + lr;
        int col = warp_n * 24 + nt * 8 + lc;
        Cs[rowt * 100 + col]           = acc[nt][0];
        Cs[rowt * 100 + col + 1]       = acc[nt][1];
        Cs[(rowt + 8) * 100 + col]     = acc[nt][2];
        Cs[(rowt + 8) * 100 + col + 1] = acc[nt][3];
    }
}

__global__ void __launch_bounds__(256)
gru_persistent(const float* __restrict__ b_hh0,
               const float* __restrict__ b_ih1, const float* __restrict__ b_hh1)
{
    extern __shared__ unsigned char smem[];
    const int bx = blockIdx.x;
    const int hb = (bx & 15) * 32;
    const int hblk = hb >> 5;
    const int m0 = (bx >> 4) * 32;
    const int mtile = m0 >> 5;
    const int grp = bx >> 4;
    const int tid = threadIdx.x;
    const int lane = tid & 31;
    const int wrp = tid >> 5;
    const int warp_m = wrp >> 2;
    const int warp_n = wrp & 3;
    const int lr8 = lane & 7;
    const int lsel = lane >> 3;
    const unsigned int a_off = (unsigned int)((lr8 + ((lsel & 1) << 3)) * 48 + (lsel >> 1) * 16);
    const unsigned int b_off = (unsigned int)(lr8 * 48 + (((lane >> 3) & 1) ? 16 : 0));
    const unsigned int sbase = s2u(smem);

    // init stage mbarriers (arrive count = 1: the producer's expect_tx arrive)
    if (tid < 4) {
        asm volatile("mbarrier.init.shared.b64 [%0], %1;"
                     :: "r"(sbase + MBAR_OFF + (unsigned int)tid * 8u), "r"(1u) : "memory");
    }
    __syncthreads();

    const __nv_bfloat16* Wb_hh0 = g_whh0_s + (size_t)hblk * 32 * 2 * WSLAB_ENT;
    const __nv_bfloat16* Wb_ih1 = g_wih1_s + (size_t)hblk * 32 * 2 * WSLAB_ENT;
    const __nv_bfloat16* Wb_hh1 = g_whh1_s + (size_t)hblk * 32 * 2 * WSLAB_ENT;
    const size_t hsbase = (size_t)mtile * 32 * 2 * HSLAB_ENT;

    int t_act = 0;
    while (t_act < T_ && m0 < g_nvalid[t_act]) t_act++;

    unsigned int nbar = 0;
    for (int t = 0; t < t_act; t++) {
        const int ot = t & 1, nt2 = ot ^ 1;
        const float* h0of = g_h0f[ot];
        float*       h0nf = g_h0f[nt2];
        const float* h1of = g_h1f[ot];
        float*       h1nf = g_h1f[nt2];

        // ---------------- phase A: h0_new = GRU0(gi0[t], h0_old) ----------------
        {
            float acc[3][4];
            #pragma unroll
            for (int i = 0; i < 3; i++)
                #pragma unroll
                for (int q = 0; q < 4; q++) acc[i][q] = 0.f;
            ps_segment(sbase, tid, warp_m, warp_n, a_off, b_off,
                       g_h0s[ot] + hsbase, Wb_hh0, acc);
            ps_dump(smem, 49152, warp_m, warp_n, lane, acc);
            __syncthreads();
            const float* Cs = (const float*)(smem + 49152);
            #pragma unroll
            for (int q = 0; q < 4; q++) {
                int i = tid + q * 256;
                int m = i >> 5, hl = i & 31;
                int b = m0 + m;
                int h = hb + hl;
                size_t idx = (size_t)b * H_ + h;
                float old = h0of[idx];
                float v;
                if (t < g_len[b]) {
                    const float* gi = g_gi0 + ((size_t)t * B_ + b) * G3;
                    float r = sigf(gi[h]        + Cs[m * 100 + hl]      + b_hh0[h]);
                    float z = sigf(gi[512 + h]  + Cs[m * 100 + 32 + hl] + b_hh0[512 + h]);
                    float n = tanhf(gi[1024 + h] + r * (Cs[m * 100 + 64 + hl] + b_hh0[1024 + h]));
                    v = (1.f - z) * n + z * old;
                } else v = old;
                h0nf[idx] = v;
                __nv_bfloat16 vh = __float2bfloat16_rn(v);
                __nv_bfloat16 vl = __float2bfloat16_rn(v - __bfloat162float(vh));
                size_t sb = (size_t)((mtile * 32 + (h >> 4)) * 2) * HSLAB_ENT
                          + (size_t)(b & 31) * 24 + (h & 15);
                g_h0s[nt2][sb] = vh;
                g_h0s[nt2][sb + HSLAB_ENT] = vl;
            }
        }
        nbar++;
        group_bar(grp, nbar * GRPSZ);

        // ---------------- phase B: h1_new = GRU1(h0_new, h1_old) ----------------
        {
            float acc[3][4];
            #pragma unroll
            for (int i = 0; i < 3; i++)
                #pragma unroll
                for (int q = 0; q < 4; q++) acc[i][q] = 0.f;
            ps_segment(sbase, tid, warp_m, warp_n, a_off, b_off,
                       g_h0s[nt2] + hsbase, Wb_ih1, acc);
            ps_dump(smem, 49152, warp_m, warp_n, lane, acc);
            #pragma unroll
            for (int i = 0; i < 3; i++)
                #pragma unroll
                for (int q = 0; q < 4; q++) acc[i][q] = 0.f;
            ps_segment(sbase, tid, warp_m, warp_n, a_off, b_off,
                       g_h1s[ot] + hsbase, Wb_hh1, acc);
            ps_dump(smem, 61952, warp_m, warp_n, lane, acc);
            __syncthreads();
            const float* Cs1 = (const float*)(smem + 49152);
            const float* Cs2 = (const float*)(smem + 61952);
            #pragma unroll
            for (int q = 0; q < 4; q++) {
                int i = tid + q * 256;
                int m = i >> 5, hl = i & 31;
                int b = m0 + m;
                int h = hb + hl;
                size_t idx = (size_t)b * H_ + h;
                size_t hidx = ((size_t)t * B_ + b) * H_ + h;
                size_t sb = (size_t)((mtile * 32 + (h >> 4)) * 2) * HSLAB_ENT
                          + (size_t)(b & 31) * 24 + (h & 15);
                float old = h1of[idx];
                if (t < g_len[b]) {
                    float r = sigf(Cs1[m * 100 + hl]      + b_ih1[h]
                                 + Cs2[m * 100 + hl]      + b_hh1[h]);
                    float z = sigf(Cs1[m * 100 + 32 + hl] + b_ih1[512 + h]
                                 + Cs2[m * 100 + 32 + hl] + b_hh1[512 + h]);
                    float n = tanhf(Cs1[m * 100 + 64 + hl] + b_ih1[1024 + h]
                                  + r * (Cs2[m * 100 + 64 + hl] + b_hh1[1024 + h]));
                    float v = (1.f - z) * n + z * old;
                    h1nf[idx] = v;
                    __nv_bfloat16 vh = __float2bfloat16_rn(v);
                    __nv_bfloat16 vl = __float2bfloat16_rn(v - __bfloat162float(vh));
                    g_h1s[nt2][sb] = vh;
                    g_h1s[nt2][sb + HSLAB_ENT] = vl;
                    g_H1h[hidx] = vh;
                    g_H1l[hidx] = vl;
                } else {
                    h1nf[idx] = old;
                    g_h1s[nt2][sb] = g_h1s[ot][sb];
                    g_h1s[nt2][sb + HSLAB_ENT] = g_h1s[ot][sb + HSLAB_ENT];
                    g_H1h[hidx] = __float2bfloat16_rn(0.f);
                    g_H1l[hidx] = __float2bfloat16_rn(0.f);
                }
            }
        }
        nbar++;
        group_bar(grp, nbar * GRPSZ);
    }
}

// ---------------- host orchestration (graph-capturable: launches only) ----------------
extern "C" void kernel_launch(void* const* d_in, const int* in_sizes, int n_in,
                              void* d_out, int out_size)
{
    const float* image_code = (const float*)d_in[0];
    const int*   captions   = (const int*)  d_in[1];
    const int*   cap_lens   = (const int*)  d_in[2];
    const float* embed_w    = (const float*)d_in[3];
    const float* init_w     = (const float*)d_in[4];
    const float* init_b     = (const float*)d_in[5];
    const float* w_ih0      = (const float*)d_in[6];
    const float* w_hh0      = (const float*)d_in[7];
    const float* b_ih0      = (const float*)d_in[8];
    const float* b_hh0      = (const float*)d_in[9];
    const float* w_ih1      = (const float*)d_in[10];
    const float* w_hh1      = (const float*)d_in[11];
    const float* b_ih1      = (const float*)d_in[12];
    const float* b_hh1      = (const float*)d_in[13];
    const float* fc_w       = (const float*)d_in[14];
    const float* fc_b       = (const float*)d_in[15];
    float* out = (float*)d_out;

    void* p;
    cudaGetSymbolAddress(&p, g_img);     float* dimg  = (float*)p;
    cudaGetSymbolAddress(&p, g_gi0c);    float* dgi0c = (float*)p;
    cudaGetSymbolAddress(&p, g_gi0);     float* dgi0  = (float*)p;
    cudaGetSymbolAddress(&p, g_h0f);     float* dh0a  = (float*)p;
    cudaGetSymbolAddress(&p, g_h1f);     float* dh1a  = (float*)p;
    cudaGetSymbolAddress(&p, g_rowidx);  int*   drow  = (int*)p;
    cudaGetSymbolAddress(&p, g_fcw_h);   __nv_bfloat16* dfcwh = (__nv_bfloat16*)p;
    cudaGetSymbolAddress(&p, g_fcw_l);   __nv_bfloat16* dfcwl = (__nv_bfloat16*)p;
    cudaGetSymbolAddress(&p, g_emb_h);   __nv_bfloat16* dembh = (__nv_bfloat16*)p;
    cudaGetSymbolAddress(&p, g_emb_l);   __nv_bfloat16* dembl = (__nv_bfloat16*)p;
    cudaGetSymbolAddress(&p, g_wih0e_h); __nv_bfloat16* dw0h  = (__nv_bfloat16*)p;
    cudaGetSymbolAddress(&p, g_wih0e_l); __nv_bfloat16* dw0l  = (__nv_bfloat16*)p;
    cudaGetSymbolAddress(&p, g_whh0_s);  __nv_bfloat16* dwhh0s = (__nv_bfloat16*)p;
    cudaGetSymbolAddress(&p, g_wih1_s);  __nv_bfloat16* dwih1s = (__nv_bfloat16*)p;
    cudaGetSymbolAddress(&p, g_whh1_s);  __nv_bfloat16* dwhh1s = (__nv_bfloat16*)p;
    cudaGetSymbolAddress(&p, g_H1h);     __nv_bfloat16* dH1h  = (__nv_bfloat16*)p;
    cudaGetSymbolAddress(&p, g_H1l);     __nv_bfloat16* dH1l  = (__nv_bfloat16*)p;
    cudaGetSymbolAddress(&p, g_h0s);     __nv_bfloat16* dh0s0 = (__nv_bfloat16*)p;
    cudaGetSymbolAddress(&p, g_h1s);     __nv_bfloat16* dh1s0 = (__nv_bfloat16*)p;

    cudaFuncSetAttribute(mmagemm_kernel,
                         cudaFuncAttributeMaxDynamicSharedMemorySize, MMA_SMEM_BYTES);
    cudaFuncSetAttribute(gru_persistent,
                         cudaFuncAttributeMaxDynamicSharedMemorySize, PS_SMEM);

    // 0. weight preconversion
    const int NW = V_ * H_;
    const int NG = G3 * H_;
    convw_kernel<<<(NW + 255) / 256, 256>>>(fc_w,    H_, 0,   dfcwh, dfcwl, NW);
    convw_kernel<<<(NW + 255) / 256, 256>>>(embed_w, H_, 0,   dembh, dembl, NW);
    convw_kernel<<<(NG + 255) / 256, 256>>>(w_ih0, IC_ + WD_, IC_, dw0h, dw0l, NG);
    convw_slab_kernel<<<NG / 256, 256>>>(w_hh0, dwhh0s);
    convw_slab_kernel<<<NG / 256, 256>>>(w_ih1, dwih1s);
    convw_slab_kernel<<<NG / 256, 256>>>(w_hh1, dwhh1s);

    // 1. sort + metadata + aux outputs (also resets group barriers)
    sort_kernel<<<1, 256>>>(cap_lens, captions, out, (long long)out_size);
    // 2. gather sorted image codes
    gather_img_kernel<<<(B_ * IC_) / 256, 256>>>(image_code);
    // 3. h0/h1 init in ONE GEMM: (256, 1024, K=2048) -> g_h0f[0], g_h1f[0]
    gemm64_kernel<<<dim3(16, 4), 256>>>(dimg, IC_, init_w, IC_, init_b,
                                        dh0a, H_, dh1a, IC_);
    // 3b. initial hidden -> slabbed bf16 planes (buffer 0)
    convh_slab_kernel<<<(B_ * H_) / 256, 256>>>(dh0a, dh0s0);
    convh_slab_kernel<<<(B_ * H_) / 256, 256>>>(dh1a, dh1s0);
    // 4. time-invariant img part of layer0 input gates (+ b_ih0)
    gemm64_kernel<<<dim3(24, 4), 256>>>(dimg, IC_, w_ih0, IC_ + WD_, b_ih0,
                                        dgi0c, G3, nullptr, IC_);
    // 5. embedding-side layer0 input gates for ALL 12800 tokens (+ gi0c broadcast)
    mmagemm_kernel<<<dim3(6, 100), 256, MMA_SMEM_BYTES>>>(
        dembh, dembl, drow, dw0h, dw0l, dgi0c, dgi0, G3, 0);
    // 6. persistent recurrence (bulk-copy pipeline, group barriers, early exit)
    gru_persistent<<<NBLK, 256, PS_SMEM>>>(b_hh0, b_ih1, b_hh1);
    // 7. FC head on tensor cores
    mmagemm_kernel<<<dim3(40, 100), 256, MMA_SMEM_BYTES>>>(
        dH1h, dH1l, nullptr, dfcwh, dfcwl, fc_b, out, V_, 1);
}

// round 12
// speedup vs baseline: 3.2921x; 1.1392x over previous
#include <cuda_runtime.h>
#include <cuda_bf16.h>
#include <stdint.h>
#include <cstdint>
#include <math.h>

// Problem constants
#define B_    256
#define TCAP  51
#define T_    50
#define V_    10000
#define WD_   512
#define H_    512
#define IC_   2048
#define G3    1536    // 3*H
#define NBLK  128     // persistent recurrence blocks
#define GRPSZ 16      // blocks per batch-tile group

// ---------------- static device scratch ----------------
__device__ float g_img [B_ * IC_];
__device__ float g_gi0c[B_ * G3];
__device__ float g_gi0 [(size_t)T_ * B_ * G3];   // precomputed layer0 input gates
__device__ float g_h0f [2][B_ * H_];             // fp32 hidden ping-pong
__device__ float g_h1f [2][B_ * H_];
__device__ int   g_order [B_];
__device__ int   g_len   [B_];
__device__ int   g_nvalid[T_];
__device__ int   g_rowidx[T_ * B_];
__device__ unsigned int g_barG[8];               // per-group barrier counters

// bf16 hi/lo planes (flat) for the big GEMMs — 128B-aligned (uint4 / bulk reads)
__device__ __align__(128) __nv_bfloat16 g_fcw_h [(size_t)V_ * H_];
__device__ __align__(128) __nv_bfloat16 g_fcw_l [(size_t)V_ * H_];
__device__ __align__(128) __nv_bfloat16 g_emb_h [(size_t)V_ * H_];
__device__ __align__(128) __nv_bfloat16 g_emb_l [(size_t)V_ * H_];
__device__ __align__(128) __nv_bfloat16 g_wih0e_h[G3 * H_];
__device__ __align__(128) __nv_bfloat16 g_wih0e_l[G3 * H_];
__device__ __align__(128) __nv_bfloat16 g_H1h [(size_t)T_ * B_ * H_];
__device__ __align__(128) __nv_bfloat16 g_H1l [(size_t)T_ * B_ * H_];

// slabbed layouts for the persistent recurrence (contiguous per (block, k-slab))
// ALIGNMENT IS LOAD-BEARING: cp.async.bulk requires 16B-aligned global src.
// weight: [hblk 16][slab 32][plane 2][row 96][24 entries (48B: 32B data+16B pad)]
#define WSLAB_ENT 2304            // 96*24 per plane
__device__ __align__(128) __nv_bfloat16 g_whh0_s[16 * 32 * 2 * WSLAB_ENT];
__device__ __align__(128) __nv_bfloat16 g_wih1_s[16 * 32 * 2 * WSLAB_ENT];
__device__ __align__(128) __nv_bfloat16 g_whh1_s[16 * 32 * 2 * WSLAB_ENT];
// hidden: [mtile 8][slab 32][plane 2][row 32][24 entries]
#define HSLAB_ENT 768             // 32*24 per plane
__device__ __align__(128) __nv_bfloat16 g_h0s[2][8 * 32 * 2 * HSLAB_ENT];
__device__ __align__(128) __nv_bfloat16 g_h1s[2][8 * 32 * 2 * HSLAB_ENT];

// fast gates: __expf-based (rel err ~1e-6, correct saturation)
__device__ __forceinline__ float sigf(float x) {
    return __fdividef(1.f, 1.f + __expf(-x));
}
__device__ __forceinline__ float tanhfast(float x) {
    return 1.f - __fdividef(2.f, __expf(2.f * x) + 1.f);
}

// ---------------- flat weight preconversion: fp32 -> bf16 hi + bf16 lo ----------------
__global__ void convw_kernel(const float* __restrict__ src, int ld, int col0,
                             __nv_bfloat16* __restrict__ dh,
                             __nv_bfloat16* __restrict__ dl, int n)
{
    int i = blockIdx.x * 256 + threadIdx.x;
    if (i >= n) return;
    int row = i >> 9;
    int col = i & 511;
    float x = src[(size_t)row * ld + col0 + col];
    __nv_bfloat16 h = __float2bfloat16_rn(x);
    dh[i] = h;
    dl[i] = __float2bfloat16_rn(x - __bfloat162float(h));
}

// ---------------- slabbed weight conversion (recurrence weights) ----------------
__global__ void convw_slab_kernel(const float* __restrict__ src,
                                  __nv_bfloat16* __restrict__ dst)
{
    int i = blockIdx.x * 256 + threadIdx.x;      // 786432 total
    int e = i & 15;
    int row = (i >> 4) % 96;
    int tmp = (i >> 4) / 96;                     // 0..511
    int slab = tmp & 31;
    int hblk = tmp >> 5;
    int g = row >> 5, r = row & 31;
    float x = src[(size_t)(g * 512 + hblk * 32 + r) * 512 + slab * 16 + e];
    __nv_bfloat16 h = __float2bfloat16_rn(x);
    size_t base = (size_t)((hblk * 32 + slab) * 2) * WSLAB_ENT;
    dst[base + row * 24 + e] = h;
    dst[base + WSLAB_ENT + row * 24 + e] = __float2bfloat16_rn(x - __bfloat162float(h));
}

// ---------------- slabbed hidden conversion (initial h0/h1) ----------------
__global__ void convh_slab_kernel(const float* __restrict__ src,
                                  __nv_bfloat16* __restrict__ dst)
{
    int i = blockIdx.x * 256 + threadIdx.x;      // 131072 total
    int e = i & 15;
    int slab = (i >> 4) & 31;
    int row = (i >> 9) & 31;
    int mtile = i >> 14;
    float x = src[(size_t)(mtile * 32 + row) * 512 + slab * 16 + e];
    __nv_bfloat16 h = __float2bfloat16_rn(x);
    size_t base = (size_t)((mtile * 32 + slab) * 2) * HSLAB_ENT;
    dst[base + row * 24 + e] = h;
    dst[base + HSLAB_ENT + row * 24 + e] = __float2bfloat16_rn(x - __bfloat162float(h));
}

// ---------------- sort + metadata (stable descending by cap_len) ----------------
__global__ void sort_kernel(const int* __restrict__ cap_lens,
                            const int* __restrict__ captions,
                            float* __restrict__ out, long long out_size)
{
    __shared__ int lens[B_];
    __shared__ int ord [B_];
    int i = threadIdx.x;
    if (i < 8) g_barG[i] = 0u;
    lens[i] = cap_lens[i];
    __syncthreads();
    int li = lens[i];
    int rank = 0;
    #pragma unroll 8
    for (int j = 0; j < B_; j++) {
        int lj = lens[j];
        rank += (lj > li) || (lj == li && j < i);
    }
    ord[rank] = i;
    __syncthreads();
    int src = ord[i];
    int len = lens[src] - 1;
    g_order[i] = src;
    g_len[i]   = len;
    if (i < T_) {
        int c = 0;
        #pragma unroll 8
        for (int b = 0; b < B_; b++) c += (lens[ord[b]] - 1) > i;
        g_nvalid[i] = c;
    }
    const long long PRED = (long long)B_ * T_ * V_;
    for (int t = 0; t < TCAP; t++) {
        int tok = captions[src * TCAP + t];
        if (t < T_) g_rowidx[t * B_ + i] = tok;
        if (out_size >= PRED + (long long)B_ * TCAP)
            out[PRED + (long long)i * TCAP + t] = (float)tok;
    }
    if (out_size >= PRED + (long long)B_ * TCAP + 2LL * B_) {
        out[PRED + (long long)B_ * TCAP + i]      = (float)len;
        out[PRED + (long long)B_ * TCAP + B_ + i] = (float)src;
    }
}

__global__ void gather_img_kernel(const float* __restrict__ image_code)
{
    int idx = blockIdx.x * 256 + threadIdx.x;
    int b = idx >> 11, k = idx & 2047;
    g_img[idx] = image_code[g_order[b] * IC_ + k];
}

// ---------------- 64x64 tile SIMT GEMM for deep-K prologue (inits, gi0c) ----------------
__global__ void __launch_bounds__(256)
gemm64_kernel(const float* __restrict__ A, int lda,
              const float* __restrict__ Bw, int ldb,
              const float* __restrict__ bias,
              float* __restrict__ C, int ldc, float* __restrict__ Cb, int K)
{
    __shared__ float As[16][68];
    __shared__ float Bs[16][68];
    int m0 = blockIdx.y * 64, n0 = blockIdx.x * 64;
    int tid = threadIdx.x;
    int lr = tid >> 2, kq = (tid & 3) * 4;
    const float* Ap = A  + (size_t)(m0 + lr) * lda + kq;
    const float* Bp = Bw + (size_t)(n0 + lr) * ldb + kq;
    int tx = tid & 15, ty = tid >> 4;
    float acc[4][4] = {};
    for (int k0 = 0; k0 < K; k0 += 16) {
        float4 av = *(const float4*)(Ap + k0);
        float4 bv = *(const float4*)(Bp + k0);
        As[kq+0][lr]=av.x; As[kq+1][lr]=av.y; As[kq+2][lr]=av.z; As[kq+3][lr]=av.w;
        Bs[kq+0][lr]=bv.x; Bs[kq+1][lr]=bv.y; Bs[kq+2][lr]=bv.z; Bs[kq+3][lr]=bv.w;
        __syncthreads();
        #pragma unroll
        for (int k = 0; k < 16; k++) {
            float4 a = *(const float4*)&As[k][ty*4];
            float4 b = *(const float4*)&Bs[k][tx*4];
            acc[0][0]+=a.x*b.x; acc[0][1]+=a.x*b.y; acc[0][2]+=a.x*b.z; acc[0][3]+=a.x*b.w;
            acc[1][0]+=a.y*b.x; acc[1][1]+=a.y*b.y; acc[1][2]+=a.y*b.z; acc[1][3]+=a.y*b.w;
            acc[2][0]+=a.z*b.x; acc[2][1]+=a.z*b.y; acc[2][2]+=a.z*b.z; acc[2][3]+=a.z*b.w;
            acc[3][0]+=a.w*b.x; acc[3][1]+=a.w*b.y; acc[3][2]+=a.w*b.z; acc[3][3]+=a.w*b.w;
        }
        __syncthreads();
    }
    #pragma unroll
    for (int i = 0; i < 4; i++) {
        int m = m0 + ty * 4 + i;
        #pragma unroll
        for (int j = 0; j < 4; j++) {
            int n = n0 + tx * 4 + j;
            float v = acc[i][j] + (bias ? bias[n] : 0.f);
            if (Cb) {
                if (n < H_) C [(size_t)m * H_ + n]       = v;
                else        Cb[(size_t)m * H_ + (n-H_)]  = v;
            } else {
                C[(size_t)m * ldc + n] = v;
            }
        }
    }
}

// ---------------- tensor-core bf16-3term GEMM machinery ----------------
__device__ __forceinline__ unsigned int s2u(const void* p) {
    return (unsigned int)__cvta_generic_to_shared(p);
}
__device__ __forceinline__ void ldsm_x4(unsigned int* r, unsigned int addr) {
    asm volatile("ldmatrix.sync.aligned.m8n8.x4.shared.b16 {%0,%1,%2,%3},[%4];"
        : "=r"(r[0]), "=r"(r[1]), "=r"(r[2]), "=r"(r[3]) : "r"(addr));
}
__device__ __forceinline__ void ldsm_x2(unsigned int& r0, unsigned int& r1, unsigned int addr) {
    asm volatile("ldmatrix.sync.aligned.m8n8.x2.shared.b16 {%0,%1},[%2];"
        : "=r"(r0), "=r"(r1) : "r"(addr));
}
__device__ __forceinline__ void mma16816(float* d, const unsigned int* a,
                                         unsigned int b0, unsigned int b1) {
    asm volatile("mma.sync.aligned.m16n8k16.row.col.f32.bf16.bf16.f32 "
        "{%0,%1,%2,%3},{%4,%5,%6,%7},{%8,%9},{%0,%1,%2,%3};"
        : "+f"(d[0]), "+f"(d[1]), "+f"(d[2]), "+f"(d[3])
        : "r"(a[0]), "r"(a[1]), "r"(a[2]), "r"(a[3]), "r"(b0), "r"(b1));
}

// ---------------- big parallel mma GEMM (gi0 + FC), proven ----------------
#define MMA_SMEM_BYTES 73728

__global__ void __launch_bounds__(256)
mmagemm_kernel(const __nv_bfloat16* __restrict__ Ah, const __nv_bfloat16* __restrict__ Al,
               const int* __restrict__ rowidx,
               const __nv_bfloat16* __restrict__ Bh, const __nv_bfloat16* __restrict__ Bl,
               const float* __restrict__ aux,
               float* __restrict__ out, int Nmax, int modeFC)
{
    extern __shared__ unsigned char smem[];
    const int tid = threadIdx.x;
    const int m0 = blockIdx.y * 128;
    const int n0 = blockIdx.x * 256;
    const int t  = m0 >> 8;
    const int bbase = m0 & 255;

    if (modeFC != 0) {
        if (t >= g_len[bbase]) {
            float4 z = make_float4(0.f, 0.f, 0.f, 0.f);
            for (int idx = tid * 4; idx < 128 * 256; idx += 1024) {
                int rr = idx >> 8;
                int cc = idx & 255;
                int gn = n0 + cc;
                if (gn < Nmax) {
                    int b = bbase + rr;
                    *(float4*)&out[((size_t)b * T_ + t) * V_ + gn] = z;
                }
            }
            return;
        }
    }

    const int lane = tid & 31;
    const int w = tid >> 5;
    const int warp_m = w & 1;
    const int warp_n = w >> 1;

    const int row2 = tid >> 1;
    const int seg = tid & 1;
    int am = m0 + row2;
    int arow = rowidx ? rowidx[am] : am;
    const char* Agh = (const char*)Ah + ((size_t)arow * H_) * 2 + seg * 16;
    const char* Agl = (const char*)Al + ((size_t)arow * H_) * 2 + seg * 16;
    int nrow = n0 + tid;
    if (nrow > Nmax - 1) nrow = Nmax - 1;
    const char* Bgh = (const char*)Bh + ((size_t)nrow * H_) * 2;
    const char* Bgl = (const char*)Bl + ((size_t)nrow * H_) * 2;

    const int lr8 = lane & 7;
    const int lsel = lane >> 3;
    const unsigned int a_off = (unsigned int)((lr8 + ((lsel & 1) << 3)) * 48 + (lsel >> 1) * 16);
    const unsigned int b_off = (unsigned int)(lr8 * 48 + (((lane >> 3) & 1) ? 16 : 0));
    const unsigned int sbase = s2u(smem);

    float acc[4][8][4];
    #pragma unroll
    for (int i = 0; i < 4; i++)
        #pragma unroll
        for (int j = 0; j < 8; j++)
            #pragma unroll
            for (int q = 0; q < 4; q++) acc[i][j][q] = 0.f;

    uint4 pah, pal, pbh0, pbh1, pbl0, pbl1;
    pah  = *(const uint4*)(Agh);
    pal  = *(const uint4*)(Agl);
    pbh0 = *(const uint4*)(Bgh);
    pbh1 = *(const uint4*)(Bgh + 16);
    pbl0 = *(const uint4*)(Bgl);
    pbl1 = *(const uint4*)(Bgl + 16);
    {
        unsigned int aoff = (unsigned int)row2 * 48u + (unsigned int)seg * 16u;
        *(uint4*)(smem + aoff)           = pah;
        *(uint4*)(smem + aoff + 12288u)  = pal;
        unsigned int boff = 24576u + (unsigned int)tid * 48u;
        *(uint4*)(smem + boff)                 = pbh0;
        *(uint4*)(smem + boff + 16u)           = pbh1;
        *(uint4*)(smem + boff + 24576u)        = pbl0;
        *(uint4*)(smem + boff + 24576u + 16u)  = pbl1;
    }
    __syncthreads();

    int buf = 0;
    for (int it = 0; it < 32; it++) {
        if (it < 31) {
            int koff = (it + 1) * 32;
            pah  = *(const uint4*)(Agh + koff);
            pal  = *(const uint4*)(Agl + koff);
            pbh0 = *(const uint4*)(Bgh + koff);
            pbh1 = *(const uint4*)(Bgh + koff + 16);
            pbl0 = *(const uint4*)(Bgl + koff);
            pbl1 = *(const uint4*)(Bgl + koff + 16);
        }

        unsigned int Ahf[4][4], Alf[4][4];
        #pragma unroll
        for (int i = 0; i < 4; i++) {
            unsigned int abase = sbase + (unsigned int)buf * 6144u
                               + (unsigned int)((warp_m * 4 + i) * 768) + a_off;
            ldsm_x4(Ahf[i], abase);
            ldsm_x4(Alf[i], abase + 12288u);
        }
        #pragma unroll
        for (int nt = 0; nt < 8; nt++) {
            unsigned int baddr = sbase + 24576u + (unsigned int)buf * 12288u
                               + (unsigned int)((warp_n * 8 + nt) * 384) + b_off;
            unsigned int bh0, bh1, bl0, bl1;
            ldsm_x2(bh0, bh1, baddr);
            ldsm_x2(bl0, bl1, baddr + 24576u);
            #pragma unroll
            for (int i = 0; i < 4; i++) {
                mma16816(acc[i][nt], Ahf[i], bh0, bh1);
                mma16816(acc[i][nt], Ahf[i], bl0, bl1);
                mma16816(acc[i][nt], Alf[i], bh0, bh1);
            }
        }

        if (it < 31) {
            int nb = buf ^ 1;
            unsigned int aoff = (unsigned int)nb * 6144u
                              + (unsigned int)row2 * 48u + (unsigned int)seg * 16u;
            *(uint4*)(smem + aoff)           = pah;
            *(uint4*)(smem + aoff + 12288u)  = pal;
            unsigned int boff = 24576u + (unsigned int)nb * 12288u + (unsigned int)tid * 48u;
            *(uint4*)(smem + boff)                 = pbh0;
            *(uint4*)(smem + boff + 16u)           = pbh1;
            *(uint4*)(smem + boff + 24576u)        = pbl0;
            *(uint4*)(smem + boff + 24576u + 16u)  = pbl1;
        }
        __syncthreads();
        buf ^= 1;
    }

    const int r  = lane >> 2;
    const int c2 = (lane & 3) * 2;
    #pragma unroll
    for (int i = 0; i < 4; i++) {
        int gm = m0 + (warp_m * 4 + i) * 16 + r;
        if (modeFC != 0) {
            int b1r = gm & 255;
            int b2r = b1r + 8;
            bool v1 = t < g_len[b1r];
            bool v2 = t < g_len[b2r];
            #pragma unroll
            for (int nt = 0; nt < 8; nt++) {
                int gn = n0 + (warp_n * 8 + nt) * 8 + c2;
                if (gn < Nmax) {
                    float bi0 = aux[gn];
                    float bi1 = aux[gn + 1];
                    float* d = acc[i][nt];
                    *(float2*)&out[((size_t)b1r * T_ + t) * V_ + gn] =
                        make_float2(v1 ? d[0] + bi0 : 0.f, v1 ? d[1] + bi1 : 0.f);
                    *(float2*)&out[((size_t)b2r * T_ + t) * V_ + gn] =
                        make_float2(v2 ? d[2] + bi0 : 0.f, v2 ? d[3] + bi1 : 0.f);
                }
            }
        } else {
            int br1 = gm & 255;
            int br2 = (gm + 8) & 255;
            #pragma unroll
            for (int nt = 0; nt < 8; nt++) {
                int gn = n0 + (warp_n * 8 + nt) * 8 + c2;
                if (gn < Nmax) {
                    float2 c1 = *(const float2*)&aux[(size_t)br1 * G3 + gn];
                    float2 cc2 = *(const float2*)&aux[(size_t)br2 * G3 + gn];
                    float* d = acc[i][nt];
                    *(float2*)&out[(size_t)gm * G3 + gn] =
                        make_float2(d[0] + c1.x, d[1] + c1.y);
                    *(float2*)&out[(size_t)(gm + 8) * G3 + gn] =
                        make_float2(d[2] + cc2.x, d[3] + cc2.y);
                }
            }
        }
    }
}

// ================= persistent tensor-core GRU recurrence =================
// ROUND-10 PROVEN skeleton (blocking group barriers) + BK=32 stages + fast gates.
// 128 blocks x 256 threads. Per block: 32 batch x 32 h-cols. 8 groups of 16.
// SMEM: 4 stages x 24576 (2 k-chunks each: A 2x(2x1536) + W 2x(2x4608)),
//       Cs1 [98304,111104), Cs2 [111104,123904), mbarriers [123904,123936).
#define PS_SMEM   123936
#define STAGE_SZ  24576
#define CS1_OFF   98304
#define CS2_OFF   111104
#define MBAR_OFF  123904u

__device__ __forceinline__ void group_bar(int g, unsigned int target)
{
    __syncthreads();
    if (threadIdx.x == 0) {
        asm volatile("red.release.gpu.global.add.u32 [%0], %1;"
                     :: "l"(&g_barG[g]), "r"(1u) : "memory");
        unsigned int v;
        while (true) {
            asm volatile("ld.acquire.gpu.global.u32 %0, [%1];"
                         : "=r"(v) : "l"(&g_barG[g]));
            if (v >= target) break;
            __nanosleep(64);
        }
        asm volatile("fence.proxy.async;" ::: "memory");
    }
    __syncthreads();
}

__device__ __forceinline__ void ps_wait(unsigned int mb, unsigned int parity)
{
    unsigned int done;
    asm volatile(
        "{\n\t.reg .pred p;\n\t"
        "mbarrier.try_wait.parity.acquire.cta.shared::cta.b64 p, [%1], %2;\n\t"
        "selp.b32 %0, 1, 0, p;\n\t}"
        : "=r"(done) : "r"(mb), "r"(parity) : "memory");
    if (!done) {
        asm volatile(
            "{\n\t.reg .pred P1;\n\t"
            "WL_%=:\n\t"
            "mbarrier.try_wait.parity.acquire.cta.shared::cta.b64 P1, [%0], %1, 0x989680;\n\t"
            "@P1 bra.uni WD_%=;\n\t"
            "bra.uni WL_%=;\n\t"
            "WD_%=:\n\t}"
            :: "r"(mb), "r"(parity) : "memory");
    }
}

// issue slab-pair p (slabs 2p,2p+1) into stage st: expect_tx + 2 bulk copies
__device__ __forceinline__ void ps_issue(unsigned int sbase, int pair, int st,
    const __nv_bfloat16* __restrict__ Abase, const __nv_bfloat16* __restrict__ Wbase)
{
    unsigned int mb = sbase + MBAR_OFF + (unsigned int)st * 8u;
    asm volatile("mbarrier.arrive.expect_tx.shared.b64 _, [%0], %1;"
                 :: "r"(mb), "r"(24576u) : "memory");
    unsigned int dst = sbase + (unsigned int)st * STAGE_SZ;
    const void* asrc = Abase + (size_t)(2 * pair) * (2 * HSLAB_ENT);   // 6144 B
    const void* wsrc = Wbase + (size_t)(2 * pair) * (2 * WSLAB_ENT);   // 18432 B
    asm volatile("cp.async.bulk.shared::cluster.global.mbarrier::complete_tx::bytes "
                 "[%0], [%1], %2, [%3];"
                 :: "r"(dst), "l"(asrc), "r"(6144u), "r"(mb) : "memory");
    asm volatile("cp.async.bulk.shared::cluster.global.mbarrier::complete_tx::bytes "
                 "[%0], [%1], %2, [%3];"
                 :: "r"(dst + 6144u), "l"(wsrc), "r"(18432u), "r"(mb) : "memory");
}

__device__ __forceinline__ void ps_segment(unsigned int sbase, int tid,
    int warp_m, int warp_n, unsigned int a_off, unsigned int b_off,
    const __nv_bfloat16* __restrict__ Abase, const __nv_bfloat16* __restrict__ Wbase,
    float acc[3][4])
{
    if (tid == 0) {
        ps_issue(sbase, 0, 0, Abase, Wbase);
        ps_issue(sbase, 1, 1, Abase, Wbase);
        ps_issue(sbase, 2, 2, Abase, Wbase);
    }
    for (int it = 0; it < 16; it++) {
        int st = it & 3;
        unsigned int parity = (unsigned int)((it >> 2) & 1);
        ps_wait(sbase + MBAR_OFF + (unsigned int)st * 8u, parity);
        #pragma unroll
        for (int c = 0; c < 2; c++) {
            unsigned int Ahf[4], Alf[4];
            unsigned int abase = sbase + (unsigned int)st * STAGE_SZ
                               + (unsigned int)c * 3072u
                               + (unsigned int)(warp_m * 16) * 48u + a_off;
            ldsm_x4(Ahf, abase);
            ldsm_x4(Alf, abase + 1536u);
            #pragma unroll
            for (int nt = 0; nt < 3; nt++) {
                unsigned int bb = sbase + (unsigned int)st * STAGE_SZ + 6144u
                                + (unsigned int)c * 9216u
                                + (unsigned int)((warp_n * 24 + nt * 8) * 48) + b_off;
                unsigned int bh0, bh1, bl0, bl1;
                ldsm_x2(bh0, bh1, bb);
                ldsm_x2(bl0, bl1, bb + 4608u);
                mma16816(acc[nt], Ahf, bh0, bh1);
                mma16816(acc[nt], Ahf, bl0, bl1);
                mma16816(acc[nt], Alf, bh0, bh1);
            }
        }
        __syncthreads();
        if (tid == 0 && it + 3 < 16)
            ps_issue(sbase, it + 3, (it + 3) & 3, Abase, Wbase);
    }
}

__device__ __forceinline__ void ps_dump(unsigned char* smem, int csoff,
    int warp_m, int warp_n, int lane, float acc[3][4])
{
    float* Cs = (float*)(smem + csoff);
    int lr = lane >> 2, lc = (lane & 3) * 2;
    #pragma unroll
    for (int nt = 0; nt < 3; nt++) {
        int rowt = warp_m * 16 + lr;
        int col = warp_n * 24 + nt * 8 + lc;
        Cs[rowt * 100 + col]           = acc[nt][0];
        Cs[rowt * 100 + col + 1]       = acc[nt][1];
        Cs[(rowt + 8) * 100 + col]     = acc[nt][2];
        Cs[(rowt + 8) * 100 + col + 1] = acc[nt][3];
    }
}

__global__ void __launch_bounds__(256)
gru_persistent(const float* __restrict__ b_hh0,
               const float* __restrict__ b_ih1, const float* __restrict__ b_hh1)
{
    extern __shared__ unsigned char smem[];
    const int bx = blockIdx.x;
    const int hb = (bx & 15) * 32;
    const int hblk = hb >> 5;
    const int m0 = (bx >> 4) * 32;
    const int mtile = m0 >> 5;
    const int grp = bx >> 4;
    const int tid = threadIdx.x;
    const int lane = tid & 31;
    const int wrp = tid >> 5;
    const int warp_m = wrp >> 2;
    const int warp_n = wrp & 3;
    const int lr8 = lane & 7;
    const int lsel = lane >> 3;
    const unsigned int a_off = (unsigned int)((lr8 + ((lsel & 1) << 3)) * 48 + (lsel >> 1) * 16);
    const unsigned int b_off = (unsigned int)(lr8 * 48 + (((lane >> 3) & 1) ? 16 : 0));
    const unsigned int sbase = s2u(smem);

    if (tid < 4) {
        asm volatile("mbarrier.init.shared.b64 [%0], %1;"
                     :: "r"(sbase + MBAR_OFF + (unsigned int)tid * 8u), "r"(1u) : "memory");
    }
    __syncthreads();

    const __nv_bfloat16* Wb_hh0 = g_whh0_s + (size_t)hblk * 32 * 2 * WSLAB_ENT;
    const __nv_bfloat16* Wb_ih1 = g_wih1_s + (size_t)hblk * 32 * 2 * WSLAB_ENT;
    const __nv_bfloat16* Wb_hh1 = g_whh1_s + (size_t)hblk * 32 * 2 * WSLAB_ENT;
    const size_t hsbase = (size_t)mtile * 32 * 2 * HSLAB_ENT;

    int t_act = 0;
    while (t_act < T_ && m0 < g_nvalid[t_act]) t_act++;   // same for whole group

    unsigned int nbar = 0;
    for (int t = 0; t < t_act; t++) {
        const int ot = t & 1, nt2 = ot ^ 1;
        const float* h0of = g_h0f[ot];
        float*       h0nf = g_h0f[nt2];
        const float* h1of = g_h1f[ot];
        float*       h1nf = g_h1f[nt2];

        // ---------------- phase A: h0_new = GRU0(gi0[t], h0_old) ----------------
        {
            float acc[3][4];
            #pragma unroll
            for (int i = 0; i < 3; i++)
                #pragma unroll
                for (int q = 0; q < 4; q++) acc[i][q] = 0.f;
            ps_segment(sbase, tid, warp_m, warp_n, a_off, b_off,
                       g_h0s[ot] + hsbase, Wb_hh0, acc);
            ps_dump(smem, CS1_OFF, warp_m, warp_n, lane, acc);
            __syncthreads();
            const float* Cs = (const float*)(smem + CS1_OFF);
            #pragma unroll
            for (int q = 0; q < 4; q++) {
                int i = tid + q * 256;
                int m = i >> 5, hl = i & 31;
                int b = m0 + m;
                int h = hb + hl;
                size_t idx = (size_t)b * H_ + h;
                float old = h0of[idx];
                float v;
                if (t < g_len[b]) {
                    const float* gi = g_gi0 + ((size_t)t * B_ + b) * G3;
                    float r = sigf(gi[h]        + Cs[m * 100 + hl]      + b_hh0[h]);
                    float z = sigf(gi[512 + h]  + Cs[m * 100 + 32 + hl] + b_hh0[512 + h]);
                    float n = tanhfast(gi[1024 + h] + r * (Cs[m * 100 + 64 + hl] + b_hh0[1024 + h]));
                    v = (1.f - z) * n + z * old;
                } else v = old;
                h0nf[idx] = v;
                __nv_bfloat16 vh = __float2bfloat16_rn(v);
                __nv_bfloat16 vl = __float2bfloat16_rn(v - __bfloat162float(vh));
                size_t sb = (size_t)((mtile * 32 + (h >> 4)) * 2) * HSLAB_ENT
                          + (size_t)(b & 31) * 24 + (h & 15);
                g_h0s[nt2][sb] = vh;
                g_h0s[nt2][sb + HSLAB_ENT] = vl;
            }
        }
        nbar++;
        group_bar(grp, nbar * GRPSZ);

        // ---------------- phase B: h1_new = GRU1(h0_new, h1_old) ----------------
        {
            float acc[3][4];
            #pragma unroll
            for (int i = 0; i < 3; i++)
                #pragma unroll
                for (int q = 0; q < 4; q++) acc[i][q] = 0.f;
            ps_segment(sbase, tid, warp_m, warp_n, a_off, b_off,
                       g_h0s[nt2] + hsbase, Wb_ih1, acc);
            ps_dump(smem, CS1_OFF, warp_m, warp_n, lane, acc);
            #pragma unroll
            for (int i = 0; i < 3; i++)
                #pragma unroll
                for (int q = 0; q < 4; q++) acc[i][q] = 0.f;
            ps_segment(sbase, tid, warp_m, warp_n, a_off, b_off,
                       g_h1s[ot] + hsbase, Wb_hh1, acc);
            ps_dump(smem, CS2_OFF, warp_m, warp_n, lane, acc);
            __syncthreads();
            const float* Cs1 = (const float*)(smem + CS1_OFF);
            const float* Cs2 = (const float*)(smem + CS2_OFF);
            #pragma unroll
            for (int q = 0; q < 4; q++) {
                int i = tid + q * 256;
                int m = i >> 5, hl = i & 31;
                int b = m0 + m;
                int h = hb + hl;
                size_t idx = (size_t)b * H_ + h;
                size_t hidx = ((size_t)t * B_ + b) * H_ + h;
                size_t sb = (size_t)((mtile * 32 + (h >> 4)) * 2) * HSLAB_ENT
                          + (size_t)(b & 31) * 24 + (h & 15);
                float old = h1of[idx];
                if (t < g_len[b]) {
                    float r = sigf(Cs1[m * 100 + hl]      + b_ih1[h]
                                 + Cs2[m * 100 + hl]      + b_hh1[h]);
                    float z = sigf(Cs1[m * 100 + 32 + hl] + b_ih1[512 + h]
                                 + Cs2[m * 100 + 32 + hl] + b_hh1[512 + h]);
                    float n = tanhfast(Cs1[m * 100 + 64 + hl] + b_ih1[1024 + h]
                                  + r * (Cs2[m * 100 + 64 + hl] + b_hh1[1024 + h]));
                    float v = (1.f - z) * n + z * old;
                    h1nf[idx] = v;
                    __nv_bfloat16 vh = __float2bfloat16_rn(v);
                    __nv_bfloat16 vl = __float2bfloat16_rn(v - __bfloat162float(vh));
                    g_h1s[nt2][sb] = vh;
                    g_h1s[nt2][sb + HSLAB_ENT] = vl;
                    g_H1h[hidx] = vh;
                    g_H1l[hidx] = vl;
                } else {
                    h1nf[idx] = old;
                    g_h1s[nt2][sb] = g_h1s[ot][sb];
                    g_h1s[nt2][sb + HSLAB_ENT] = g_h1s[ot][sb + HSLAB_ENT];
                    g_H1h[hidx] = __float2bfloat16_rn(0.f);
                    g_H1l[hidx] = __float2bfloat16_rn(0.f);
                }
            }
        }
        nbar++;
        group_bar(grp, nbar * GRPSZ);
    }
}

// ---------------- host orchestration (graph-capturable: launches only) ----------------
extern "C" void kernel_launch(void* const* d_in, const int* in_sizes, int n_in,
                              void* d_out, int out_size)
{
    const float* image_code = (const float*)d_in[0];
    const int*   captions   = (const int*)  d_in[1];
    const int*   cap_lens   = (const int*)  d_in[2];
    const float* embed_w    = (const float*)d_in[3];
    const float* init_w     = (const float*)d_in[4];
    const float* init_b     = (const float*)d_in[5];
    const float* w_ih0      = (const float*)d_in[6];
    const float* w_hh0      = (const float*)d_in[7];
    const float* b_ih0      = (const float*)d_in[8];
    const float* b_hh0      = (const float*)d_in[9];
    const float* w_ih1      = (const float*)d_in[10];
    const float* w_hh1      = (const float*)d_in[11];
    const float* b_ih1      = (const float*)d_in[12];
    const float* b_hh1      = (const float*)d_in[13];
    const float* fc_w       = (const float*)d_in[14];
    const float* fc_b       = (const float*)d_in[15];
    float* out = (float*)d_out;

    void* p;
    cudaGetSymbolAddress(&p, g_img);     float* dimg  = (float*)p;
    cudaGetSymbolAddress(&p, g_gi0c);    float* dgi0c = (float*)p;
    cudaGetSymbolAddress(&p, g_gi0);     float* dgi0  = (float*)p;
    cudaGetSymbolAddress(&p, g_h0f);     float* dh0a  = (float*)p;
    cudaGetSymbolAddress(&p, g_h1f);     float* dh1a  = (float*)p;
    cudaGetSymbolAddress(&p, g_rowidx);  int*   drow  = (int*)p;
    cudaGetSymbolAddress(&p, g_fcw_h);   __nv_bfloat16* dfcwh = (__nv_bfloat16*)p;
    cudaGetSymbolAddress(&p, g_fcw_l);   __nv_bfloat16* dfcwl = (__nv_bfloat16*)p;
    cudaGetSymbolAddress(&p, g_emb_h);   __nv_bfloat16* dembh = (__nv_bfloat16*)p;
    cudaGetSymbolAddress(&p, g_emb_l);   __nv_bfloat16* dembl = (__nv_bfloat16*)p;
    cudaGetSymbolAddress(&p, g_wih0e_h); __nv_bfloat16* dw0h  = (__nv_bfloat16*)p;
    cudaGetSymbolAddress(&p, g_wih0e_l); __nv_bfloat16* dw0l  = (__nv_bfloat16*)p;
    cudaGetSymbolAddress(&p, g_whh0_s);  __nv_bfloat16* dwhh0s = (__nv_bfloat16*)p;
    cudaGetSymbolAddress(&p, g_wih1_s);  __nv_bfloat16* dwih1s = (__nv_bfloat16*)p;
    cudaGetSymbolAddress(&p, g_whh1_s);  __nv_bfloat16* dwhh1s = (__nv_bfloat16*)p;
    cudaGetSymbolAddress(&p, g_H1h);     __nv_bfloat16* dH1h  = (__nv_bfloat16*)p;
    cudaGetSymbolAddress(&p, g_H1l);     __nv_bfloat16* dH1l  = (__nv_bfloat16*)p;
    cudaGetSymbolAddress(&p, g_h0s);     __nv_bfloat16* dh0s0 = (__nv_bfloat16*)p;
    cudaGetSymbolAddress(&p, g_h1s);     __nv_bfloat16* dh1s0 = (__nv_bfloat16*)p;

    cudaFuncSetAttribute(mmagemm_kernel,
                         cudaFuncAttributeMaxDynamicSharedMemorySize, MMA_SMEM_BYTES);
    cudaFuncSetAttribute(gru_persistent,
                         cudaFuncAttributeMaxDynamicSharedMemorySize, PS_SMEM);

    // 0. weight preconversion
    const int NW = V_ * H_;
    const int NG = G3 * H_;
    convw_kernel<<<(NW + 255) / 256, 256>>>(fc_w,    H_, 0,   dfcwh, dfcwl, NW);
    convw_kernel<<<(NW + 255) / 256, 256>>>(embed_w, H_, 0,   dembh, dembl, NW);
    convw_kernel<<<(NG + 255) / 256, 256>>>(w_ih0, IC_ + WD_, IC_, dw0h, dw0l, NG);
    convw_slab_kernel<<<NG / 256, 256>>>(w_hh0, dwhh0s);
    convw_slab_kernel<<<NG / 256, 256>>>(w_ih1, dwih1s);
    convw_slab_kernel<<<NG / 256, 256>>>(w_hh1, dwhh1s);

    // 1. sort + metadata + aux outputs (also resets group barriers)
    sort_kernel<<<1, 256>>>(cap_lens, captions, out, (long long)out_size);
    // 2. gather sorted image codes
    gather_img_kernel<<<(B_ * IC_) / 256, 256>>>(image_code);
    // 3. h0/h1 init in ONE GEMM: (256, 1024, K=2048) -> g_h0f[0], g_h1f[0]
    gemm64_kernel<<<dim3(16, 4), 256>>>(dimg, IC_, init_w, IC_, init_b,
                                        dh0a, H_, dh1a, IC_);
    // 3b. initial hidden -> slabbed bf16 planes (buffer 0)
    convh_slab_kernel<<<(B_ * H_) / 256, 256>>>(dh0a, dh0s0);
    convh_slab_kernel<<<(B_ * H_) / 256, 256>>>(dh1a, dh1s0);
    // 4. time-invariant img part of layer0 input gates (+ b_ih0)
    gemm64_kernel<<<dim3(24, 4), 256>>>(dimg, IC_, w_ih0, IC_ + WD_, b_ih0,
                                        dgi0c, G3, nullptr, IC_);
    // 5. embedding-side layer0 input gates for ALL 12800 tokens (+ gi0c broadcast)
    mmagemm_kernel<<<dim3(6, 100), 256, MMA_SMEM_BYTES>>>(
        dembh, dembl, drow, dw0h, dw0l, dgi0c, dgi0, G3, 0);
    // 6. persistent recurrence (BK=32 bulk pipeline, blocking group barriers, early exit)
    gru_persistent<<<NBLK, 256, PS_SMEM>>>(b_hh0, b_ih1, b_hh1);
    // 7. FC head on tensor cores
    mmagemm_kernel<<<dim3(40, 100), 256, MMA_SMEM_BYTES>>>(
        dH1h, dH1l, nullptr, dfcwh, dfcwl, fc_b, out, V_, 1);
}